// round 3
// baseline (speedup 1.0000x reference)
#include <cuda_runtime.h>
#include <cuda_bf16.h>
#include <math.h>

// Problem constants
#define S 4096
#define H 2048
#define NH 16
#define HD 128
#define SCALE 0.08838834764831845f   // 1/sqrt(128)

// ---------------------------------------------------------------------------
// Scratch (device globals — allocation-free per harness rules)
// ---------------------------------------------------------------------------
__device__ float g_Q[S * H];
__device__ float g_K[S * H];
__device__ float g_V[S * H];
__device__ float g_O[S * H];

// ---------------------------------------------------------------------------
// SGEMM (NT): C[m][n] = sum_k A[m][k] * B[n][k] + bias[n]
// ---------------------------------------------------------------------------
#define GBM 128
#define GBN 128
#define GBK 16
#define GTM 8
#define GTN 8
#define GPAD 4

__global__ __launch_bounds__(256) void gemm_nt_bias(
    const float* __restrict__ A, const float* __restrict__ B,
    const float* __restrict__ bias, float* __restrict__ C,
    int M, int N, int K)
{
    __shared__ float As[GBK][GBM + GPAD];
    __shared__ float Bs[GBK][GBN + GPAD];

    const int tid = threadIdx.x;
    const int bm = blockIdx.y * GBM;
    const int bn = blockIdx.x * GBN;
    const int tx = tid & 15;
    const int ty = tid >> 4;

    float acc[GTM][GTN];
#pragma unroll
    for (int i = 0; i < GTM; i++)
#pragma unroll
        for (int j = 0; j < GTN; j++) acc[i][j] = 0.f;

    for (int k0 = 0; k0 < K; k0 += GBK) {
#pragma unroll
        for (int it = 0; it < 2; it++) {
            int i4 = tid + it * 256;
            int r  = i4 >> 2;
            int c  = (i4 & 3) << 2;
            float4 v = *(const float4*)&A[(size_t)(bm + r) * K + k0 + c];
            As[c + 0][r] = v.x; As[c + 1][r] = v.y;
            As[c + 2][r] = v.z; As[c + 3][r] = v.w;
        }
#pragma unroll
        for (int it = 0; it < 2; it++) {
            int i4 = tid + it * 256;
            int r  = i4 >> 2;
            int c  = (i4 & 3) << 2;
            float4 v = *(const float4*)&B[(size_t)(bn + r) * K + k0 + c];
            Bs[c + 0][r] = v.x; Bs[c + 1][r] = v.y;
            Bs[c + 2][r] = v.z; Bs[c + 3][r] = v.w;
        }
        __syncthreads();

#pragma unroll
        for (int kk = 0; kk < GBK; kk++) {
            float a[GTM], b[GTN];
#pragma unroll
            for (int i = 0; i < GTM; i++) a[i] = As[kk][ty * GTM + i];
#pragma unroll
            for (int j = 0; j < GTN; j++) b[j] = Bs[kk][tx * GTN + j];
#pragma unroll
            for (int i = 0; i < GTM; i++)
#pragma unroll
                for (int j = 0; j < GTN; j++)
                    acc[i][j] = fmaf(a[i], b[j], acc[i][j]);
        }
        __syncthreads();
    }

#pragma unroll
    for (int i = 0; i < GTM; i++) {
        int m = bm + ty * GTM + i;
        int n0 = bn + tx * GTN;
#pragma unroll
        for (int j = 0; j < GTN; j += 4) {
            float4 o;
            o.x = acc[i][j + 0] + bias[n0 + j + 0];
            o.y = acc[i][j + 1] + bias[n0 + j + 1];
            o.z = acc[i][j + 2] + bias[n0 + j + 2];
            o.w = acc[i][j + 3] + bias[n0 + j + 3];
            *(float4*)&C[(size_t)m * N + n0 + j] = o;
        }
    }
}

// ---------------------------------------------------------------------------
// Flash attention, fp32, register-tiled (GEMM-style) score and PV phases.
// Grid: (S/BM, NH). Block: 256 threads. One CTA: 64 queries of one head.
//
// Phase 1 (scores):  16x16 thread grid, 4 queries x 4 keys per thread.
//                    Qs/Ks stored transposed [d][row] so the d-loop reads
//                    float4 rows.
// Softmax:           4 threads per query row (16 keys each), shuffle-combined.
// Phase 3 (PV):      16x16 thread grid, 4 rows x 8 dims per thread with
//                    persistent accumulators rescaled via row_corr.
// ---------------------------------------------------------------------------
#define BM 64
#define BN 64
#define QST (BM + 4)     // 68: stride of transposed Q/K tiles
#define VST (HD + 4)     // 132
#define SST (BN + 4)     // 68

__global__ __launch_bounds__(256) void flash_attn_kernel(
    const float* __restrict__ Q, const float* __restrict__ K,
    const float* __restrict__ V, float* __restrict__ O)
{
    extern __shared__ float sm[];
    float* Qs = sm;                      // HD * QST   [d][q]
    float* Ks = Qs + HD * QST;           // HD * QST   [d][k]
    float* Vs = Ks + HD * QST;           // BN * VST   [k][d]
    float* Ss = Vs + BN * VST;           // BM * SST   [q][k]
    float* row_corr = Ss + BM * SST;     // BM
    float* row_l    = row_corr + BM;     // BM

    const int tid = threadIdx.x;
    const int h = blockIdx.y;
    const int qbase = blockIdx.x * BM;
    const size_t headoff = (size_t)h * HD;

    const int tx = tid & 15;   // phase-1: key group; phase-3: dim group
    const int ty = tid >> 4;   // phase-1: query group; phase-3: row group
    const int srow = tid >> 2; // softmax: query row
    const int scg  = tid & 3;  // softmax: key quarter

    // Load Q tile transposed + pre-scaled: Qs[d][q]
    for (int i = tid; i < BM * (HD / 4); i += 256) {
        int r = i / (HD / 4);
        int c = (i % (HD / 4)) * 4;
        float4 v = *(const float4*)&Q[(size_t)(qbase + r) * H + headoff + c];
        Qs[(c + 0) * QST + r] = v.x * SCALE;
        Qs[(c + 1) * QST + r] = v.y * SCALE;
        Qs[(c + 2) * QST + r] = v.z * SCALE;
        Qs[(c + 3) * QST + r] = v.w * SCALE;
    }

    float m_i = -INFINITY, l_i = 0.f;  // per softmax-thread row state
    float acc[4][8];
#pragma unroll
    for (int i = 0; i < 4; i++)
#pragma unroll
        for (int j = 0; j < 8; j++) acc[i][j] = 0.f;

    for (int kb = 0; kb < S; kb += BN) {
        __syncthreads();   // previous iteration done with Ks/Vs/Ss

        // Load K transposed [d][k], V row-major [k][d]
        for (int i = tid; i < BN * (HD / 4); i += 256) {
            int r = i / (HD / 4);
            int c = (i % (HD / 4)) * 4;
            float4 kv = *(const float4*)&K[(size_t)(kb + r) * H + headoff + c];
            Ks[(c + 0) * QST + r] = kv.x;
            Ks[(c + 1) * QST + r] = kv.y;
            Ks[(c + 2) * QST + r] = kv.z;
            Ks[(c + 3) * QST + r] = kv.w;
            float4 vv = *(const float4*)&V[(size_t)(kb + r) * H + headoff + c];
            *(float4*)&Vs[r * VST + c] = vv;
        }
        __syncthreads();

        // ---- Phase 1: S = Q K^T, 4x4 microtile ----
        float sacc[4][4];
#pragma unroll
        for (int i = 0; i < 4; i++)
#pragma unroll
            for (int j = 0; j < 4; j++) sacc[i][j] = 0.f;

#pragma unroll 8
        for (int d = 0; d < HD; d++) {
            float4 a = *(const float4*)&Qs[d * QST + ty * 4];
            float4 b = *(const float4*)&Ks[d * QST + tx * 4];
            float av[4] = {a.x, a.y, a.z, a.w};
            float bv[4] = {b.x, b.y, b.z, b.w};
#pragma unroll
            for (int i = 0; i < 4; i++)
#pragma unroll
                for (int j = 0; j < 4; j++)
                    sacc[i][j] = fmaf(av[i], bv[j], sacc[i][j]);
        }
#pragma unroll
        for (int i = 0; i < 4; i++) {
            float4 o = make_float4(sacc[i][0], sacc[i][1], sacc[i][2], sacc[i][3]);
            *(float4*)&Ss[(ty * 4 + i) * SST + tx * 4] = o;
        }
        __syncthreads();

        // ---- Softmax (online): 4 threads per row, 16 keys each ----
        float sv[16];
        float lmax = -INFINITY;
#pragma unroll
        for (int j = 0; j < 16; j++) {
            sv[j] = Ss[srow * SST + scg * 16 + j];
            lmax = fmaxf(lmax, sv[j]);
        }
        lmax = fmaxf(lmax, __shfl_xor_sync(0xffffffffu, lmax, 1));
        lmax = fmaxf(lmax, __shfl_xor_sync(0xffffffffu, lmax, 2));
        float m_new = fmaxf(m_i, lmax);
        float corr = __expf(m_i - m_new);
        float lsum = 0.f;
#pragma unroll
        for (int j = 0; j < 16; j++) {
            float p = __expf(sv[j] - m_new);
            Ss[srow * SST + scg * 16 + j] = p;
            lsum += p;
        }
        lsum += __shfl_xor_sync(0xffffffffu, lsum, 1);
        lsum += __shfl_xor_sync(0xffffffffu, lsum, 2);
        l_i = l_i * corr + lsum;
        m_i = m_new;
        if (scg == 0) {
            row_corr[srow] = corr;
            row_l[srow] = l_i;
        }
        __syncthreads();

        // ---- Phase 3: O += P V, 4x8 microtile, persistent acc ----
        float rc[4];
#pragma unroll
        for (int i = 0; i < 4; i++) rc[i] = row_corr[ty * 4 + i];
#pragma unroll
        for (int i = 0; i < 4; i++)
#pragma unroll
            for (int j = 0; j < 8; j++) acc[i][j] *= rc[i];

#pragma unroll 4
        for (int k = 0; k < BN; k++) {
            float4 b0 = *(const float4*)&Vs[k * VST + tx * 8];
            float4 b1 = *(const float4*)&Vs[k * VST + tx * 8 + 4];
            float bv[8] = {b0.x, b0.y, b0.z, b0.w, b1.x, b1.y, b1.z, b1.w};
            float av[4];
#pragma unroll
            for (int i = 0; i < 4; i++) av[i] = Ss[(ty * 4 + i) * SST + k];
#pragma unroll
            for (int i = 0; i < 4; i++)
#pragma unroll
                for (int j = 0; j < 8; j++)
                    acc[i][j] = fmaf(av[i], bv[j], acc[i][j]);
        }
    }

    // ---- Epilogue: normalize and write O ----
#pragma unroll
    for (int i = 0; i < 4; i++) {
        float inv = 1.f / row_l[ty * 4 + i];
        float* op = &O[(size_t)(qbase + ty * 4 + i) * H + headoff + tx * 8];
        float4 o0, o1;
        o0.x = acc[i][0] * inv; o0.y = acc[i][1] * inv;
        o0.z = acc[i][2] * inv; o0.w = acc[i][3] * inv;
        o1.x = acc[i][4] * inv; o1.y = acc[i][5] * inv;
        o1.z = acc[i][6] * inv; o1.w = acc[i][7] * inv;
        *(float4*)&op[0] = o0;
        *(float4*)&op[4] = o1;
    }
}

// ---------------------------------------------------------------------------
// Launch
// ---------------------------------------------------------------------------
extern "C" void kernel_launch(void* const* d_in, const int* in_sizes, int n_in,
                              void* d_out, int out_size)
{
    const float* hidden = (const float*)d_in[0];
    const float* Wq = (const float*)d_in[1];
    const float* bq = (const float*)d_in[2];
    const float* Wk = (const float*)d_in[3];
    const float* bk = (const float*)d_in[4];
    const float* Wv = (const float*)d_in[5];
    const float* bv = (const float*)d_in[6];
    const float* Wo = (const float*)d_in[7];
    const float* bo = (const float*)d_in[8];
    float* out = (float*)d_out;

    float *Qp, *Kp, *Vp, *Op;
    cudaGetSymbolAddress((void**)&Qp, g_Q);
    cudaGetSymbolAddress((void**)&Kp, g_K);
    cudaGetSymbolAddress((void**)&Vp, g_V);
    cudaGetSymbolAddress((void**)&Op, g_O);

    const int attn_smem = (int)((2 * HD * QST + BN * VST + BM * SST + 2 * BM)
                                * sizeof(float));
    cudaFuncSetAttribute(flash_attn_kernel,
                         cudaFuncAttributeMaxDynamicSharedMemorySize, attn_smem);

    dim3 ggrid(H / GBN, S / GBM);   // (16, 32)
    dim3 gblk(256);

    gemm_nt_bias<<<ggrid, gblk>>>(hidden, Wq, bq, Qp, S, H, H);
    gemm_nt_bias<<<ggrid, gblk>>>(hidden, Wk, bk, Kp, S, H, H);
    gemm_nt_bias<<<ggrid, gblk>>>(hidden, Wv, bv, Vp, S, H, H);

    dim3 agrid(S / BM, NH);         // (64, 16)
    flash_attn_kernel<<<agrid, 256, attn_smem>>>(Qp, Kp, Vp, Op);

    gemm_nt_bias<<<ggrid, gblk>>>(Op, Wo, bo, out, S, H, H);
}

// round 5
// speedup vs baseline: 2.4890x; 2.4890x over previous
#include <cuda_runtime.h>
#include <cuda_bf16.h>
#include <cstdint>
#include <math.h>

#define S_LEN 4096
#define HDIM  2048
#define NHEADS 16
#define HD    128
#define SCALE 0.08838834764831845f

__device__ float g_Q[S_LEN * HDIM];
__device__ float g_K[S_LEN * HDIM];
__device__ float g_V[S_LEN * HDIM];
__device__ float g_O[S_LEN * HDIM];
__device__ float g_VT[HDIM * S_LEN];

// ---------------- helpers ----------------
__device__ __forceinline__ uint32_t smem_u32(const void* p) {
    uint32_t a;
    asm("{ .reg .u64 t; cvta.to.shared.u64 t, %1; cvt.u32.u64 %0, t; }"
        : "=r"(a) : "l"(p));
    return a;
}
__device__ __forceinline__ void ldsm4(uint32_t* r, uint32_t a) {
    asm volatile("ldmatrix.sync.aligned.m8n8.x4.shared.b16 {%0,%1,%2,%3}, [%4];"
        : "=r"(r[0]), "=r"(r[1]), "=r"(r[2]), "=r"(r[3]) : "r"(a));
}
__device__ __forceinline__ void mma_bf16(float* c, const uint32_t* a,
                                         const uint32_t* b) {
    asm volatile("mma.sync.aligned.m16n8k16.row.col.f32.bf16.bf16.f32 "
        "{%0,%1,%2,%3}, {%4,%5,%6,%7}, {%8,%9}, {%0,%1,%2,%3};"
        : "+f"(c[0]), "+f"(c[1]), "+f"(c[2]), "+f"(c[3])
        : "r"(a[0]), "r"(a[1]), "r"(a[2]), "r"(a[3]), "r"(b[0]), "r"(b[1]));
}
// split fp32 pair into bf16 hi/lo pairs, store as 32-bit each
__device__ __forceinline__ void split_store2(__nv_bfloat16* hi,
                                             __nv_bfloat16* lo,
                                             float x, float y) {
    __nv_bfloat16 hx = __float2bfloat16(x), hy = __float2bfloat16(y);
    __nv_bfloat162 h2; h2.x = hx; h2.y = hy;
    __nv_bfloat162 l2;
    l2.x = __float2bfloat16(x - __bfloat162float(hx));
    l2.y = __float2bfloat16(y - __bfloat162float(hy));
    *reinterpret_cast<__nv_bfloat162*>(hi) = h2;
    *reinterpret_cast<__nv_bfloat162*>(lo) = l2;
}

// ---------------- HMMA GEMM (NT + bias): BM=128 BN=128 BK=32 ----------------
#define LDAB 40   // bf16 leading dim for 32-wide K tiles (conflict-free ldmatrix)

__global__ __launch_bounds__(256) void gemm_hmma(
    const float* __restrict__ A, const float* __restrict__ B,
    const float* __restrict__ bias, float* __restrict__ C,
    int M, int N, int K)
{
    __shared__ __nv_bfloat16 Ah[128 * LDAB], Al[128 * LDAB];
    __shared__ __nv_bfloat16 Bh[128 * LDAB], Bl[128 * LDAB];

    const int tid = threadIdx.x, lane = tid & 31, wid = tid >> 5;
    const int wm = wid >> 2, wn = wid & 3;            // 2 x 4 warp grid
    const int bm = blockIdx.y * 128, bn = blockIdx.x * 128;
    const int m0 = wm * 64, n0 = wn * 32;

    const int grow = tid >> 1, gcs = (tid & 1) * 16;  // gmem load mapping
    const int a_r = lane & 15, a_c = (lane >> 4) * 8; // ldmatrix A lanes
    const int b_n = ((lane >> 4) & 1) * 8 + (lane & 7);
    const int b_k = ((lane >> 3) & 1) * 8;

    float acc[4][4][4];
#pragma unroll
    for (int mt = 0; mt < 4; mt++)
#pragma unroll
        for (int nt = 0; nt < 4; nt++)
#pragma unroll
            for (int j = 0; j < 4; j++) acc[mt][nt][j] = 0.f;

    const int nIter = K / 32;
    for (int kc = 0; kc < nIter; kc++) {
        __syncthreads();
        const float* ag = A + (size_t)(bm + grow) * K + kc * 32 + gcs;
        const float* bg = B + (size_t)(bn + grow) * K + kc * 32 + gcs;
#pragma unroll
        for (int j = 0; j < 4; j++) {
            float4 v = *(const float4*)(ag + j * 4);
            int o = grow * LDAB + gcs + j * 4;
            split_store2(Ah + o, Al + o, v.x, v.y);
            split_store2(Ah + o + 2, Al + o + 2, v.z, v.w);
            float4 w = *(const float4*)(bg + j * 4);
            split_store2(Bh + o, Bl + o, w.x, w.y);
            split_store2(Bh + o + 2, Bl + o + 2, w.z, w.w);
        }
        __syncthreads();

#pragma unroll
        for (int ks = 0; ks < 2; ks++) {
            const int k0 = ks * 16;
            uint32_t ah[4][4], al[4][4], bh[2][4], bl[2][4];
#pragma unroll
            for (int mt = 0; mt < 4; mt++) {
                int off = (m0 + mt * 16 + a_r) * LDAB + k0 + a_c;
                ldsm4(ah[mt], smem_u32(Ah + off));
                ldsm4(al[mt], smem_u32(Al + off));
            }
#pragma unroll
            for (int bp = 0; bp < 2; bp++) {
                int off = (n0 + bp * 16 + b_n) * LDAB + k0 + b_k;
                ldsm4(bh[bp], smem_u32(Bh + off));
                ldsm4(bl[bp], smem_u32(Bl + off));
            }
#pragma unroll
            for (int mt = 0; mt < 4; mt++)
#pragma unroll
                for (int nt = 0; nt < 4; nt++) {
                    const uint32_t* bhp = &bh[nt >> 1][(nt & 1) * 2];
                    const uint32_t* blp = &bl[nt >> 1][(nt & 1) * 2];
                    mma_bf16(acc[mt][nt], ah[mt], bhp);
                    mma_bf16(acc[mt][nt], ah[mt], blp);
                    mma_bf16(acc[mt][nt], al[mt], bhp);
                }
        }
    }

#pragma unroll
    for (int mt = 0; mt < 4; mt++) {
        const int r0 = bm + m0 + mt * 16 + (lane >> 2);
#pragma unroll
        for (int nt = 0; nt < 4; nt++) {
            const int col = bn + n0 + nt * 8 + (lane & 3) * 2;
            float2 bv = *(const float2*)(bias + col);
            float2 o0, o1;
            o0.x = acc[mt][nt][0] + bv.x; o0.y = acc[mt][nt][1] + bv.y;
            o1.x = acc[mt][nt][2] + bv.x; o1.y = acc[mt][nt][3] + bv.y;
            *(float2*)(C + (size_t)r0 * N + col) = o0;
            *(float2*)(C + (size_t)(r0 + 8) * N + col) = o1;
        }
    }
}

// ---------------- transpose: out[c][s] = in[s][c] ----------------
__global__ __launch_bounds__(256) void transpose_k(
    const float* __restrict__ in, float* __restrict__ out)
{
    __shared__ float tile[32][33];
    const int cb = blockIdx.x * 32, sbk = blockIdx.y * 32;
    const int tx = threadIdx.x, ty = threadIdx.y;
#pragma unroll
    for (int j = 0; j < 4; j++)
        tile[ty + j * 8][tx] = in[(size_t)(sbk + ty + j * 8) * HDIM + cb + tx];
    __syncthreads();
#pragma unroll
    for (int j = 0; j < 4; j++)
        out[(size_t)(cb + ty + j * 8) * S_LEN + sbk + tx] = tile[tx][ty + j * 8];
}

// ---------------- HMMA flash attention ----------------
// CTA = (128 queries, 1 head), 64-key tiles, 8 warps (2m x 4n).
#define LDQ 136
#define LDV 72

__global__ __launch_bounds__(256) void attn_hmma(
    const float* __restrict__ Q, const float* __restrict__ K,
    const float* __restrict__ VT, float* __restrict__ O)
{
    extern __shared__ char smraw[];
    __nv_bfloat16* Qh = (__nv_bfloat16*)smraw;          // 128*136
    __nv_bfloat16* Ql = Qh + 128 * LDQ;
    __nv_bfloat16* Kh = Ql + 128 * LDQ;                 // 64*136
    __nv_bfloat16* Kl = Kh + 64 * LDQ;
    __nv_bfloat16* Vh = Kl + 64 * LDQ;                  // 128*72 (VT tile)
    __nv_bfloat16* Vl = Vh + 128 * LDV;
    __nv_bfloat16* Ph = Vl + 128 * LDV;                 // 128*72
    __nv_bfloat16* Pl = Ph + 128 * LDV;
    float* tmax = (float*)(Pl + 128 * LDV);             // [4][128]
    float* tsum = tmax + 512;                           // [4][128]
    float* rowm = tsum + 512;                           // [128]
    float* rowl = rowm + 128;                           // [128]
    float* corr = rowl + 128;                           // [128]

    const int tid = threadIdx.x, lane = tid & 31, wid = tid >> 5;
    const int wm = wid >> 2, wn = wid & 3;
    const int qb = blockIdx.x * 128, h = blockIdx.y;

    const int a_r = lane & 15, a_c = (lane >> 4) * 8;
    const int b_n = ((lane >> 4) & 1) * 8 + (lane & 7);
    const int b_k = ((lane >> 3) & 1) * 8;

    // Q tile load (pre-scaled)
    {
        const int r = tid >> 1, cs = (tid & 1) * 64;
        const float* qg = Q + (size_t)(qb + r) * HDIM + h * HD + cs;
#pragma unroll
        for (int j = 0; j < 16; j++) {
            float4 v = *(const float4*)(qg + j * 4);
            int o = r * LDQ + cs + j * 4;
            split_store2(Qh + o, Ql + o, v.x * SCALE, v.y * SCALE);
            split_store2(Qh + o + 2, Ql + o + 2, v.z * SCALE, v.w * SCALE);
        }
    }
    if (tid < 128) { rowm[tid] = -INFINITY; rowl[tid] = 0.f; }

    float oacc[4][4][4];
#pragma unroll
    for (int mt = 0; mt < 4; mt++)
#pragma unroll
        for (int nt = 0; nt < 4; nt++)
#pragma unroll
            for (int j = 0; j < 4; j++) oacc[mt][nt][j] = 0.f;

    for (int t = 0; t < S_LEN / 64; t++) {
        __syncthreads();
        // K tile 64x128
        {
            const int r = tid >> 2, cs = (tid & 3) * 32;
            const float* kg = K + (size_t)(t * 64 + r) * HDIM + h * HD + cs;
#pragma unroll
            for (int j = 0; j < 8; j++) {
                float4 v = *(const float4*)(kg + j * 4);
                int o = r * LDQ + cs + j * 4;
                split_store2(Kh + o, Kl + o, v.x, v.y);
                split_store2(Kh + o + 2, Kl + o + 2, v.z, v.w);
            }
        }
        // VT tile 128(d) x 64(k)
        {
            const int r = tid >> 1, cs = (tid & 1) * 32;
            const float* vg = VT + (size_t)(h * HD + r) * S_LEN + t * 64 + cs;
#pragma unroll
            for (int j = 0; j < 8; j++) {
                float4 v = *(const float4*)(vg + j * 4);
                int o = r * LDV + cs + j * 4;
                split_store2(Vh + o, Vl + o, v.x, v.y);
                split_store2(Vh + o + 2, Vl + o + 2, v.z, v.w);
            }
        }
        __syncthreads();

        // ---- Phase 1: S = Q K^T ---- (warp: 64q x 16k)
        float sacc[4][2][4];
#pragma unroll
        for (int mt = 0; mt < 4; mt++)
#pragma unroll
            for (int nt = 0; nt < 2; nt++)
#pragma unroll
                for (int j = 0; j < 4; j++) sacc[mt][nt][j] = 0.f;

#pragma unroll
        for (int ks = 0; ks < 8; ks++) {
            const int k0 = ks * 16;
            uint32_t ah[4][4], al[4][4], bh[4], bl[4];
#pragma unroll
            for (int mt = 0; mt < 4; mt++) {
                int off = (wm * 64 + mt * 16 + a_r) * LDQ + k0 + a_c;
                ldsm4(ah[mt], smem_u32(Qh + off));
                ldsm4(al[mt], smem_u32(Ql + off));
            }
            {
                int off = (wn * 16 + b_n) * LDQ + k0 + b_k;
                ldsm4(bh, smem_u32(Kh + off));
                ldsm4(bl, smem_u32(Kl + off));
            }
#pragma unroll
            for (int mt = 0; mt < 4; mt++)
#pragma unroll
                for (int nt = 0; nt < 2; nt++) {
                    mma_bf16(sacc[mt][nt], ah[mt], &bh[nt * 2]);
                    mma_bf16(sacc[mt][nt], ah[mt], &bl[nt * 2]);
                    mma_bf16(sacc[mt][nt], al[mt], &bh[nt * 2]);
                }
        }

        // ---- row max ----
        float pm[4][2];
#pragma unroll
        for (int mt = 0; mt < 4; mt++)
#pragma unroll
            for (int i = 0; i < 2; i++) {
                float m = fmaxf(sacc[mt][0][i * 2], sacc[mt][0][i * 2 + 1]);
                m = fmaxf(m, fmaxf(sacc[mt][1][i * 2], sacc[mt][1][i * 2 + 1]));
                m = fmaxf(m, __shfl_xor_sync(0xffffffffu, m, 1));
                m = fmaxf(m, __shfl_xor_sync(0xffffffffu, m, 2));
                pm[mt][i] = m;
            }
        if ((lane & 3) == 0) {
#pragma unroll
            for (int mt = 0; mt < 4; mt++)
#pragma unroll
                for (int i = 0; i < 2; i++)
                    tmax[wn * 128 + wm * 64 + mt * 16 + (lane >> 2) + 8 * i] = pm[mt][i];
        }
        __syncthreads();
        if (tid < 128) {
            float m_old = rowm[tid];
            float tm = fmaxf(fmaxf(tmax[tid], tmax[128 + tid]),
                             fmaxf(tmax[256 + tid], tmax[384 + tid]));
            float m_new = fmaxf(m_old, tm);
            corr[tid] = __expf(m_old - m_new);
            rowm[tid] = m_new;
        }
        __syncthreads();

        // ---- P = exp(S - m), store hi/lo, row sums ----
        float ps[4][2];
#pragma unroll
        for (int mt = 0; mt < 4; mt++) { ps[mt][0] = 0.f; ps[mt][1] = 0.f; }
#pragma unroll
        for (int mt = 0; mt < 4; mt++) {
            const int r0 = wm * 64 + mt * 16 + (lane >> 2);
            const float m0v = rowm[r0], m1v = rowm[r0 + 8];
#pragma unroll
            for (int nt = 0; nt < 2; nt++) {
                const int col = wn * 16 + nt * 8 + (lane & 3) * 2;
                float p00 = __expf(sacc[mt][nt][0] - m0v);
                float p01 = __expf(sacc[mt][nt][1] - m0v);
                float p10 = __expf(sacc[mt][nt][2] - m1v);
                float p11 = __expf(sacc[mt][nt][3] - m1v);
                ps[mt][0] += p00 + p01;
                ps[mt][1] += p10 + p11;
                split_store2(Ph + r0 * LDV + col, Pl + r0 * LDV + col, p00, p01);
                split_store2(Ph + (r0 + 8) * LDV + col, Pl + (r0 + 8) * LDV + col,
                             p10, p11);
            }
        }
#pragma unroll
        for (int mt = 0; mt < 4; mt++)
#pragma unroll
            for (int i = 0; i < 2; i++) {
                ps[mt][i] += __shfl_xor_sync(0xffffffffu, ps[mt][i], 1);
                ps[mt][i] += __shfl_xor_sync(0xffffffffu, ps[mt][i], 2);
            }
        if ((lane & 3) == 0) {
#pragma unroll
            for (int mt = 0; mt < 4; mt++)
#pragma unroll
                for (int i = 0; i < 2; i++)
                    tsum[wn * 128 + wm * 64 + mt * 16 + (lane >> 2) + 8 * i] = ps[mt][i];
        }
        __syncthreads();
        if (tid < 128)
            rowl[tid] = rowl[tid] * corr[tid] +
                        (tsum[tid] + tsum[128 + tid] + tsum[256 + tid] + tsum[384 + tid]);

        // ---- Phase 2: O = O*corr + P V ---- (warp: 64q x 32d)
#pragma unroll
        for (int mt = 0; mt < 4; mt++) {
            const int r0 = wm * 64 + mt * 16 + (lane >> 2);
            const float c0 = corr[r0], c1 = corr[r0 + 8];
#pragma unroll
            for (int nt = 0; nt < 4; nt++) {
                oacc[mt][nt][0] *= c0; oacc[mt][nt][1] *= c0;
                oacc[mt][nt][2] *= c1; oacc[mt][nt][3] *= c1;
            }
        }
#pragma unroll
        for (int ks = 0; ks < 4; ks++) {
            const int k0 = ks * 16;
            uint32_t ah[4][4], al[4][4], bh[2][4], bl[2][4];
#pragma unroll
            for (int mt = 0; mt < 4; mt++) {
                int off = (wm * 64 + mt * 16 + a_r) * LDV + k0 + a_c;
                ldsm4(ah[mt], smem_u32(Ph + off));
                ldsm4(al[mt], smem_u32(Pl + off));
            }
#pragma unroll
            for (int bp = 0; bp < 2; bp++) {
                int off = (wn * 32 + bp * 16 + b_n) * LDV + k0 + b_k;
                ldsm4(bh[bp], smem_u32(Vh + off));
                ldsm4(bl[bp], smem_u32(Vl + off));
            }
#pragma unroll
            for (int mt = 0; mt < 4; mt++)
#pragma unroll
                for (int nt = 0; nt < 4; nt++) {
                    const uint32_t* bhp = &bh[nt >> 1][(nt & 1) * 2];
                    const uint32_t* blp = &bl[nt >> 1][(nt & 1) * 2];
                    mma_bf16(oacc[mt][nt], ah[mt], bhp);
                    mma_bf16(oacc[mt][nt], ah[mt], blp);
                    mma_bf16(oacc[mt][nt], al[mt], bhp);
                }
        }
    }
    __syncthreads();

    // ---- epilogue ----
#pragma unroll
    for (int mt = 0; mt < 4; mt++) {
        const int r0 = wm * 64 + mt * 16 + (lane >> 2);
        const float inv0 = 1.f / rowl[r0], inv1 = 1.f / rowl[r0 + 8];
#pragma unroll
        for (int nt = 0; nt < 4; nt++) {
            const int col = wn * 32 + nt * 8 + (lane & 3) * 2;
            float2 o0, o1;
            o0.x = oacc[mt][nt][0] * inv0; o0.y = oacc[mt][nt][1] * inv0;
            o1.x = oacc[mt][nt][2] * inv1; o1.y = oacc[mt][nt][3] * inv1;
            *(float2*)(O + (size_t)(qb + r0) * HDIM + h * HD + col) = o0;
            *(float2*)(O + (size_t)(qb + r0 + 8) * HDIM + h * HD + col) = o1;
        }
    }
}

// ---------------- launch ----------------
#define ATT_SMEM 183808

extern "C" void kernel_launch(void* const* d_in, const int* in_sizes, int n_in,
                              void* d_out, int out_size)
{
    const float* hidden = (const float*)d_in[0];
    const float* Wq = (const float*)d_in[1];
    const float* bq = (const float*)d_in[2];
    const float* Wk = (const float*)d_in[3];
    const float* bk = (const float*)d_in[4];
    const float* Wv = (const float*)d_in[5];
    const float* bv = (const float*)d_in[6];
    const float* Wo = (const float*)d_in[7];
    const float* bo = (const float*)d_in[8];
    float* out = (float*)d_out;

    float *Qp, *Kp, *Vp, *Op, *VTp;
    cudaGetSymbolAddress((void**)&Qp, g_Q);
    cudaGetSymbolAddress((void**)&Kp, g_K);
    cudaGetSymbolAddress((void**)&Vp, g_V);
    cudaGetSymbolAddress((void**)&Op, g_O);
    cudaGetSymbolAddress((void**)&VTp, g_VT);

    cudaFuncSetAttribute(attn_hmma, cudaFuncAttributeMaxDynamicSharedMemorySize,
                         ATT_SMEM);

    dim3 ggrid(HDIM / 128, S_LEN / 128);   // (16, 32)
    gemm_hmma<<<ggrid, 256>>>(hidden, Wq, bq, Qp, S_LEN, HDIM, HDIM);
    gemm_hmma<<<ggrid, 256>>>(hidden, Wk, bk, Kp, S_LEN, HDIM, HDIM);
    gemm_hmma<<<ggrid, 256>>>(hidden, Wv, bv, Vp, S_LEN, HDIM, HDIM);

    dim3 tgrid(HDIM / 32, S_LEN / 32);
    transpose_k<<<tgrid, dim3(32, 8)>>>(Vp, VTp);

    dim3 agrid(S_LEN / 128, NHEADS);       // (32, 16)
    attn_hmma<<<agrid, 256, ATT_SMEM>>>(Qp, Kp, VTp, Op);

    gemm_hmma<<<ggrid, 256>>>(Op, Wo, bo, out, S_LEN, HDIM, HDIM);
}

// round 6
// speedup vs baseline: 2.8294x; 1.1368x over previous
#include <cuda_runtime.h>
#include <cuda_bf16.h>
#include <cstdint>
#include <math.h>

#define S_LEN 4096
#define HDIM  2048
#define NHEADS 16
#define HD    128
#define SCALE 0.08838834764831845f

// ---------------- scratch globals ----------------
__device__ __nv_bfloat16 g_Hhi[S_LEN * HDIM], g_Hlo[S_LEN * HDIM];
__device__ __nv_bfloat16 g_Wqhi[HDIM * HDIM], g_Wqlo[HDIM * HDIM];
__device__ __nv_bfloat16 g_Wkhi[HDIM * HDIM], g_Wklo[HDIM * HDIM];
__device__ __nv_bfloat16 g_Wvhi[HDIM * HDIM], g_Wvlo[HDIM * HDIM];
__device__ __nv_bfloat16 g_Wohi[HDIM * HDIM], g_Wolo[HDIM * HDIM];
__device__ __nv_bfloat16 g_Qhi[S_LEN * HDIM], g_Qlo[S_LEN * HDIM];
__device__ __nv_bfloat16 g_Khi[S_LEN * HDIM], g_Klo[S_LEN * HDIM];
__device__ uint32_t      g_Vp [S_LEN * HDIM];
__device__ uint32_t      g_VTp[HDIM * S_LEN];
__device__ __nv_bfloat16 g_Ohi[S_LEN * HDIM], g_Olo[S_LEN * HDIM];

// ---------------- helpers ----------------
__device__ __forceinline__ uint32_t smem_u32(const void* p) {
    uint32_t a;
    asm("{ .reg .u64 t; cvta.to.shared.u64 t, %1; cvt.u32.u64 %0, t; }"
        : "=r"(a) : "l"(p));
    return a;
}
__device__ __forceinline__ void ldsm4(uint32_t* r, uint32_t a) {
    asm volatile("ldmatrix.sync.aligned.m8n8.x4.shared.b16 {%0,%1,%2,%3}, [%4];"
        : "=r"(r[0]), "=r"(r[1]), "=r"(r[2]), "=r"(r[3]) : "r"(a));
}
__device__ __forceinline__ void mma_bf16(float* c, const uint32_t* a,
                                         const uint32_t* b) {
    asm volatile("mma.sync.aligned.m16n8k16.row.col.f32.bf16.bf16.f32 "
        "{%0,%1,%2,%3}, {%4,%5,%6,%7}, {%8,%9}, {%0,%1,%2,%3};"
        : "+f"(c[0]), "+f"(c[1]), "+f"(c[2]), "+f"(c[3])
        : "r"(a[0]), "r"(a[1]), "r"(a[2]), "r"(a[3]), "r"(b[0]), "r"(b[1]));
}
__device__ __forceinline__ void split_store2(__nv_bfloat16* hi,
                                             __nv_bfloat16* lo,
                                             float x, float y) {
    __nv_bfloat16 hx = __float2bfloat16(x), hy = __float2bfloat16(y);
    __nv_bfloat162 h2; h2.x = hx; h2.y = hy;
    __nv_bfloat162 l2;
    l2.x = __float2bfloat16(x - __bfloat162float(hx));
    l2.y = __float2bfloat16(y - __bfloat162float(hy));
    *reinterpret_cast<__nv_bfloat162*>(hi) = h2;
    *reinterpret_cast<__nv_bfloat162*>(lo) = l2;
}
__device__ __forceinline__ uint32_t pack_hl(float x) {
    __nv_bfloat16 h = __float2bfloat16(x);
    __nv_bfloat16 l = __float2bfloat16(x - __bfloat162float(h));
    uint16_t hb = *(uint16_t*)&h, lb = *(uint16_t*)&l;
    return (uint32_t)hb | ((uint32_t)lb << 16);
}
#define CP_ASYNC16(dst, src) \
    asm volatile("cp.async.cg.shared.global [%0], [%1], 16;\n" \
                 :: "r"(dst), "l"(src))
#define CP_COMMIT asm volatile("cp.async.commit_group;\n" ::: "memory")
#define CP_WAIT0  asm volatile("cp.async.wait_group 0;\n" ::: "memory")

// ---------------- prepass: fp32 -> bf16 hi/lo ----------------
__global__ __launch_bounds__(256) void split_pre(
    const float* __restrict__ in, __nv_bfloat16* __restrict__ hi,
    __nv_bfloat16* __restrict__ lo, int n4)
{
    int i = blockIdx.x * blockDim.x + threadIdx.x;
    if (i < n4) {
        float4 v = ((const float4*)in)[i];
        split_store2(hi + i * 4, lo + i * 4, v.x, v.y);
        split_store2(hi + i * 4 + 2, lo + i * 4 + 2, v.z, v.w);
    }
}

// ---------------- HMMA GEMM (NT + bias), cp.async double-buffered ----------
// BM=BN=128, BK=32. 256 threads, 8 warps (2m x 4n).
// OUT_MODE: 0 = fp32, 1 = bf16 hi/lo, 2 = packed u32 (hi | lo<<16)
#define LDAB 40
#define STG_BYTES 40960   // per stage: Ah(10240) Al Bh Bl
#define GEMM_SMEM (2 * STG_BYTES)

template <int OUT_MODE>
__global__ __launch_bounds__(256) void gemm_hmma(
    const __nv_bfloat16* __restrict__ Ahi, const __nv_bfloat16* __restrict__ Alo,
    const __nv_bfloat16* __restrict__ Bhi, const __nv_bfloat16* __restrict__ Blo,
    const float* __restrict__ bias,
    float* __restrict__ Cf, __nv_bfloat16* __restrict__ Chi,
    __nv_bfloat16* __restrict__ Clo, uint32_t* __restrict__ Cp,
    int M, int N, int K)
{
    extern __shared__ char smraw[];
    const uint32_t sb = smem_u32(smraw);

    const int tid = threadIdx.x, lane = tid & 31, wid = tid >> 5;
    const int wm = wid >> 2, wn = wid & 3;
    const int bm = blockIdx.y * 128, bn = blockIdx.x * 128;
    const int m0 = wm * 64, n0 = wn * 32;

    const int a_r = lane & 15, a_c = (lane >> 4) * 8;
    const int b_n = ((lane >> 4) & 1) * 8 + (lane & 7);
    const int b_k = ((lane >> 3) & 1) * 8;

    // load mapping: 2 x 16B chunks per array per thread
    const int l_row0 = (tid * 2) >> 2, l_c0 = ((tid * 2) & 3) * 8;
    const int l_row1 = (tid * 2 + 1) >> 2, l_c1 = ((tid * 2 + 1) & 3) * 8;

    float acc[4][4][4];
#pragma unroll
    for (int mt = 0; mt < 4; mt++)
#pragma unroll
        for (int nt = 0; nt < 4; nt++)
#pragma unroll
            for (int j = 0; j < 4; j++) acc[mt][nt][j] = 0.f;

    const int nIter = K / 32;

    auto load_stage = [&](int kc, int s) {
        const uint32_t st = sb + s * STG_BYTES;
        const int k0 = kc * 32;
        // Ah, Al, Bh, Bl
        CP_ASYNC16(st + (l_row0 * LDAB + l_c0) * 2,
                   Ahi + (size_t)(bm + l_row0) * K + k0 + l_c0);
        CP_ASYNC16(st + (l_row1 * LDAB + l_c1) * 2,
                   Ahi + (size_t)(bm + l_row1) * K + k0 + l_c1);
        CP_ASYNC16(st + 10240 + (l_row0 * LDAB + l_c0) * 2,
                   Alo + (size_t)(bm + l_row0) * K + k0 + l_c0);
        CP_ASYNC16(st + 10240 + (l_row1 * LDAB + l_c1) * 2,
                   Alo + (size_t)(bm + l_row1) * K + k0 + l_c1);
        CP_ASYNC16(st + 20480 + (l_row0 * LDAB + l_c0) * 2,
                   Bhi + (size_t)(bn + l_row0) * K + k0 + l_c0);
        CP_ASYNC16(st + 20480 + (l_row1 * LDAB + l_c1) * 2,
                   Bhi + (size_t)(bn + l_row1) * K + k0 + l_c1);
        CP_ASYNC16(st + 30720 + (l_row0 * LDAB + l_c0) * 2,
                   Blo + (size_t)(bn + l_row0) * K + k0 + l_c0);
        CP_ASYNC16(st + 30720 + (l_row1 * LDAB + l_c1) * 2,
                   Blo + (size_t)(bn + l_row1) * K + k0 + l_c1);
        CP_COMMIT;
    };

    load_stage(0, 0);
    for (int kc = 0; kc < nIter; kc++) {
        const int s = kc & 1;
        CP_WAIT0;
        __syncthreads();
        if (kc + 1 < nIter) load_stage(kc + 1, s ^ 1);

        const uint32_t st = sb + s * STG_BYTES;
#pragma unroll
        for (int ks = 0; ks < 2; ks++) {
            const int k0 = ks * 16;
            uint32_t ah[4][4], al[4][4], bh[2][4], bl[2][4];
#pragma unroll
            for (int mt = 0; mt < 4; mt++) {
                int off = ((m0 + mt * 16 + a_r) * LDAB + k0 + a_c) * 2;
                ldsm4(ah[mt], st + off);
                ldsm4(al[mt], st + 10240 + off);
            }
#pragma unroll
            for (int bp = 0; bp < 2; bp++) {
                int off = ((n0 + bp * 16 + b_n) * LDAB + k0 + b_k) * 2;
                ldsm4(bh[bp], st + 20480 + off);
                ldsm4(bl[bp], st + 30720 + off);
            }
#pragma unroll
            for (int mt = 0; mt < 4; mt++)
#pragma unroll
                for (int nt = 0; nt < 4; nt++) {
                    const uint32_t* bhp = &bh[nt >> 1][(nt & 1) * 2];
                    const uint32_t* blp = &bl[nt >> 1][(nt & 1) * 2];
                    mma_bf16(acc[mt][nt], ah[mt], bhp);
                    mma_bf16(acc[mt][nt], ah[mt], blp);
                    mma_bf16(acc[mt][nt], al[mt], bhp);
                }
        }
    }

#pragma unroll
    for (int mt = 0; mt < 4; mt++) {
        const int r0 = bm + m0 + mt * 16 + (lane >> 2);
#pragma unroll
        for (int nt = 0; nt < 4; nt++) {
            const int col = bn + n0 + nt * 8 + (lane & 3) * 2;
            float2 bv = *(const float2*)(bias + col);
            float c00 = acc[mt][nt][0] + bv.x, c01 = acc[mt][nt][1] + bv.y;
            float c10 = acc[mt][nt][2] + bv.x, c11 = acc[mt][nt][3] + bv.y;
            if (OUT_MODE == 0) {
                *(float2*)(Cf + (size_t)r0 * N + col) = make_float2(c00, c01);
                *(float2*)(Cf + (size_t)(r0 + 8) * N + col) = make_float2(c10, c11);
            } else if (OUT_MODE == 1) {
                split_store2(Chi + (size_t)r0 * N + col,
                             Clo + (size_t)r0 * N + col, c00, c01);
                split_store2(Chi + (size_t)(r0 + 8) * N + col,
                             Clo + (size_t)(r0 + 8) * N + col, c10, c11);
            } else {
                *(uint2*)(Cp + (size_t)r0 * N + col) =
                    make_uint2(pack_hl(c00), pack_hl(c01));
                *(uint2*)(Cp + (size_t)(r0 + 8) * N + col) =
                    make_uint2(pack_hl(c10), pack_hl(c11));
            }
        }
    }
}

// ---------------- transpose packed u32: out[c][s] = in[s][c] ----------------
__global__ __launch_bounds__(256) void transpose_u32(
    const uint32_t* __restrict__ in, uint32_t* __restrict__ out)
{
    __shared__ uint32_t tile[32][33];
    const int cb = blockIdx.x * 32, sbk = blockIdx.y * 32;
    const int tx = threadIdx.x, ty = threadIdx.y;
#pragma unroll
    for (int j = 0; j < 4; j++)
        tile[ty + j * 8][tx] = in[(size_t)(sbk + ty + j * 8) * HDIM + cb + tx];
    __syncthreads();
#pragma unroll
    for (int j = 0; j < 4; j++)
        out[(size_t)(cb + ty + j * 8) * S_LEN + sbk + tx] = tile[tx][ty + j * 8];
}

// ---------------- HMMA flash attention ----------------
#define LDQ 136
#define LDV 72
#define ATT_SMEM 183808

__global__ __launch_bounds__(256) void attn_hmma(
    const __nv_bfloat16* __restrict__ Qhi, const __nv_bfloat16* __restrict__ Qlo,
    const __nv_bfloat16* __restrict__ Khi, const __nv_bfloat16* __restrict__ Klo,
    const uint32_t* __restrict__ VTp,
    __nv_bfloat16* __restrict__ Ohi, __nv_bfloat16* __restrict__ Olo)
{
    extern __shared__ char smraw[];
    __nv_bfloat16* Qh = (__nv_bfloat16*)smraw;
    __nv_bfloat16* Ql = Qh + 128 * LDQ;
    __nv_bfloat16* Kh = Ql + 128 * LDQ;
    __nv_bfloat16* Kl = Kh + 64 * LDQ;
    __nv_bfloat16* Vh = Kl + 64 * LDQ;
    __nv_bfloat16* Vl = Vh + 128 * LDV;
    __nv_bfloat16* Ph = Vl + 128 * LDV;
    __nv_bfloat16* Pl = Ph + 128 * LDV;
    float* tmax = (float*)(Pl + 128 * LDV);
    float* tsum = tmax + 512;
    float* rowm = tsum + 512;
    float* rowl = rowm + 128;
    float* corr = rowl + 128;

    const int tid = threadIdx.x, lane = tid & 31, wid = tid >> 5;
    const int wm = wid >> 2, wn = wid & 3;
    const int qb = blockIdx.x * 128, h = blockIdx.y;

    const int a_r = lane & 15, a_c = (lane >> 4) * 8;
    const int b_n = ((lane >> 4) & 1) * 8 + (lane & 7);
    const int b_k = ((lane >> 3) & 1) * 8;

    // Q tile: direct bf16 copies
    {
        const int r = tid >> 1, cs = (tid & 1) * 64;
        const __nv_bfloat16* qh = Qhi + (size_t)(qb + r) * HDIM + h * HD + cs;
        const __nv_bfloat16* ql = Qlo + (size_t)(qb + r) * HDIM + h * HD + cs;
#pragma unroll
        for (int j = 0; j < 8; j++) {
            *(uint4*)(Qh + r * LDQ + cs + j * 8) = *(const uint4*)(qh + j * 8);
            *(uint4*)(Ql + r * LDQ + cs + j * 8) = *(const uint4*)(ql + j * 8);
        }
    }
    if (tid < 128) { rowm[tid] = -INFINITY; rowl[tid] = 0.f; }

    float oacc[4][4][4];
#pragma unroll
    for (int mt = 0; mt < 4; mt++)
#pragma unroll
        for (int nt = 0; nt < 4; nt++)
#pragma unroll
            for (int j = 0; j < 4; j++) oacc[mt][nt][j] = 0.f;

    for (int t = 0; t < S_LEN / 64; t++) {
        __syncthreads();
        // K tile 64x128
        {
            const int r = tid >> 2, cs = (tid & 3) * 32;
            const __nv_bfloat16* kh = Khi + (size_t)(t * 64 + r) * HDIM + h * HD + cs;
            const __nv_bfloat16* kl = Klo + (size_t)(t * 64 + r) * HDIM + h * HD + cs;
#pragma unroll
            for (int j = 0; j < 4; j++) {
                *(uint4*)(Kh + r * LDQ + cs + j * 8) = *(const uint4*)(kh + j * 8);
                *(uint4*)(Kl + r * LDQ + cs + j * 8) = *(const uint4*)(kl + j * 8);
            }
        }
        // VT tile 128(d) x 64(k) from packed
        {
            const int r = tid >> 1, cs = (tid & 1) * 32;
            const uint32_t* vp = VTp + (size_t)(h * HD + r) * S_LEN + t * 64 + cs;
#pragma unroll
            for (int j = 0; j < 8; j++) {
                uint4 w = *(const uint4*)(vp + j * 4);
                uint32_t* vh = (uint32_t*)(Vh + r * LDV + cs + j * 4);
                uint32_t* vl = (uint32_t*)(Vl + r * LDV + cs + j * 4);
                vh[0] = __byte_perm(w.x, w.y, 0x5410);
                vl[0] = __byte_perm(w.x, w.y, 0x7632);
                vh[1] = __byte_perm(w.z, w.w, 0x5410);
                vl[1] = __byte_perm(w.z, w.w, 0x7632);
            }
        }
        __syncthreads();

        // ---- Phase 1: S = Q K^T ----
        float sacc[4][2][4];
#pragma unroll
        for (int mt = 0; mt < 4; mt++)
#pragma unroll
            for (int nt = 0; nt < 2; nt++)
#pragma unroll
                for (int j = 0; j < 4; j++) sacc[mt][nt][j] = 0.f;

#pragma unroll
        for (int ks = 0; ks < 8; ks++) {
            const int k0 = ks * 16;
            uint32_t ah[4][4], al[4][4], bh[4], bl[4];
#pragma unroll
            for (int mt = 0; mt < 4; mt++) {
                int off = (wm * 64 + mt * 16 + a_r) * LDQ + k0 + a_c;
                ldsm4(ah[mt], smem_u32(Qh + off));
                ldsm4(al[mt], smem_u32(Ql + off));
            }
            {
                int off = (wn * 16 + b_n) * LDQ + k0 + b_k;
                ldsm4(bh, smem_u32(Kh + off));
                ldsm4(bl, smem_u32(Kl + off));
            }
#pragma unroll
            for (int mt = 0; mt < 4; mt++)
#pragma unroll
                for (int nt = 0; nt < 2; nt++) {
                    mma_bf16(sacc[mt][nt], ah[mt], &bh[nt * 2]);
                    mma_bf16(sacc[mt][nt], ah[mt], &bl[nt * 2]);
                    mma_bf16(sacc[mt][nt], al[mt], &bh[nt * 2]);
                }
        }
        // apply softmax scale
#pragma unroll
        for (int mt = 0; mt < 4; mt++)
#pragma unroll
            for (int nt = 0; nt < 2; nt++)
#pragma unroll
                for (int j = 0; j < 4; j++) sacc[mt][nt][j] *= SCALE;

        // ---- row max ----
        float pm[4][2];
#pragma unroll
        for (int mt = 0; mt < 4; mt++)
#pragma unroll
            for (int i = 0; i < 2; i++) {
                float m = fmaxf(sacc[mt][0][i * 2], sacc[mt][0][i * 2 + 1]);
                m = fmaxf(m, fmaxf(sacc[mt][1][i * 2], sacc[mt][1][i * 2 + 1]));
                m = fmaxf(m, __shfl_xor_sync(0xffffffffu, m, 1));
                m = fmaxf(m, __shfl_xor_sync(0xffffffffu, m, 2));
                pm[mt][i] = m;
            }
        if ((lane & 3) == 0) {
#pragma unroll
            for (int mt = 0; mt < 4; mt++)
#pragma unroll
                for (int i = 0; i < 2; i++)
                    tmax[wn * 128 + wm * 64 + mt * 16 + (lane >> 2) + 8 * i] = pm[mt][i];
        }
        __syncthreads();
        if (tid < 128) {
            float m_old = rowm[tid];
            float tm = fmaxf(fmaxf(tmax[tid], tmax[128 + tid]),
                             fmaxf(tmax[256 + tid], tmax[384 + tid]));
            float m_new = fmaxf(m_old, tm);
            corr[tid] = __expf(m_old - m_new);
            rowm[tid] = m_new;
        }
        __syncthreads();

        // ---- P = exp(S - m) ----
        float ps[4][2];
#pragma unroll
        for (int mt = 0; mt < 4; mt++) { ps[mt][0] = 0.f; ps[mt][1] = 0.f; }
#pragma unroll
        for (int mt = 0; mt < 4; mt++) {
            const int r0 = wm * 64 + mt * 16 + (lane >> 2);
            const float m0v = rowm[r0], m1v = rowm[r0 + 8];
#pragma unroll
            for (int nt = 0; nt < 2; nt++) {
                const int col = wn * 16 + nt * 8 + (lane & 3) * 2;
                float p00 = __expf(sacc[mt][nt][0] - m0v);
                float p01 = __expf(sacc[mt][nt][1] - m0v);
                float p10 = __expf(sacc[mt][nt][2] - m1v);
                float p11 = __expf(sacc[mt][nt][3] - m1v);
                ps[mt][0] += p00 + p01;
                ps[mt][1] += p10 + p11;
                split_store2(Ph + r0 * LDV + col, Pl + r0 * LDV + col, p00, p01);
                split_store2(Ph + (r0 + 8) * LDV + col, Pl + (r0 + 8) * LDV + col,
                             p10, p11);
            }
        }
#pragma unroll
        for (int mt = 0; mt < 4; mt++)
#pragma unroll
            for (int i = 0; i < 2; i++) {
                ps[mt][i] += __shfl_xor_sync(0xffffffffu, ps[mt][i], 1);
                ps[mt][i] += __shfl_xor_sync(0xffffffffu, ps[mt][i], 2);
            }
        if ((lane & 3) == 0) {
#pragma unroll
            for (int mt = 0; mt < 4; mt++)
#pragma unroll
                for (int i = 0; i < 2; i++)
                    tsum[wn * 128 + wm * 64 + mt * 16 + (lane >> 2) + 8 * i] = ps[mt][i];
        }
        __syncthreads();
        if (tid < 128)
            rowl[tid] = rowl[tid] * corr[tid] +
                        (tsum[tid] + tsum[128 + tid] + tsum[256 + tid] + tsum[384 + tid]);

        // ---- Phase 2: O = O*corr + P V ----
#pragma unroll
        for (int mt = 0; mt < 4; mt++) {
            const int r0 = wm * 64 + mt * 16 + (lane >> 2);
            const float c0 = corr[r0], c1 = corr[r0 + 8];
#pragma unroll
            for (int nt = 0; nt < 4; nt++) {
                oacc[mt][nt][0] *= c0; oacc[mt][nt][1] *= c0;
                oacc[mt][nt][2] *= c1; oacc[mt][nt][3] *= c1;
            }
        }
#pragma unroll
        for (int ks = 0; ks < 4; ks++) {
            const int k0 = ks * 16;
            uint32_t ah[4][4], al[4][4], bh[2][4], bl[2][4];
#pragma unroll
            for (int mt = 0; mt < 4; mt++) {
                int off = (wm * 64 + mt * 16 + a_r) * LDV + k0 + a_c;
                ldsm4(ah[mt], smem_u32(Ph + off));
                ldsm4(al[mt], smem_u32(Pl + off));
            }
#pragma unroll
            for (int bp = 0; bp < 2; bp++) {
                int off = (wn * 32 + bp * 16 + b_n) * LDV + k0 + b_k;
                ldsm4(bh[bp], smem_u32(Vh + off));
                ldsm4(bl[bp], smem_u32(Vl + off));
            }
#pragma unroll
            for (int mt = 0; mt < 4; mt++)
#pragma unroll
                for (int nt = 0; nt < 4; nt++) {
                    const uint32_t* bhp = &bh[nt >> 1][(nt & 1) * 2];
                    const uint32_t* blp = &bl[nt >> 1][(nt & 1) * 2];
                    mma_bf16(oacc[mt][nt], ah[mt], bhp);
                    mma_bf16(oacc[mt][nt], ah[mt], blp);
                    mma_bf16(oacc[mt][nt], al[mt], bhp);
                }
        }
    }
    __syncthreads();

    // ---- epilogue: normalize + hi/lo split out ----
#pragma unroll
    for (int mt = 0; mt < 4; mt++) {
        const int r0 = wm * 64 + mt * 16 + (lane >> 2);
        const float inv0 = 1.f / rowl[r0], inv1 = 1.f / rowl[r0 + 8];
#pragma unroll
        for (int nt = 0; nt < 4; nt++) {
            const int col = wn * 32 + nt * 8 + (lane & 3) * 2;
            size_t i0 = (size_t)(qb + r0) * HDIM + h * HD + col;
            size_t i1 = (size_t)(qb + r0 + 8) * HDIM + h * HD + col;
            split_store2(Ohi + i0, Olo + i0,
                         oacc[mt][nt][0] * inv0, oacc[mt][nt][1] * inv0);
            split_store2(Ohi + i1, Olo + i1,
                         oacc[mt][nt][2] * inv1, oacc[mt][nt][3] * inv1);
        }
    }
}

// ---------------- launch ----------------
extern "C" void kernel_launch(void* const* d_in, const int* in_sizes, int n_in,
                              void* d_out, int out_size)
{
    const float* hidden = (const float*)d_in[0];
    const float* Wq = (const float*)d_in[1];
    const float* bq = (const float*)d_in[2];
    const float* Wk = (const float*)d_in[3];
    const float* bk = (const float*)d_in[4];
    const float* Wv = (const float*)d_in[5];
    const float* bv = (const float*)d_in[6];
    const float* Wo = (const float*)d_in[7];
    const float* bo = (const float*)d_in[8];
    float* out = (float*)d_out;

    __nv_bfloat16 *Hhi, *Hlo, *Wqhi, *Wqlo, *Wkhi, *Wklo, *Wvhi, *Wvlo,
                  *Wohi, *Wolo, *Qhi, *Qlo, *Khi, *Klo, *Ohi, *Olo;
    uint32_t *Vp, *VTp;
    cudaGetSymbolAddress((void**)&Hhi, g_Hhi);  cudaGetSymbolAddress((void**)&Hlo, g_Hlo);
    cudaGetSymbolAddress((void**)&Wqhi, g_Wqhi); cudaGetSymbolAddress((void**)&Wqlo, g_Wqlo);
    cudaGetSymbolAddress((void**)&Wkhi, g_Wkhi); cudaGetSymbolAddress((void**)&Wklo, g_Wklo);
    cudaGetSymbolAddress((void**)&Wvhi, g_Wvhi); cudaGetSymbolAddress((void**)&Wvlo, g_Wvlo);
    cudaGetSymbolAddress((void**)&Wohi, g_Wohi); cudaGetSymbolAddress((void**)&Wolo, g_Wolo);
    cudaGetSymbolAddress((void**)&Qhi, g_Qhi);   cudaGetSymbolAddress((void**)&Qlo, g_Qlo);
    cudaGetSymbolAddress((void**)&Khi, g_Khi);   cudaGetSymbolAddress((void**)&Klo, g_Klo);
    cudaGetSymbolAddress((void**)&Ohi, g_Ohi);   cudaGetSymbolAddress((void**)&Olo, g_Olo);
    cudaGetSymbolAddress((void**)&Vp, g_Vp);     cudaGetSymbolAddress((void**)&VTp, g_VTp);

    cudaFuncSetAttribute(gemm_hmma<0>, cudaFuncAttributeMaxDynamicSharedMemorySize, GEMM_SMEM);
    cudaFuncSetAttribute(gemm_hmma<1>, cudaFuncAttributeMaxDynamicSharedMemorySize, GEMM_SMEM);
    cudaFuncSetAttribute(gemm_hmma<2>, cudaFuncAttributeMaxDynamicSharedMemorySize, GEMM_SMEM);
    cudaFuncSetAttribute(attn_hmma, cudaFuncAttributeMaxDynamicSharedMemorySize, ATT_SMEM);

    // prepass splits
    const int nH4 = S_LEN * HDIM / 4, nW4 = HDIM * HDIM / 4;
    split_pre<<<nH4 / 256, 256>>>(hidden, Hhi, Hlo, nH4);
    split_pre<<<nW4 / 256, 256>>>(Wq, Wqhi, Wqlo, nW4);
    split_pre<<<nW4 / 256, 256>>>(Wk, Wkhi, Wklo, nW4);
    split_pre<<<nW4 / 256, 256>>>(Wv, Wvhi, Wvlo, nW4);
    split_pre<<<nW4 / 256, 256>>>(Wo, Wohi, Wolo, nW4);

    dim3 ggrid(HDIM / 128, S_LEN / 128);   // (16, 32)
    gemm_hmma<1><<<ggrid, 256, GEMM_SMEM>>>(Hhi, Hlo, Wqhi, Wqlo, bq,
                                            nullptr, Qhi, Qlo, nullptr,
                                            S_LEN, HDIM, HDIM);
    gemm_hmma<1><<<ggrid, 256, GEMM_SMEM>>>(Hhi, Hlo, Wkhi, Wklo, bk,
                                            nullptr, Khi, Klo, nullptr,
                                            S_LEN, HDIM, HDIM);
    gemm_hmma<2><<<ggrid, 256, GEMM_SMEM>>>(Hhi, Hlo, Wvhi, Wvlo, bv,
                                            nullptr, nullptr, nullptr, Vp,
                                            S_LEN, HDIM, HDIM);

    dim3 tgrid(HDIM / 32, S_LEN / 32);
    transpose_u32<<<tgrid, dim3(32, 8)>>>(Vp, VTp);

    dim3 agrid(S_LEN / 128, NHEADS);       // (32, 16)
    attn_hmma<<<agrid, 256, ATT_SMEM>>>(Qhi, Qlo, Khi, Klo, VTp, Ohi, Olo);

    gemm_hmma<0><<<ggrid, 256, GEMM_SMEM>>>(Ohi, Olo, Wohi, Wolo, bo,
                                            out, nullptr, nullptr, nullptr,
                                            S_LEN, HDIM, HDIM);
}

// round 7
// speedup vs baseline: 2.8838x; 1.0192x over previous
#include <cuda_runtime.h>
#include <cuda_bf16.h>
#include <cstdint>
#include <math.h>

#define S_LEN 4096
#define HDIM  2048
#define NHEADS 16
#define HD    128
#define SCALE 0.08838834764831845f

// ---------------- scratch globals ----------------
__device__ __nv_bfloat16 g_Hhi[S_LEN * HDIM], g_Hlo[S_LEN * HDIM];
__device__ __nv_bfloat16 g_Wqhi[HDIM * HDIM], g_Wqlo[HDIM * HDIM];
__device__ __nv_bfloat16 g_Wkhi[HDIM * HDIM], g_Wklo[HDIM * HDIM];
__device__ __nv_bfloat16 g_Wvhi[HDIM * HDIM], g_Wvlo[HDIM * HDIM];
__device__ __nv_bfloat16 g_Wohi[HDIM * HDIM], g_Wolo[HDIM * HDIM];
__device__ __nv_bfloat16 g_Qhi[S_LEN * HDIM], g_Qlo[S_LEN * HDIM];
__device__ __nv_bfloat16 g_Khi[S_LEN * HDIM], g_Klo[S_LEN * HDIM];
__device__ uint32_t      g_Vp [S_LEN * HDIM];
__device__ uint32_t      g_VTp[HDIM * S_LEN];
__device__ __nv_bfloat16 g_Ohi[S_LEN * HDIM], g_Olo[S_LEN * HDIM];

// ---------------- helpers ----------------
__device__ __forceinline__ uint32_t smem_u32(const void* p) {
    uint32_t a;
    asm("{ .reg .u64 t; cvta.to.shared.u64 t, %1; cvt.u32.u64 %0, t; }"
        : "=r"(a) : "l"(p));
    return a;
}
__device__ __forceinline__ void ldsm4(uint32_t* r, uint32_t a) {
    asm volatile("ldmatrix.sync.aligned.m8n8.x4.shared.b16 {%0,%1,%2,%3}, [%4];"
        : "=r"(r[0]), "=r"(r[1]), "=r"(r[2]), "=r"(r[3]) : "r"(a));
}
__device__ __forceinline__ void mma_bf16(float* c, const uint32_t* a,
                                         const uint32_t* b) {
    asm volatile("mma.sync.aligned.m16n8k16.row.col.f32.bf16.bf16.f32 "
        "{%0,%1,%2,%3}, {%4,%5,%6,%7}, {%8,%9}, {%0,%1,%2,%3};"
        : "+f"(c[0]), "+f"(c[1]), "+f"(c[2]), "+f"(c[3])
        : "r"(a[0]), "r"(a[1]), "r"(a[2]), "r"(a[3]), "r"(b[0]), "r"(b[1]));
}
__device__ __forceinline__ void split_store2(__nv_bfloat16* hi,
                                             __nv_bfloat16* lo,
                                             float x, float y) {
    __nv_bfloat16 hx = __float2bfloat16(x), hy = __float2bfloat16(y);
    __nv_bfloat162 h2; h2.x = hx; h2.y = hy;
    __nv_bfloat162 l2;
    l2.x = __float2bfloat16(x - __bfloat162float(hx));
    l2.y = __float2bfloat16(y - __bfloat162float(hy));
    *reinterpret_cast<__nv_bfloat162*>(hi) = h2;
    *reinterpret_cast<__nv_bfloat162*>(lo) = l2;
}
__device__ __forceinline__ uint32_t pack_hl(float x) {
    __nv_bfloat16 h = __float2bfloat16(x);
    __nv_bfloat16 l = __float2bfloat16(x - __bfloat162float(h));
    uint16_t hb = *(uint16_t*)&h, lb = *(uint16_t*)&l;
    return (uint32_t)hb | ((uint32_t)lb << 16);
}
// split two floats into packed bf16x2 hi-word and lo-word
__device__ __forceinline__ void split_pack2(float x, float y,
                                            uint32_t& hi, uint32_t& lo) {
    __nv_bfloat16 hx = __float2bfloat16(x), hy = __float2bfloat16(y);
    __nv_bfloat16 lx = __float2bfloat16(x - __bfloat162float(hx));
    __nv_bfloat16 ly = __float2bfloat16(y - __bfloat162float(hy));
    uint16_t a = *(uint16_t*)&hx, b = *(uint16_t*)&hy;
    uint16_t c = *(uint16_t*)&lx, d = *(uint16_t*)&ly;
    hi = (uint32_t)a | ((uint32_t)b << 16);
    lo = (uint32_t)c | ((uint32_t)d << 16);
}
#define CP_ASYNC16(dst, src) \
    asm volatile("cp.async.cg.shared.global [%0], [%1], 16;\n" \
                 :: "r"(dst), "l"(src))
#define CP_COMMIT asm volatile("cp.async.commit_group;\n" ::: "memory")
#define CP_WAIT0  asm volatile("cp.async.wait_group 0;\n" ::: "memory")

// ---------------- prepass: fp32 -> bf16 hi/lo ----------------
__global__ __launch_bounds__(256) void split_pre(
    const float* __restrict__ in, __nv_bfloat16* __restrict__ hi,
    __nv_bfloat16* __restrict__ lo, int n4)
{
    int i = blockIdx.x * blockDim.x + threadIdx.x;
    if (i < n4) {
        float4 v = ((const float4*)in)[i];
        split_store2(hi + i * 4, lo + i * 4, v.x, v.y);
        split_store2(hi + i * 4 + 2, lo + i * 4 + 2, v.z, v.w);
    }
}

// ---------------- HMMA GEMM (NT + bias)*scale, cp.async 2-stage ----------
// BM=BN=128, BK=32. 256 threads, 8 warps (2m x 4n).
// OUT_MODE: 0 = fp32, 1 = bf16 hi/lo, 2 = packed u32 (hi | lo<<16)
#define LDAB 40
#define STG_BYTES 40960
#define GEMM_SMEM (2 * STG_BYTES)

template <int OUT_MODE>
__global__ __launch_bounds__(256) void gemm_hmma(
    const __nv_bfloat16* __restrict__ Ahi, const __nv_bfloat16* __restrict__ Alo,
    const __nv_bfloat16* __restrict__ Bhi, const __nv_bfloat16* __restrict__ Blo,
    const float* __restrict__ bias, float scale,
    float* __restrict__ Cf, __nv_bfloat16* __restrict__ Chi,
    __nv_bfloat16* __restrict__ Clo, uint32_t* __restrict__ Cp,
    int M, int N, int K)
{
    extern __shared__ char smraw[];
    const uint32_t sb = smem_u32(smraw);

    const int tid = threadIdx.x, lane = tid & 31, wid = tid >> 5;
    const int wm = wid >> 2, wn = wid & 3;
    const int bm = blockIdx.y * 128, bn = blockIdx.x * 128;
    const int m0 = wm * 64, n0 = wn * 32;

    const int a_r = lane & 15, a_c = (lane >> 4) * 8;
    const int b_n = ((lane >> 4) & 1) * 8 + (lane & 7);
    const int b_k = ((lane >> 3) & 1) * 8;

    const int l_row0 = (tid * 2) >> 2, l_c0 = ((tid * 2) & 3) * 8;
    const int l_row1 = (tid * 2 + 1) >> 2, l_c1 = ((tid * 2 + 1) & 3) * 8;

    float acc[4][4][4];
#pragma unroll
    for (int mt = 0; mt < 4; mt++)
#pragma unroll
        for (int nt = 0; nt < 4; nt++)
#pragma unroll
            for (int j = 0; j < 4; j++) acc[mt][nt][j] = 0.f;

    const int nIter = K / 32;

    auto load_stage = [&](int kc, int s) {
        const uint32_t st = sb + s * STG_BYTES;
        const int k0 = kc * 32;
        CP_ASYNC16(st + (l_row0 * LDAB + l_c0) * 2,
                   Ahi + (size_t)(bm + l_row0) * K + k0 + l_c0);
        CP_ASYNC16(st + (l_row1 * LDAB + l_c1) * 2,
                   Ahi + (size_t)(bm + l_row1) * K + k0 + l_c1);
        CP_ASYNC16(st + 10240 + (l_row0 * LDAB + l_c0) * 2,
                   Alo + (size_t)(bm + l_row0) * K + k0 + l_c0);
        CP_ASYNC16(st + 10240 + (l_row1 * LDAB + l_c1) * 2,
                   Alo + (size_t)(bm + l_row1) * K + k0 + l_c1);
        CP_ASYNC16(st + 20480 + (l_row0 * LDAB + l_c0) * 2,
                   Bhi + (size_t)(bn + l_row0) * K + k0 + l_c0);
        CP_ASYNC16(st + 20480 + (l_row1 * LDAB + l_c1) * 2,
                   Bhi + (size_t)(bn + l_row1) * K + k0 + l_c1);
        CP_ASYNC16(st + 30720 + (l_row0 * LDAB + l_c0) * 2,
                   Blo + (size_t)(bn + l_row0) * K + k0 + l_c0);
        CP_ASYNC16(st + 30720 + (l_row1 * LDAB + l_c1) * 2,
                   Blo + (size_t)(bn + l_row1) * K + k0 + l_c1);
        CP_COMMIT;
    };

    load_stage(0, 0);
    for (int kc = 0; kc < nIter; kc++) {
        const int s = kc & 1;
        CP_WAIT0;
        __syncthreads();
        if (kc + 1 < nIter) load_stage(kc + 1, s ^ 1);

        const uint32_t st = sb + s * STG_BYTES;
#pragma unroll
        for (int ks = 0; ks < 2; ks++) {
            const int k0 = ks * 16;
            uint32_t ah[4][4], al[4][4], bh[2][4], bl[2][4];
#pragma unroll
            for (int mt = 0; mt < 4; mt++) {
                int off = ((m0 + mt * 16 + a_r) * LDAB + k0 + a_c) * 2;
                ldsm4(ah[mt], st + off);
                ldsm4(al[mt], st + 10240 + off);
            }
#pragma unroll
            for (int bp = 0; bp < 2; bp++) {
                int off = ((n0 + bp * 16 + b_n) * LDAB + k0 + b_k) * 2;
                ldsm4(bh[bp], st + 20480 + off);
                ldsm4(bl[bp], st + 30720 + off);
            }
#pragma unroll
            for (int mt = 0; mt < 4; mt++)
#pragma unroll
                for (int nt = 0; nt < 4; nt++) {
                    const uint32_t* bhp = &bh[nt >> 1][(nt & 1) * 2];
                    const uint32_t* blp = &bl[nt >> 1][(nt & 1) * 2];
                    mma_bf16(acc[mt][nt], ah[mt], bhp);
                    mma_bf16(acc[mt][nt], ah[mt], blp);
                    mma_bf16(acc[mt][nt], al[mt], bhp);
                }
        }
    }

#pragma unroll
    for (int mt = 0; mt < 4; mt++) {
        const int r0 = bm + m0 + mt * 16 + (lane >> 2);
#pragma unroll
        for (int nt = 0; nt < 4; nt++) {
            const int col = bn + n0 + nt * 8 + (lane & 3) * 2;
            float2 bv = *(const float2*)(bias + col);
            float c00 = (acc[mt][nt][0] + bv.x) * scale;
            float c01 = (acc[mt][nt][1] + bv.y) * scale;
            float c10 = (acc[mt][nt][2] + bv.x) * scale;
            float c11 = (acc[mt][nt][3] + bv.y) * scale;
            if (OUT_MODE == 0) {
                *(float2*)(Cf + (size_t)r0 * N + col) = make_float2(c00, c01);
                *(float2*)(Cf + (size_t)(r0 + 8) * N + col) = make_float2(c10, c11);
            } else if (OUT_MODE == 1) {
                split_store2(Chi + (size_t)r0 * N + col,
                             Clo + (size_t)r0 * N + col, c00, c01);
                split_store2(Chi + (size_t)(r0 + 8) * N + col,
                             Clo + (size_t)(r0 + 8) * N + col, c10, c11);
            } else {
                *(uint2*)(Cp + (size_t)r0 * N + col) =
                    make_uint2(pack_hl(c00), pack_hl(c01));
                *(uint2*)(Cp + (size_t)(r0 + 8) * N + col) =
                    make_uint2(pack_hl(c10), pack_hl(c11));
            }
        }
    }
}

// ---------------- transpose packed u32: out[c][s] = in[s][c] ----------------
__global__ __launch_bounds__(256) void transpose_u32(
    const uint32_t* __restrict__ in, uint32_t* __restrict__ out)
{
    __shared__ uint32_t tile[32][33];
    const int cb = blockIdx.x * 32, sbk = blockIdx.y * 32;
    const int tx = threadIdx.x, ty = threadIdx.y;
#pragma unroll
    for (int j = 0; j < 4; j++)
        tile[ty + j * 8][tx] = in[(size_t)(sbk + ty + j * 8) * HDIM + cb + tx];
    __syncthreads();
#pragma unroll
    for (int j = 0; j < 4; j++)
        out[(size_t)(cb + ty + j * 8) * S_LEN + sbk + tx] = tile[tx][ty + j * 8];
}

// ---------------- HMMA flash attention, FA2 layout ----------------
// CTA = (128 queries, 1 head). 8 warps; warp w owns query rows [w*16, w*16+16).
// 64-key tiles. Softmax fully warp-local. P kept in registers as A-fragments.
#define LDQ 136
#define LDV 72
// smem (bf16 elems): Qh 17408 | Ql 17408 | Kh 8704 | Kl 8704 | Vh 9216 | Vl 9216
#define SM_QH 0
#define SM_QL 17408
#define SM_KH 34816
#define SM_KL 43520
#define SM_VH 52224
#define SM_VL 61440
#define ATT_SMEM (70656 * 2)

__global__ __launch_bounds__(256) void attn_hmma(
    const __nv_bfloat16* __restrict__ Qhi, const __nv_bfloat16* __restrict__ Qlo,
    const __nv_bfloat16* __restrict__ Khi, const __nv_bfloat16* __restrict__ Klo,
    const uint32_t* __restrict__ VTp,
    __nv_bfloat16* __restrict__ Ohi, __nv_bfloat16* __restrict__ Olo)
{
    extern __shared__ __nv_bfloat16 sm[];
    __nv_bfloat16* Qh = sm + SM_QH;
    __nv_bfloat16* Ql = sm + SM_QL;
    __nv_bfloat16* Kh = sm + SM_KH;
    __nv_bfloat16* Kl = sm + SM_KL;
    __nv_bfloat16* Vh = sm + SM_VH;
    __nv_bfloat16* Vl = sm + SM_VL;

    const int tid = threadIdx.x, lane = tid & 31, wid = tid >> 5;
    const int qb = blockIdx.x * 128, h = blockIdx.y;

    const int a_r = lane & 15, a_c = (lane >> 4) * 8;
    const int b_n = ((lane >> 4) & 1) * 8 + (lane & 7);
    const int b_k = ((lane >> 3) & 1) * 8;
    const int qrow = wid * 16;           // warp's query-row base

    // Q tile: direct bf16 copies (Q already pre-scaled by SCALE in projection)
    {
        const int r = tid >> 1, cs = (tid & 1) * 64;
        const __nv_bfloat16* qh = Qhi + (size_t)(qb + r) * HDIM + h * HD + cs;
        const __nv_bfloat16* ql = Qlo + (size_t)(qb + r) * HDIM + h * HD + cs;
#pragma unroll
        for (int j = 0; j < 8; j++) {
            *(uint4*)(Qh + r * LDQ + cs + j * 8) = *(const uint4*)(qh + j * 8);
            *(uint4*)(Ql + r * LDQ + cs + j * 8) = *(const uint4*)(ql + j * 8);
        }
    }

    // per-thread softmax state for its two rows (r, r+8)
    float m0 = -INFINITY, m1 = -INFINITY, l0 = 0.f, l1 = 0.f;

    float oacc[16][4];
#pragma unroll
    for (int nt = 0; nt < 16; nt++)
#pragma unroll
        for (int j = 0; j < 4; j++) oacc[nt][j] = 0.f;

    for (int t = 0; t < S_LEN / 64; t++) {
        __syncthreads();
        // K tile 64x128
        {
            const int r = tid >> 2, cs = (tid & 3) * 32;
            const __nv_bfloat16* kh = Khi + (size_t)(t * 64 + r) * HDIM + h * HD + cs;
            const __nv_bfloat16* kl = Klo + (size_t)(t * 64 + r) * HDIM + h * HD + cs;
#pragma unroll
            for (int j = 0; j < 4; j++) {
                *(uint4*)(Kh + r * LDQ + cs + j * 8) = *(const uint4*)(kh + j * 8);
                *(uint4*)(Kl + r * LDQ + cs + j * 8) = *(const uint4*)(kl + j * 8);
            }
        }
        // VT tile 128(d) x 64(k) from packed
        {
            const int r = tid >> 1, cs = (tid & 1) * 32;
            const uint32_t* vp = VTp + (size_t)(h * HD + r) * S_LEN + t * 64 + cs;
#pragma unroll
            for (int j = 0; j < 8; j++) {
                uint4 w = *(const uint4*)(vp + j * 4);
                uint32_t* vh = (uint32_t*)(Vh + r * LDV + cs + j * 4);
                uint32_t* vl = (uint32_t*)(Vl + r * LDV + cs + j * 4);
                vh[0] = __byte_perm(w.x, w.y, 0x5410);
                vl[0] = __byte_perm(w.x, w.y, 0x7632);
                vh[1] = __byte_perm(w.z, w.w, 0x5410);
                vl[1] = __byte_perm(w.z, w.w, 0x7632);
            }
        }
        __syncthreads();

        // ---- Phase 1: S = Q K^T  (warp: 16q x 64k) ----
        float sacc[8][4];
#pragma unroll
        for (int nt = 0; nt < 8; nt++)
#pragma unroll
            for (int j = 0; j < 4; j++) sacc[nt][j] = 0.f;

#pragma unroll
        for (int ks = 0; ks < 8; ks++) {
            const int k0 = ks * 16;
            uint32_t ah[4], al[4], bh[4][4], bl[4][4];
            {
                int off = (qrow + a_r) * LDQ + k0 + a_c;
                ldsm4(ah, smem_u32(Qh + off));
                ldsm4(al, smem_u32(Ql + off));
            }
#pragma unroll
            for (int g = 0; g < 4; g++) {
                int off = (g * 16 + b_n) * LDQ + k0 + b_k;
                ldsm4(bh[g], smem_u32(Kh + off));
                ldsm4(bl[g], smem_u32(Kl + off));
            }
#pragma unroll
            for (int nt = 0; nt < 8; nt++) {
                const uint32_t* bhp = &bh[nt >> 1][(nt & 1) * 2];
                const uint32_t* blp = &bl[nt >> 1][(nt & 1) * 2];
                mma_bf16(sacc[nt], ah, bhp);
                mma_bf16(sacc[nt], ah, blp);
                mma_bf16(sacc[nt], al, bhp);
            }
        }

        // ---- warp-local online softmax ----
        float tm0 = -INFINITY, tm1 = -INFINITY;
#pragma unroll
        for (int nt = 0; nt < 8; nt++) {
            tm0 = fmaxf(tm0, fmaxf(sacc[nt][0], sacc[nt][1]));
            tm1 = fmaxf(tm1, fmaxf(sacc[nt][2], sacc[nt][3]));
        }
        tm0 = fmaxf(tm0, __shfl_xor_sync(0xffffffffu, tm0, 1));
        tm0 = fmaxf(tm0, __shfl_xor_sync(0xffffffffu, tm0, 2));
        tm1 = fmaxf(tm1, __shfl_xor_sync(0xffffffffu, tm1, 1));
        tm1 = fmaxf(tm1, __shfl_xor_sync(0xffffffffu, tm1, 2));
        const float mn0 = fmaxf(m0, tm0), mn1 = fmaxf(m1, tm1);
        const float c0 = __expf(m0 - mn0), c1 = __expf(m1 - mn1);
        m0 = mn0; m1 = mn1;

        float ls0 = 0.f, ls1 = 0.f;
#pragma unroll
        for (int nt = 0; nt < 8; nt++) {
            sacc[nt][0] = __expf(sacc[nt][0] - mn0);
            sacc[nt][1] = __expf(sacc[nt][1] - mn0);
            sacc[nt][2] = __expf(sacc[nt][2] - mn1);
            sacc[nt][3] = __expf(sacc[nt][3] - mn1);
            ls0 += sacc[nt][0] + sacc[nt][1];
            ls1 += sacc[nt][2] + sacc[nt][3];
        }
        ls0 += __shfl_xor_sync(0xffffffffu, ls0, 1);
        ls0 += __shfl_xor_sync(0xffffffffu, ls0, 2);
        ls1 += __shfl_xor_sync(0xffffffffu, ls1, 1);
        ls1 += __shfl_xor_sync(0xffffffffu, ls1, 2);
        l0 = l0 * c0 + ls0;
        l1 = l1 * c1 + ls1;

        // rescale O accumulators
#pragma unroll
        for (int nt = 0; nt < 16; nt++) {
            oacc[nt][0] *= c0; oacc[nt][1] *= c0;
            oacc[nt][2] *= c1; oacc[nt][3] *= c1;
        }

        // ---- Phase 2: O += P V  (P as register A-fragments) ----
#pragma unroll
        for (int ks = 0; ks < 4; ks++) {
            uint32_t ph4[4], pl4[4];
            split_pack2(sacc[2 * ks][0], sacc[2 * ks][1], ph4[0], pl4[0]);
            split_pack2(sacc[2 * ks][2], sacc[2 * ks][3], ph4[1], pl4[1]);
            split_pack2(sacc[2 * ks + 1][0], sacc[2 * ks + 1][1], ph4[2], pl4[2]);
            split_pack2(sacc[2 * ks + 1][2], sacc[2 * ks + 1][3], ph4[3], pl4[3]);
            const int k0 = ks * 16;
#pragma unroll
            for (int g = 0; g < 8; g++) {
                uint32_t vh[4], vl[4];
                int off = (g * 16 + b_n) * LDV + k0 + b_k;
                ldsm4(vh, smem_u32(Vh + off));
                ldsm4(vl, smem_u32(Vl + off));
#pragma unroll
                for (int sub = 0; sub < 2; sub++) {
                    const int nt = g * 2 + sub;
                    mma_bf16(oacc[nt], ph4, &vh[sub * 2]);
                    mma_bf16(oacc[nt], ph4, &vl[sub * 2]);
                    mma_bf16(oacc[nt], pl4, &vh[sub * 2]);
                }
            }
        }
    }

    // ---- epilogue: normalize + hi/lo split out ----
    const float inv0 = 1.f / l0, inv1 = 1.f / l1;
    const int r0 = qrow + (lane >> 2);
#pragma unroll
    for (int nt = 0; nt < 16; nt++) {
        const int col = nt * 8 + (lane & 3) * 2;
        size_t i0 = (size_t)(qb + r0) * HDIM + h * HD + col;
        size_t i1 = (size_t)(qb + r0 + 8) * HDIM + h * HD + col;
        split_store2(Ohi + i0, Olo + i0, oacc[nt][0] * inv0, oacc[nt][1] * inv0);
        split_store2(Ohi + i1, Olo + i1, oacc[nt][2] * inv1, oacc[nt][3] * inv1);
    }
}

// ---------------- launch ----------------
extern "C" void kernel_launch(void* const* d_in, const int* in_sizes, int n_in,
                              void* d_out, int out_size)
{
    const float* hidden = (const float*)d_in[0];
    const float* Wq = (const float*)d_in[1];
    const float* bq = (const float*)d_in[2];
    const float* Wk = (const float*)d_in[3];
    const float* bk = (const float*)d_in[4];
    const float* Wv = (const float*)d_in[5];
    const float* bv = (const float*)d_in[6];
    const float* Wo = (const float*)d_in[7];
    const float* bo = (const float*)d_in[8];
    float* out = (float*)d_out;

    __nv_bfloat16 *Hhi, *Hlo, *Wqhi, *Wqlo, *Wkhi, *Wklo, *Wvhi, *Wvlo,
                  *Wohi, *Wolo, *Qhi, *Qlo, *Khi, *Klo, *Ohi, *Olo;
    uint32_t *Vp, *VTp;
    cudaGetSymbolAddress((void**)&Hhi, g_Hhi);  cudaGetSymbolAddress((void**)&Hlo, g_Hlo);
    cudaGetSymbolAddress((void**)&Wqhi, g_Wqhi); cudaGetSymbolAddress((void**)&Wqlo, g_Wqlo);
    cudaGetSymbolAddress((void**)&Wkhi, g_Wkhi); cudaGetSymbolAddress((void**)&Wklo, g_Wklo);
    cudaGetSymbolAddress((void**)&Wvhi, g_Wvhi); cudaGetSymbolAddress((void**)&Wvlo, g_Wvlo);
    cudaGetSymbolAddress((void**)&Wohi, g_Wohi); cudaGetSymbolAddress((void**)&Wolo, g_Wolo);
    cudaGetSymbolAddress((void**)&Qhi, g_Qhi);   cudaGetSymbolAddress((void**)&Qlo, g_Qlo);
    cudaGetSymbolAddress((void**)&Khi, g_Khi);   cudaGetSymbolAddress((void**)&Klo, g_Klo);
    cudaGetSymbolAddress((void**)&Ohi, g_Ohi);   cudaGetSymbolAddress((void**)&Olo, g_Olo);
    cudaGetSymbolAddress((void**)&Vp, g_Vp);     cudaGetSymbolAddress((void**)&VTp, g_VTp);

    cudaFuncSetAttribute(gemm_hmma<0>, cudaFuncAttributeMaxDynamicSharedMemorySize, GEMM_SMEM);
    cudaFuncSetAttribute(gemm_hmma<1>, cudaFuncAttributeMaxDynamicSharedMemorySize, GEMM_SMEM);
    cudaFuncSetAttribute(gemm_hmma<2>, cudaFuncAttributeMaxDynamicSharedMemorySize, GEMM_SMEM);
    cudaFuncSetAttribute(attn_hmma, cudaFuncAttributeMaxDynamicSharedMemorySize, ATT_SMEM);

    const int nH4 = S_LEN * HDIM / 4, nW4 = HDIM * HDIM / 4;
    split_pre<<<nH4 / 256, 256>>>(hidden, Hhi, Hlo, nH4);
    split_pre<<<nW4 / 256, 256>>>(Wq, Wqhi, Wqlo, nW4);
    split_pre<<<nW4 / 256, 256>>>(Wk, Wkhi, Wklo, nW4);
    split_pre<<<nW4 / 256, 256>>>(Wv, Wvhi, Wvlo, nW4);
    split_pre<<<nW4 / 256, 256>>>(Wo, Wohi, Wolo, nW4);

    dim3 ggrid(HDIM / 128, S_LEN / 128);   // (16, 32)
    // Q projection pre-scaled by 1/sqrt(HD)
    gemm_hmma<1><<<ggrid, 256, GEMM_SMEM>>>(Hhi, Hlo, Wqhi, Wqlo, bq, SCALE,
                                            nullptr, Qhi, Qlo, nullptr,
                                            S_LEN, HDIM, HDIM);
    gemm_hmma<1><<<ggrid, 256, GEMM_SMEM>>>(Hhi, Hlo, Wkhi, Wklo, bk, 1.f,
                                            nullptr, Khi, Klo, nullptr,
                                            S_LEN, HDIM, HDIM);
    gemm_hmma<2><<<ggrid, 256, GEMM_SMEM>>>(Hhi, Hlo, Wvhi, Wvlo, bv, 1.f,
                                            nullptr, nullptr, nullptr, Vp,
                                            S_LEN, HDIM, HDIM);

    dim3 tgrid(HDIM / 32, S_LEN / 32);
    transpose_u32<<<tgrid, dim3(32, 8)>>>(Vp, VTp);

    dim3 agrid(S_LEN / 128, NHEADS);       // (32, 16)
    attn_hmma<<<agrid, 256, ATT_SMEM>>>(Qhi, Qlo, Khi, Klo, VTp, Ohi, Olo);

    gemm_hmma<0><<<ggrid, 256, GEMM_SMEM>>>(Ohi, Olo, Wohi, Wolo, bo, 1.f,
                                            out, nullptr, nullptr, nullptr,
                                            S_LEN, HDIM, HDIM);
}

// round 8
// speedup vs baseline: 3.1220x; 1.0826x over previous
#include <cuda_runtime.h>
#include <cuda_bf16.h>
#include <cstdint>
#include <math.h>

#define S_LEN 4096
#define HDIM  2048
#define NHEADS 16
#define HD    128
#define SCALE 0.08838834764831845f

// ---------------- scratch globals ----------------
__device__ __nv_bfloat16 g_Hhi[S_LEN * HDIM], g_Hlo[S_LEN * HDIM];
__device__ __nv_bfloat16 g_Wqhi[HDIM * HDIM], g_Wqlo[HDIM * HDIM];
__device__ __nv_bfloat16 g_Wkhi[HDIM * HDIM], g_Wklo[HDIM * HDIM];
__device__ __nv_bfloat16 g_Wvhi[HDIM * HDIM], g_Wvlo[HDIM * HDIM];
__device__ __nv_bfloat16 g_Wohi[HDIM * HDIM], g_Wolo[HDIM * HDIM];
__device__ __nv_bfloat16 g_Qhi[S_LEN * HDIM], g_Qlo[S_LEN * HDIM];
__device__ __nv_bfloat16 g_Khi[S_LEN * HDIM], g_Klo[S_LEN * HDIM];
__device__ uint32_t      g_Vp [S_LEN * HDIM];
__device__ __nv_bfloat16 g_VThi[HDIM * S_LEN], g_VTlo[HDIM * S_LEN];
__device__ __nv_bfloat16 g_Ohi[S_LEN * HDIM], g_Olo[S_LEN * HDIM];

// ---------------- helpers ----------------
__device__ __forceinline__ uint32_t smem_u32(const void* p) {
    uint32_t a;
    asm("{ .reg .u64 t; cvta.to.shared.u64 t, %1; cvt.u32.u64 %0, t; }"
        : "=r"(a) : "l"(p));
    return a;
}
__device__ __forceinline__ void ldsm4(uint32_t* r, uint32_t a) {
    asm volatile("ldmatrix.sync.aligned.m8n8.x4.shared.b16 {%0,%1,%2,%3}, [%4];"
        : "=r"(r[0]), "=r"(r[1]), "=r"(r[2]), "=r"(r[3]) : "r"(a));
}
__device__ __forceinline__ void mma_bf16(float* c, const uint32_t* a,
                                         const uint32_t* b) {
    asm volatile("mma.sync.aligned.m16n8k16.row.col.f32.bf16.bf16.f32 "
        "{%0,%1,%2,%3}, {%4,%5,%6,%7}, {%8,%9}, {%0,%1,%2,%3};"
        : "+f"(c[0]), "+f"(c[1]), "+f"(c[2]), "+f"(c[3])
        : "r"(a[0]), "r"(a[1]), "r"(a[2]), "r"(a[3]), "r"(b[0]), "r"(b[1]));
}
__device__ __forceinline__ void split_store2(__nv_bfloat16* hi,
                                             __nv_bfloat16* lo,
                                             float x, float y) {
    __nv_bfloat16 hx = __float2bfloat16(x), hy = __float2bfloat16(y);
    __nv_bfloat162 h2; h2.x = hx; h2.y = hy;
    __nv_bfloat162 l2;
    l2.x = __float2bfloat16(x - __bfloat162float(hx));
    l2.y = __float2bfloat16(y - __bfloat162float(hy));
    *reinterpret_cast<__nv_bfloat162*>(hi) = h2;
    *reinterpret_cast<__nv_bfloat162*>(lo) = l2;
}
__device__ __forceinline__ uint32_t pack_hl(float x) {
    __nv_bfloat16 h = __float2bfloat16(x);
    __nv_bfloat16 l = __float2bfloat16(x - __bfloat162float(h));
    uint16_t hb = *(uint16_t*)&h, lb = *(uint16_t*)&l;
    return (uint32_t)hb | ((uint32_t)lb << 16);
}
__device__ __forceinline__ void split_pack2(float x, float y,
                                            uint32_t& hi, uint32_t& lo) {
    __nv_bfloat16 hx = __float2bfloat16(x), hy = __float2bfloat16(y);
    __nv_bfloat16 lx = __float2bfloat16(x - __bfloat162float(hx));
    __nv_bfloat16 ly = __float2bfloat16(y - __bfloat162float(hy));
    uint16_t a = *(uint16_t*)&hx, b = *(uint16_t*)&hy;
    uint16_t c = *(uint16_t*)&lx, d = *(uint16_t*)&ly;
    hi = (uint32_t)a | ((uint32_t)b << 16);
    lo = (uint32_t)c | ((uint32_t)d << 16);
}
#define CP_ASYNC16(dst, src) \
    asm volatile("cp.async.cg.shared.global [%0], [%1], 16;\n" \
                 :: "r"(dst), "l"(src))
#define CP_COMMIT asm volatile("cp.async.commit_group;\n" ::: "memory")
#define CP_WAIT0  asm volatile("cp.async.wait_group 0;\n" ::: "memory")
#define CP_WAIT1  asm volatile("cp.async.wait_group 1;\n" ::: "memory")

// ---------------- prepass: fp32 -> bf16 hi/lo ----------------
__global__ __launch_bounds__(256) void split_pre(
    const float* __restrict__ in, __nv_bfloat16* __restrict__ hi,
    __nv_bfloat16* __restrict__ lo, int n4)
{
    int i = blockIdx.x * blockDim.x + threadIdx.x;
    if (i < n4) {
        float4 v = ((const float4*)in)[i];
        split_store2(hi + i * 4, lo + i * 4, v.x, v.y);
        split_store2(hi + i * 4 + 2, lo + i * 4 + 2, v.z, v.w);
    }
}

// ---------------- HMMA GEMM (NT + bias)*scale, cp.async 2-stage ----------
#define LDAB 40
#define STG_BYTES 40960
#define GEMM_SMEM (2 * STG_BYTES)

template <int OUT_MODE>
__global__ __launch_bounds__(256) void gemm_hmma(
    const __nv_bfloat16* __restrict__ Ahi, const __nv_bfloat16* __restrict__ Alo,
    const __nv_bfloat16* __restrict__ Bhi, const __nv_bfloat16* __restrict__ Blo,
    const float* __restrict__ bias, float scale,
    float* __restrict__ Cf, __nv_bfloat16* __restrict__ Chi,
    __nv_bfloat16* __restrict__ Clo, uint32_t* __restrict__ Cp,
    int M, int N, int K)
{
    extern __shared__ char smraw[];
    const uint32_t sb = smem_u32(smraw);

    const int tid = threadIdx.x, lane = tid & 31, wid = tid >> 5;
    const int wm = wid >> 2, wn = wid & 3;
    const int bm = blockIdx.y * 128, bn = blockIdx.x * 128;
    const int m0 = wm * 64, n0 = wn * 32;

    const int a_r = lane & 15, a_c = (lane >> 4) * 8;
    const int b_n = ((lane >> 4) & 1) * 8 + (lane & 7);
    const int b_k = ((lane >> 3) & 1) * 8;

    const int l_row0 = (tid * 2) >> 2, l_c0 = ((tid * 2) & 3) * 8;
    const int l_row1 = (tid * 2 + 1) >> 2, l_c1 = ((tid * 2 + 1) & 3) * 8;

    float acc[4][4][4];
#pragma unroll
    for (int mt = 0; mt < 4; mt++)
#pragma unroll
        for (int nt = 0; nt < 4; nt++)
#pragma unroll
            for (int j = 0; j < 4; j++) acc[mt][nt][j] = 0.f;

    const int nIter = K / 32;

    auto load_stage = [&](int kc, int s) {
        const uint32_t st = sb + s * STG_BYTES;
        const int k0 = kc * 32;
        CP_ASYNC16(st + (l_row0 * LDAB + l_c0) * 2,
                   Ahi + (size_t)(bm + l_row0) * K + k0 + l_c0);
        CP_ASYNC16(st + (l_row1 * LDAB + l_c1) * 2,
                   Ahi + (size_t)(bm + l_row1) * K + k0 + l_c1);
        CP_ASYNC16(st + 10240 + (l_row0 * LDAB + l_c0) * 2,
                   Alo + (size_t)(bm + l_row0) * K + k0 + l_c0);
        CP_ASYNC16(st + 10240 + (l_row1 * LDAB + l_c1) * 2,
                   Alo + (size_t)(bm + l_row1) * K + k0 + l_c1);
        CP_ASYNC16(st + 20480 + (l_row0 * LDAB + l_c0) * 2,
                   Bhi + (size_t)(bn + l_row0) * K + k0 + l_c0);
        CP_ASYNC16(st + 20480 + (l_row1 * LDAB + l_c1) * 2,
                   Bhi + (size_t)(bn + l_row1) * K + k0 + l_c1);
        CP_ASYNC16(st + 30720 + (l_row0 * LDAB + l_c0) * 2,
                   Blo + (size_t)(bn + l_row0) * K + k0 + l_c0);
        CP_ASYNC16(st + 30720 + (l_row1 * LDAB + l_c1) * 2,
                   Blo + (size_t)(bn + l_row1) * K + k0 + l_c1);
        CP_COMMIT;
    };

    load_stage(0, 0);
    for (int kc = 0; kc < nIter; kc++) {
        const int s = kc & 1;
        CP_WAIT0;
        __syncthreads();
        if (kc + 1 < nIter) load_stage(kc + 1, s ^ 1);

        const uint32_t st = sb + s * STG_BYTES;
#pragma unroll
        for (int ks = 0; ks < 2; ks++) {
            const int k0 = ks * 16;
            uint32_t ah[4][4], al[4][4], bh[2][4], bl[2][4];
#pragma unroll
            for (int mt = 0; mt < 4; mt++) {
                int off = ((m0 + mt * 16 + a_r) * LDAB + k0 + a_c) * 2;
                ldsm4(ah[mt], st + off);
                ldsm4(al[mt], st + 10240 + off);
            }
#pragma unroll
            for (int bp = 0; bp < 2; bp++) {
                int off = ((n0 + bp * 16 + b_n) * LDAB + k0 + b_k) * 2;
                ldsm4(bh[bp], st + 20480 + off);
                ldsm4(bl[bp], st + 30720 + off);
            }
#pragma unroll
            for (int mt = 0; mt < 4; mt++)
#pragma unroll
                for (int nt = 0; nt < 4; nt++) {
                    const uint32_t* bhp = &bh[nt >> 1][(nt & 1) * 2];
                    const uint32_t* blp = &bl[nt >> 1][(nt & 1) * 2];
                    mma_bf16(acc[mt][nt], ah[mt], bhp);
                    mma_bf16(acc[mt][nt], ah[mt], blp);
                    mma_bf16(acc[mt][nt], al[mt], bhp);
                }
        }
    }

#pragma unroll
    for (int mt = 0; mt < 4; mt++) {
        const int r0 = bm + m0 + mt * 16 + (lane >> 2);
#pragma unroll
        for (int nt = 0; nt < 4; nt++) {
            const int col = bn + n0 + nt * 8 + (lane & 3) * 2;
            float2 bv = *(const float2*)(bias + col);
            float c00 = (acc[mt][nt][0] + bv.x) * scale;
            float c01 = (acc[mt][nt][1] + bv.y) * scale;
            float c10 = (acc[mt][nt][2] + bv.x) * scale;
            float c11 = (acc[mt][nt][3] + bv.y) * scale;
            if (OUT_MODE == 0) {
                *(float2*)(Cf + (size_t)r0 * N + col) = make_float2(c00, c01);
                *(float2*)(Cf + (size_t)(r0 + 8) * N + col) = make_float2(c10, c11);
            } else if (OUT_MODE == 1) {
                split_store2(Chi + (size_t)r0 * N + col,
                             Clo + (size_t)r0 * N + col, c00, c01);
                split_store2(Chi + (size_t)(r0 + 8) * N + col,
                             Clo + (size_t)(r0 + 8) * N + col, c10, c11);
            } else {
                *(uint2*)(Cp + (size_t)r0 * N + col) =
                    make_uint2(pack_hl(c00), pack_hl(c01));
                *(uint2*)(Cp + (size_t)(r0 + 8) * N + col) =
                    make_uint2(pack_hl(c10), pack_hl(c11));
            }
        }
    }
}

// ------- transpose packed u32 -> separate hi/lo bf16 planes -------
__global__ __launch_bounds__(256) void transpose_hl(
    const uint32_t* __restrict__ in, __nv_bfloat16* __restrict__ oh,
    __nv_bfloat16* __restrict__ ol)
{
    __shared__ uint32_t tile[32][33];
    const int cb = blockIdx.x * 32, sbk = blockIdx.y * 32;
    const int tx = threadIdx.x, ty = threadIdx.y;
#pragma unroll
    for (int j = 0; j < 4; j++)
        tile[ty + j * 8][tx] = in[(size_t)(sbk + ty + j * 8) * HDIM + cb + tx];
    __syncthreads();
#pragma unroll
    for (int j = 0; j < 4; j++) {
        uint32_t w = tile[tx][ty + j * 8];
        size_t o = (size_t)(cb + ty + j * 8) * S_LEN + sbk + tx;
        uint16_t hb = (uint16_t)(w & 0xffffu), lb = (uint16_t)(w >> 16);
        oh[o] = *(__nv_bfloat16*)&hb;
        ol[o] = *(__nv_bfloat16*)&lb;
    }
}

// ---------------- HMMA flash attention, FA2 + cp.async pipeline ----------
// CTA = (128 queries, 1 head). warp w owns rows [w*16, w*16+16). 64-key tiles.
// smem element offsets (bf16):
//   Qh 0, Ql 17408, stage s: base 34816 + s*35840:
//     Kh +0 (8704), Kl +8704, Vh +17408 (9216), Vl +26624; stage end 35840
#define LDQ 136
#define LDV 72
#define AQL 17408
#define ASTG0 34816
#define ASTG  35840
#define AKL 8704
#define AVH 17408
#define AVL 26624
#define ATT_SMEM 212992

__global__ __launch_bounds__(256) void attn_hmma(
    const __nv_bfloat16* __restrict__ Qhi, const __nv_bfloat16* __restrict__ Qlo,
    const __nv_bfloat16* __restrict__ Khi, const __nv_bfloat16* __restrict__ Klo,
    const __nv_bfloat16* __restrict__ VThi, const __nv_bfloat16* __restrict__ VTlo,
    __nv_bfloat16* __restrict__ Ohi, __nv_bfloat16* __restrict__ Olo)
{
    extern __shared__ __nv_bfloat16 sm[];
    const uint32_t sb = smem_u32(sm);

    const int tid = threadIdx.x, lane = tid & 31, wid = tid >> 5;
    const int qb = blockIdx.x * 128, h = blockIdx.y;

    const int a_r = lane & 15, a_c = (lane >> 4) * 8;
    const int b_n = ((lane >> 4) & 1) * 8 + (lane & 7);
    const int b_k = ((lane >> 3) & 1) * 8;
    const int qrow = wid * 16;

    // K load mapping: 4 threads/row, 4 chunks each
    const int k_r = tid >> 2, k_c = (tid & 3) * 32;
    // V load mapping: 2 threads/row, 4 chunks each
    const int v_r = tid >> 1, v_c = (tid & 1) * 32;

    auto load_kv = [&](int t, int s) {
        const uint32_t stg = sb + (ASTG0 + s * ASTG) * 2;
        const __nv_bfloat16* kh = Khi + (size_t)(t * 64 + k_r) * HDIM + h * HD + k_c;
        const __nv_bfloat16* kl = Klo + (size_t)(t * 64 + k_r) * HDIM + h * HD + k_c;
#pragma unroll
        for (int j = 0; j < 4; j++) {
            CP_ASYNC16(stg + (k_r * LDQ + k_c + j * 8) * 2, kh + j * 8);
            CP_ASYNC16(stg + (AKL + k_r * LDQ + k_c + j * 8) * 2, kl + j * 8);
        }
        const __nv_bfloat16* vh = VThi + (size_t)(h * HD + v_r) * S_LEN + t * 64 + v_c;
        const __nv_bfloat16* vl = VTlo + (size_t)(h * HD + v_r) * S_LEN + t * 64 + v_c;
#pragma unroll
        for (int j = 0; j < 4; j++) {
            CP_ASYNC16(stg + (AVH + v_r * LDV + v_c + j * 8) * 2, vh + j * 8);
            CP_ASYNC16(stg + (AVL + v_r * LDV + v_c + j * 8) * 2, vl + j * 8);
        }
        CP_COMMIT;
    };

    // Q tile via cp.async (Q pre-scaled in projection): 2 threads/row, 8 chunks
    {
        const int r = tid >> 1, cs = (tid & 1) * 64;
        const __nv_bfloat16* qh = Qhi + (size_t)(qb + r) * HDIM + h * HD + cs;
        const __nv_bfloat16* ql = Qlo + (size_t)(qb + r) * HDIM + h * HD + cs;
#pragma unroll
        for (int j = 0; j < 8; j++) {
            CP_ASYNC16(sb + (r * LDQ + cs + j * 8) * 2, qh + j * 8);
            CP_ASYNC16(sb + (AQL + r * LDQ + cs + j * 8) * 2, ql + j * 8);
        }
    }
    load_kv(0, 0);   // commits group containing Q + tile 0

    float m0 = -INFINITY, m1 = -INFINITY, l0 = 0.f, l1 = 0.f;
    float oacc[16][4];
#pragma unroll
    for (int nt = 0; nt < 16; nt++)
#pragma unroll
        for (int j = 0; j < 4; j++) oacc[nt][j] = 0.f;

    const int NT = S_LEN / 64;
    for (int t = 0; t < NT; t++) {
        const int s = t & 1;
        if (t + 1 < NT) { load_kv(t + 1, s ^ 1); CP_WAIT1; }
        else            { CP_WAIT0; }
        __syncthreads();

        const uint32_t stg = sb + (ASTG0 + s * ASTG) * 2;

        // ---- Phase 1: S = Q K^T  (warp: 16q x 64k) ----
        float sacc[8][4];
#pragma unroll
        for (int nt = 0; nt < 8; nt++)
#pragma unroll
            for (int j = 0; j < 4; j++) sacc[nt][j] = 0.f;

#pragma unroll
        for (int ks = 0; ks < 8; ks++) {
            const int k0 = ks * 16;
            uint32_t ah[4], al[4], bh[4][4], bl[4][4];
            {
                int off = ((qrow + a_r) * LDQ + k0 + a_c) * 2;
                ldsm4(ah, sb + off);
                ldsm4(al, sb + AQL * 2 + off);
            }
#pragma unroll
            for (int g = 0; g < 4; g++) {
                int off = ((g * 16 + b_n) * LDQ + k0 + b_k) * 2;
                ldsm4(bh[g], stg + off);
                ldsm4(bl[g], stg + AKL * 2 + off);
            }
#pragma unroll
            for (int nt = 0; nt < 8; nt++) {
                const uint32_t* bhp = &bh[nt >> 1][(nt & 1) * 2];
                const uint32_t* blp = &bl[nt >> 1][(nt & 1) * 2];
                mma_bf16(sacc[nt], ah, bhp);
                mma_bf16(sacc[nt], ah, blp);
                mma_bf16(sacc[nt], al, bhp);
            }
        }

        // ---- warp-local online softmax ----
        float tm0 = -INFINITY, tm1 = -INFINITY;
#pragma unroll
        for (int nt = 0; nt < 8; nt++) {
            tm0 = fmaxf(tm0, fmaxf(sacc[nt][0], sacc[nt][1]));
            tm1 = fmaxf(tm1, fmaxf(sacc[nt][2], sacc[nt][3]));
        }
        tm0 = fmaxf(tm0, __shfl_xor_sync(0xffffffffu, tm0, 1));
        tm0 = fmaxf(tm0, __shfl_xor_sync(0xffffffffu, tm0, 2));
        tm1 = fmaxf(tm1, __shfl_xor_sync(0xffffffffu, tm1, 1));
        tm1 = fmaxf(tm1, __shfl_xor_sync(0xffffffffu, tm1, 2));
        const float mn0 = fmaxf(m0, tm0), mn1 = fmaxf(m1, tm1);
        const float c0 = __expf(m0 - mn0), c1 = __expf(m1 - mn1);
        m0 = mn0; m1 = mn1;

        float ls0 = 0.f, ls1 = 0.f;
#pragma unroll
        for (int nt = 0; nt < 8; nt++) {
            sacc[nt][0] = __expf(sacc[nt][0] - mn0);
            sacc[nt][1] = __expf(sacc[nt][1] - mn0);
            sacc[nt][2] = __expf(sacc[nt][2] - mn1);
            sacc[nt][3] = __expf(sacc[nt][3] - mn1);
            ls0 += sacc[nt][0] + sacc[nt][1];
            ls1 += sacc[nt][2] + sacc[nt][3];
        }
        ls0 += __shfl_xor_sync(0xffffffffu, ls0, 1);
        ls0 += __shfl_xor_sync(0xffffffffu, ls0, 2);
        ls1 += __shfl_xor_sync(0xffffffffu, ls1, 1);
        ls1 += __shfl_xor_sync(0xffffffffu, ls1, 2);
        l0 = l0 * c0 + ls0;
        l1 = l1 * c1 + ls1;

#pragma unroll
        for (int nt = 0; nt < 16; nt++) {
            oacc[nt][0] *= c0; oacc[nt][1] *= c0;
            oacc[nt][2] *= c1; oacc[nt][3] *= c1;
        }

        // ---- Phase 2: O += P V  (P as register A-fragments) ----
#pragma unroll
        for (int ks = 0; ks < 4; ks++) {
            uint32_t ph4[4], pl4[4];
            split_pack2(sacc[2 * ks][0], sacc[2 * ks][1], ph4[0], pl4[0]);
            split_pack2(sacc[2 * ks][2], sacc[2 * ks][3], ph4[1], pl4[1]);
            split_pack2(sacc[2 * ks + 1][0], sacc[2 * ks + 1][1], ph4[2], pl4[2]);
            split_pack2(sacc[2 * ks + 1][2], sacc[2 * ks + 1][3], ph4[3], pl4[3]);
            const int k0 = ks * 16;
#pragma unroll
            for (int g = 0; g < 8; g++) {
                uint32_t vh[4], vl[4];
                int off = ((g * 16 + b_n) * LDV + k0 + b_k) * 2;
                ldsm4(vh, stg + AVH * 2 + off);
                ldsm4(vl, stg + AVL * 2 + off);
#pragma unroll
                for (int sub = 0; sub < 2; sub++) {
                    const int nt = g * 2 + sub;
                    mma_bf16(oacc[nt], ph4, &vh[sub * 2]);
                    mma_bf16(oacc[nt], ph4, &vl[sub * 2]);
                    mma_bf16(oacc[nt], pl4, &vh[sub * 2]);
                }
            }
        }
        __syncthreads();   // all warps done with stage s before it is reloaded
    }

    // ---- epilogue ----
    const float inv0 = 1.f / l0, inv1 = 1.f / l1;
    const int r0 = qrow + (lane >> 2);
#pragma unroll
    for (int nt = 0; nt < 16; nt++) {
        const int col = nt * 8 + (lane & 3) * 2;
        size_t i0 = (size_t)(qb + r0) * HDIM + h * HD + col;
        size_t i1 = (size_t)(qb + r0 + 8) * HDIM + h * HD + col;
        split_store2(Ohi + i0, Olo + i0, oacc[nt][0] * inv0, oacc[nt][1] * inv0);
        split_store2(Ohi + i1, Olo + i1, oacc[nt][2] * inv1, oacc[nt][3] * inv1);
    }
}

// ---------------- launch ----------------
extern "C" void kernel_launch(void* const* d_in, const int* in_sizes, int n_in,
                              void* d_out, int out_size)
{
    const float* hidden = (const float*)d_in[0];
    const float* Wq = (const float*)d_in[1];
    const float* bq = (const float*)d_in[2];
    const float* Wk = (const float*)d_in[3];
    const float* bk = (const float*)d_in[4];
    const float* Wv = (const float*)d_in[5];
    const float* bv = (const float*)d_in[6];
    const float* Wo = (const float*)d_in[7];
    const float* bo = (const float*)d_in[8];
    float* out = (float*)d_out;

    __nv_bfloat16 *Hhi, *Hlo, *Wqhi, *Wqlo, *Wkhi, *Wklo, *Wvhi, *Wvlo,
                  *Wohi, *Wolo, *Qhi, *Qlo, *Khi, *Klo, *Ohi, *Olo, *VThi, *VTlo;
    uint32_t *Vp;
    cudaGetSymbolAddress((void**)&Hhi, g_Hhi);  cudaGetSymbolAddress((void**)&Hlo, g_Hlo);
    cudaGetSymbolAddress((void**)&Wqhi, g_Wqhi); cudaGetSymbolAddress((void**)&Wqlo, g_Wqlo);
    cudaGetSymbolAddress((void**)&Wkhi, g_Wkhi); cudaGetSymbolAddress((void**)&Wklo, g_Wklo);
    cudaGetSymbolAddress((void**)&Wvhi, g_Wvhi); cudaGetSymbolAddress((void**)&Wvlo, g_Wvlo);
    cudaGetSymbolAddress((void**)&Wohi, g_Wohi); cudaGetSymbolAddress((void**)&Wolo, g_Wolo);
    cudaGetSymbolAddress((void**)&Qhi, g_Qhi);   cudaGetSymbolAddress((void**)&Qlo, g_Qlo);
    cudaGetSymbolAddress((void**)&Khi, g_Khi);   cudaGetSymbolAddress((void**)&Klo, g_Klo);
    cudaGetSymbolAddress((void**)&Ohi, g_Ohi);   cudaGetSymbolAddress((void**)&Olo, g_Olo);
    cudaGetSymbolAddress((void**)&Vp, g_Vp);
    cudaGetSymbolAddress((void**)&VThi, g_VThi); cudaGetSymbolAddress((void**)&VTlo, g_VTlo);

    cudaFuncSetAttribute(gemm_hmma<0>, cudaFuncAttributeMaxDynamicSharedMemorySize, GEMM_SMEM);
    cudaFuncSetAttribute(gemm_hmma<1>, cudaFuncAttributeMaxDynamicSharedMemorySize, GEMM_SMEM);
    cudaFuncSetAttribute(gemm_hmma<2>, cudaFuncAttributeMaxDynamicSharedMemorySize, GEMM_SMEM);
    cudaFuncSetAttribute(attn_hmma, cudaFuncAttributeMaxDynamicSharedMemorySize, ATT_SMEM);

    const int nH4 = S_LEN * HDIM / 4, nW4 = HDIM * HDIM / 4;
    split_pre<<<nH4 / 256, 256>>>(hidden, Hhi, Hlo, nH4);
    split_pre<<<nW4 / 256, 256>>>(Wq, Wqhi, Wqlo, nW4);
    split_pre<<<nW4 / 256, 256>>>(Wk, Wkhi, Wklo, nW4);
    split_pre<<<nW4 / 256, 256>>>(Wv, Wvhi, Wvlo, nW4);
    split_pre<<<nW4 / 256, 256>>>(Wo, Wohi, Wolo, nW4);

    dim3 ggrid(HDIM / 128, S_LEN / 128);   // (16, 32)
    gemm_hmma<1><<<ggrid, 256, GEMM_SMEM>>>(Hhi, Hlo, Wqhi, Wqlo, bq, SCALE,
                                            nullptr, Qhi, Qlo, nullptr,
                                            S_LEN, HDIM, HDIM);
    gemm_hmma<1><<<ggrid, 256, GEMM_SMEM>>>(Hhi, Hlo, Wkhi, Wklo, bk, 1.f,
                                            nullptr, Khi, Klo, nullptr,
                                            S_LEN, HDIM, HDIM);
    gemm_hmma<2><<<ggrid, 256, GEMM_SMEM>>>(Hhi, Hlo, Wvhi, Wvlo, bv, 1.f,
                                            nullptr, nullptr, nullptr, Vp,
                                            S_LEN, HDIM, HDIM);

    dim3 tgrid(HDIM / 32, S_LEN / 32);
    transpose_hl<<<tgrid, dim3(32, 8)>>>(Vp, VThi, VTlo);

    dim3 agrid(S_LEN / 128, NHEADS);       // (32, 16)
    attn_hmma<<<agrid, 256, ATT_SMEM>>>(Qhi, Qlo, Khi, Klo, VThi, VTlo, Ohi, Olo);

    gemm_hmma<0><<<ggrid, 256, GEMM_SMEM>>>(Ohi, Olo, Wohi, Wolo, bo, 1.f,
                                            out, nullptr, nullptr, nullptr,
                                            S_LEN, HDIM, HDIM);
}

// round 9
// speedup vs baseline: 3.1777x; 1.0178x over previous
#include <cuda_runtime.h>
#include <cuda_bf16.h>
#include <cstdint>
#include <math.h>

#define S_LEN 4096
#define HDIM  2048
#define NHEADS 16
#define HD    128
#define SCALE 0.08838834764831845f
// SCALE * log2(e): scores come out of QK^T already in log2 units
#define SCALE2 0.1275332511737922f

// ---------------- scratch globals ----------------
__device__ __nv_bfloat16 g_Hhi[S_LEN * HDIM], g_Hlo[S_LEN * HDIM];
__device__ __nv_bfloat16 g_Wqhi[HDIM * HDIM], g_Wqlo[HDIM * HDIM];
__device__ __nv_bfloat16 g_Wkhi[HDIM * HDIM], g_Wklo[HDIM * HDIM];
__device__ __nv_bfloat16 g_Wvhi[HDIM * HDIM], g_Wvlo[HDIM * HDIM];
__device__ __nv_bfloat16 g_Wohi[HDIM * HDIM], g_Wolo[HDIM * HDIM];
__device__ __nv_bfloat16 g_Qhi[S_LEN * HDIM], g_Qlo[S_LEN * HDIM];
__device__ __nv_bfloat16 g_Khi[S_LEN * HDIM], g_Klo[S_LEN * HDIM];
__device__ uint32_t      g_Vp [S_LEN * HDIM];
__device__ __nv_bfloat16 g_VThi[HDIM * S_LEN], g_VTlo[HDIM * S_LEN];
__device__ __nv_bfloat16 g_Ohi[S_LEN * HDIM], g_Olo[S_LEN * HDIM];

// ---------------- helpers ----------------
__device__ __forceinline__ uint32_t smem_u32(const void* p) {
    uint32_t a;
    asm("{ .reg .u64 t; cvta.to.shared.u64 t, %1; cvt.u32.u64 %0, t; }"
        : "=r"(a) : "l"(p));
    return a;
}
__device__ __forceinline__ void ldsm4(uint32_t* r, uint32_t a) {
    asm volatile("ldmatrix.sync.aligned.m8n8.x4.shared.b16 {%0,%1,%2,%3}, [%4];"
        : "=r"(r[0]), "=r"(r[1]), "=r"(r[2]), "=r"(r[3]) : "r"(a));
}
__device__ __forceinline__ void mma_bf16(float* c, const uint32_t* a,
                                         const uint32_t* b) {
    asm volatile("mma.sync.aligned.m16n8k16.row.col.f32.bf16.bf16.f32 "
        "{%0,%1,%2,%3}, {%4,%5,%6,%7}, {%8,%9}, {%0,%1,%2,%3};"
        : "+f"(c[0]), "+f"(c[1]), "+f"(c[2]), "+f"(c[3])
        : "r"(a[0]), "r"(a[1]), "r"(a[2]), "r"(a[3]), "r"(b[0]), "r"(b[1]));
}
__device__ __forceinline__ float ex2f(float x) {
    float r;
    asm("ex2.approx.f32 %0, %1;" : "=f"(r) : "f"(x));
    return r;
}
__device__ __forceinline__ void split_store2(__nv_bfloat16* hi,
                                             __nv_bfloat16* lo,
                                             float x, float y) {
    __nv_bfloat16 hx = __float2bfloat16(x), hy = __float2bfloat16(y);
    __nv_bfloat162 h2; h2.x = hx; h2.y = hy;
    __nv_bfloat162 l2;
    l2.x = __float2bfloat16(x - __bfloat162float(hx));
    l2.y = __float2bfloat16(y - __bfloat162float(hy));
    *reinterpret_cast<__nv_bfloat162*>(hi) = h2;
    *reinterpret_cast<__nv_bfloat162*>(lo) = l2;
}
__device__ __forceinline__ uint32_t pack_hl(float x) {
    __nv_bfloat16 h = __float2bfloat16(x);
    __nv_bfloat16 l = __float2bfloat16(x - __bfloat162float(h));
    uint16_t hb = *(uint16_t*)&h, lb = *(uint16_t*)&l;
    return (uint32_t)hb | ((uint32_t)lb << 16);
}
__device__ __forceinline__ void split_pack2(float x, float y,
                                            uint32_t& hi, uint32_t& lo) {
    __nv_bfloat16 hx = __float2bfloat16(x), hy = __float2bfloat16(y);
    __nv_bfloat16 lx = __float2bfloat16(x - __bfloat162float(hx));
    __nv_bfloat16 ly = __float2bfloat16(y - __bfloat162float(hy));
    uint16_t a = *(uint16_t*)&hx, b = *(uint16_t*)&hy;
    uint16_t c = *(uint16_t*)&lx, d = *(uint16_t*)&ly;
    hi = (uint32_t)a | ((uint32_t)b << 16);
    lo = (uint32_t)c | ((uint32_t)d << 16);
}
#define CP_ASYNC16(dst, src) \
    asm volatile("cp.async.cg.shared.global [%0], [%1], 16;\n" \
                 :: "r"(dst), "l"(src))
#define CP_COMMIT asm volatile("cp.async.commit_group;\n" ::: "memory")
#define CP_WAIT0  asm volatile("cp.async.wait_group 0;\n" ::: "memory")
#define CP_WAIT1  asm volatile("cp.async.wait_group 1;\n" ::: "memory")

// ---------------- prepass: fp32 -> bf16 hi/lo ----------------
__global__ __launch_bounds__(256) void split_pre(
    const float* __restrict__ in, __nv_bfloat16* __restrict__ hi,
    __nv_bfloat16* __restrict__ lo, int n4)
{
    int i = blockIdx.x * blockDim.x + threadIdx.x;
    if (i < n4) {
        float4 v = ((const float4*)in)[i];
        split_store2(hi + i * 4, lo + i * 4, v.x, v.y);
        split_store2(hi + i * 4 + 2, lo + i * 4 + 2, v.z, v.w);
    }
}

// ---------------- HMMA GEMM (NT + bias)*scale, cp.async 2-stage ----------
#define LDAB 40
#define STG_BYTES 40960
#define GEMM_SMEM (2 * STG_BYTES)

template <int OUT_MODE>
__global__ __launch_bounds__(256) void gemm_hmma(
    const __nv_bfloat16* __restrict__ Ahi, const __nv_bfloat16* __restrict__ Alo,
    const __nv_bfloat16* __restrict__ Bhi, const __nv_bfloat16* __restrict__ Blo,
    const float* __restrict__ bias, float scale,
    float* __restrict__ Cf, __nv_bfloat16* __restrict__ Chi,
    __nv_bfloat16* __restrict__ Clo, uint32_t* __restrict__ Cp,
    int M, int N, int K)
{
    extern __shared__ char smraw[];
    const uint32_t sb = smem_u32(smraw);

    const int tid = threadIdx.x, lane = tid & 31, wid = tid >> 5;
    const int wm = wid >> 2, wn = wid & 3;
    const int bm = blockIdx.y * 128, bn = blockIdx.x * 128;
    const int m0 = wm * 64, n0 = wn * 32;

    const int a_r = lane & 15, a_c = (lane >> 4) * 8;
    const int b_n = ((lane >> 4) & 1) * 8 + (lane & 7);
    const int b_k = ((lane >> 3) & 1) * 8;

    const int l_row0 = (tid * 2) >> 2, l_c0 = ((tid * 2) & 3) * 8;
    const int l_row1 = (tid * 2 + 1) >> 2, l_c1 = ((tid * 2 + 1) & 3) * 8;

    float acc[4][4][4];
#pragma unroll
    for (int mt = 0; mt < 4; mt++)
#pragma unroll
        for (int nt = 0; nt < 4; nt++)
#pragma unroll
            for (int j = 0; j < 4; j++) acc[mt][nt][j] = 0.f;

    const int nIter = K / 32;

    auto load_stage = [&](int kc, int s) {
        const uint32_t st = sb + s * STG_BYTES;
        const int k0 = kc * 32;
        CP_ASYNC16(st + (l_row0 * LDAB + l_c0) * 2,
                   Ahi + (size_t)(bm + l_row0) * K + k0 + l_c0);
        CP_ASYNC16(st + (l_row1 * LDAB + l_c1) * 2,
                   Ahi + (size_t)(bm + l_row1) * K + k0 + l_c1);
        CP_ASYNC16(st + 10240 + (l_row0 * LDAB + l_c0) * 2,
                   Alo + (size_t)(bm + l_row0) * K + k0 + l_c0);
        CP_ASYNC16(st + 10240 + (l_row1 * LDAB + l_c1) * 2,
                   Alo + (size_t)(bm + l_row1) * K + k0 + l_c1);
        CP_ASYNC16(st + 20480 + (l_row0 * LDAB + l_c0) * 2,
                   Bhi + (size_t)(bn + l_row0) * K + k0 + l_c0);
        CP_ASYNC16(st + 20480 + (l_row1 * LDAB + l_c1) * 2,
                   Bhi + (size_t)(bn + l_row1) * K + k0 + l_c1);
        CP_ASYNC16(st + 30720 + (l_row0 * LDAB + l_c0) * 2,
                   Blo + (size_t)(bn + l_row0) * K + k0 + l_c0);
        CP_ASYNC16(st + 30720 + (l_row1 * LDAB + l_c1) * 2,
                   Blo + (size_t)(bn + l_row1) * K + k0 + l_c1);
        CP_COMMIT;
    };

    load_stage(0, 0);
    for (int kc = 0; kc < nIter; kc++) {
        const int s = kc & 1;
        CP_WAIT0;
        __syncthreads();
        if (kc + 1 < nIter) load_stage(kc + 1, s ^ 1);

        const uint32_t st = sb + s * STG_BYTES;
#pragma unroll
        for (int ks = 0; ks < 2; ks++) {
            const int k0 = ks * 16;
            uint32_t ah[4][4], al[4][4], bh[2][4], bl[2][4];
#pragma unroll
            for (int mt = 0; mt < 4; mt++) {
                int off = ((m0 + mt * 16 + a_r) * LDAB + k0 + a_c) * 2;
                ldsm4(ah[mt], st + off);
                ldsm4(al[mt], st + 10240 + off);
            }
#pragma unroll
            for (int bp = 0; bp < 2; bp++) {
                int off = ((n0 + bp * 16 + b_n) * LDAB + k0 + b_k) * 2;
                ldsm4(bh[bp], st + 20480 + off);
                ldsm4(bl[bp], st + 30720 + off);
            }
#pragma unroll
            for (int mt = 0; mt < 4; mt++)
#pragma unroll
                for (int nt = 0; nt < 4; nt++) {
                    const uint32_t* bhp = &bh[nt >> 1][(nt & 1) * 2];
                    const uint32_t* blp = &bl[nt >> 1][(nt & 1) * 2];
                    mma_bf16(acc[mt][nt], ah[mt], bhp);
                    mma_bf16(acc[mt][nt], ah[mt], blp);
                    mma_bf16(acc[mt][nt], al[mt], bhp);
                }
        }
    }

#pragma unroll
    for (int mt = 0; mt < 4; mt++) {
        const int r0 = bm + m0 + mt * 16 + (lane >> 2);
#pragma unroll
        for (int nt = 0; nt < 4; nt++) {
            const int col = bn + n0 + nt * 8 + (lane & 3) * 2;
            float2 bv = *(const float2*)(bias + col);
            float c00 = (acc[mt][nt][0] + bv.x) * scale;
            float c01 = (acc[mt][nt][1] + bv.y) * scale;
            float c10 = (acc[mt][nt][2] + bv.x) * scale;
            float c11 = (acc[mt][nt][3] + bv.y) * scale;
            if (OUT_MODE == 0) {
                *(float2*)(Cf + (size_t)r0 * N + col) = make_float2(c00, c01);
                *(float2*)(Cf + (size_t)(r0 + 8) * N + col) = make_float2(c10, c11);
            } else if (OUT_MODE == 1) {
                split_store2(Chi + (size_t)r0 * N + col,
                             Clo + (size_t)r0 * N + col, c00, c01);
                split_store2(Chi + (size_t)(r0 + 8) * N + col,
                             Clo + (size_t)(r0 + 8) * N + col, c10, c11);
            } else {
                *(uint2*)(Cp + (size_t)r0 * N + col) =
                    make_uint2(pack_hl(c00), pack_hl(c01));
                *(uint2*)(Cp + (size_t)(r0 + 8) * N + col) =
                    make_uint2(pack_hl(c10), pack_hl(c11));
            }
        }
    }
}

// ------- transpose packed u32 -> separate hi/lo bf16 planes -------
__global__ __launch_bounds__(256) void transpose_hl(
    const uint32_t* __restrict__ in, __nv_bfloat16* __restrict__ oh,
    __nv_bfloat16* __restrict__ ol)
{
    __shared__ uint32_t tile[32][33];
    const int cb = blockIdx.x * 32, sbk = blockIdx.y * 32;
    const int tx = threadIdx.x, ty = threadIdx.y;
#pragma unroll
    for (int j = 0; j < 4; j++)
        tile[ty + j * 8][tx] = in[(size_t)(sbk + ty + j * 8) * HDIM + cb + tx];
    __syncthreads();
#pragma unroll
    for (int j = 0; j < 4; j++) {
        uint32_t w = tile[tx][ty + j * 8];
        size_t o = (size_t)(cb + ty + j * 8) * S_LEN + sbk + tx;
        uint16_t hb = (uint16_t)(w & 0xffffu), lb = (uint16_t)(w >> 16);
        oh[o] = *(__nv_bfloat16*)&hb;
        ol[o] = *(__nv_bfloat16*)&lb;
    }
}

// ---------------- HMMA flash attention, FA2 + cp.async, Q in registers ----
// CTA = (128 queries, 1 head). warp w owns rows [w*16, w*16+16). 64-key tiles.
// Q scores arrive in log2 units (SCALE2 folded into Q projection) -> ex2 softmax.
#define LDQ 136
#define LDV 72
#define AQL 17408
#define ASTG0 34816
#define ASTG  35840
#define AKL 8704
#define AVH 17408
#define AVL 26624
#define ATT_SMEM 212992

__global__ __launch_bounds__(256) void attn_hmma(
    const __nv_bfloat16* __restrict__ Qhi, const __nv_bfloat16* __restrict__ Qlo,
    const __nv_bfloat16* __restrict__ Khi, const __nv_bfloat16* __restrict__ Klo,
    const __nv_bfloat16* __restrict__ VThi, const __nv_bfloat16* __restrict__ VTlo,
    __nv_bfloat16* __restrict__ Ohi, __nv_bfloat16* __restrict__ Olo)
{
    extern __shared__ __nv_bfloat16 sm[];
    const uint32_t sb = smem_u32(sm);

    const int tid = threadIdx.x, lane = tid & 31, wid = tid >> 5;
    const int qb = blockIdx.x * 128, h = blockIdx.y;

    const int a_r = lane & 15, a_c = (lane >> 4) * 8;
    const int b_n = ((lane >> 4) & 1) * 8 + (lane & 7);
    const int b_k = ((lane >> 3) & 1) * 8;
    const int qrow = wid * 16;

    const int k_r = tid >> 2, k_c = (tid & 3) * 32;
    const int v_r = tid >> 1, v_c = (tid & 1) * 32;

    auto load_kv = [&](int t, int s) {
        const uint32_t stg = sb + (ASTG0 + s * ASTG) * 2;
        const __nv_bfloat16* kh = Khi + (size_t)(t * 64 + k_r) * HDIM + h * HD + k_c;
        const __nv_bfloat16* kl = Klo + (size_t)(t * 64 + k_r) * HDIM + h * HD + k_c;
#pragma unroll
        for (int j = 0; j < 4; j++) {
            CP_ASYNC16(stg + (k_r * LDQ + k_c + j * 8) * 2, kh + j * 8);
            CP_ASYNC16(stg + (AKL + k_r * LDQ + k_c + j * 8) * 2, kl + j * 8);
        }
        const __nv_bfloat16* vh = VThi + (size_t)(h * HD + v_r) * S_LEN + t * 64 + v_c;
        const __nv_bfloat16* vl = VTlo + (size_t)(h * HD + v_r) * S_LEN + t * 64 + v_c;
#pragma unroll
        for (int j = 0; j < 4; j++) {
            CP_ASYNC16(stg + (AVH + v_r * LDV + v_c + j * 8) * 2, vh + j * 8);
            CP_ASYNC16(stg + (AVL + v_r * LDV + v_c + j * 8) * 2, vl + j * 8);
        }
        CP_COMMIT;
    };

    // Q tile via cp.async into smem (own group), then hoist into registers
    {
        const int r = tid >> 1, cs = (tid & 1) * 64;
        const __nv_bfloat16* qh = Qhi + (size_t)(qb + r) * HDIM + h * HD + cs;
        const __nv_bfloat16* ql = Qlo + (size_t)(qb + r) * HDIM + h * HD + cs;
#pragma unroll
        for (int j = 0; j < 8; j++) {
            CP_ASYNC16(sb + (r * LDQ + cs + j * 8) * 2, qh + j * 8);
            CP_ASYNC16(sb + (AQL + r * LDQ + cs + j * 8) * 2, ql + j * 8);
        }
        CP_COMMIT;          // group: Q
    }
    load_kv(0, 0);          // group: KV(0)

    CP_WAIT1;               // Q arrived (KV(0) may still fly)
    __syncthreads();

    // Q fragments live in registers for the whole kernel
    uint32_t qfh[8][4], qfl[8][4];
#pragma unroll
    for (int ks = 0; ks < 8; ks++) {
        int off = ((qrow + a_r) * LDQ + ks * 16 + a_c) * 2;
        ldsm4(qfh[ks], sb + off);
        ldsm4(qfl[ks], sb + AQL * 2 + off);
    }

    float m0 = -INFINITY, m1 = -INFINITY, l0 = 0.f, l1 = 0.f;
    float oacc[16][4];
#pragma unroll
    for (int nt = 0; nt < 16; nt++)
#pragma unroll
        for (int j = 0; j < 4; j++) oacc[nt][j] = 0.f;

    const int NT = S_LEN / 64;
    for (int t = 0; t < NT; t++) {
        const int s = t & 1;
        CP_WAIT0;            // KV(t) arrived (only pending group)
        __syncthreads();     // everyone done reading stage s^1 (tile t-1)
        if (t + 1 < NT) load_kv(t + 1, s ^ 1);   // flies under compute(t)

        const uint32_t stg = sb + (ASTG0 + s * ASTG) * 2;

        // ---- Phase 1: S = Q K^T  (warp: 16q x 64k) ----
        float sacc[8][4];
#pragma unroll
        for (int nt = 0; nt < 8; nt++)
#pragma unroll
            for (int j = 0; j < 4; j++) sacc[nt][j] = 0.f;

#pragma unroll
        for (int ks = 0; ks < 8; ks++) {
            const int k0 = ks * 16;
            uint32_t bh[4][4], bl[4][4];
#pragma unroll
            for (int g = 0; g < 4; g++) {
                int off = ((g * 16 + b_n) * LDQ + k0 + b_k) * 2;
                ldsm4(bh[g], stg + off);
                ldsm4(bl[g], stg + AKL * 2 + off);
            }
#pragma unroll
            for (int nt = 0; nt < 8; nt++) {
                const uint32_t* bhp = &bh[nt >> 1][(nt & 1) * 2];
                const uint32_t* blp = &bl[nt >> 1][(nt & 1) * 2];
                mma_bf16(sacc[nt], qfh[ks], bhp);
                mma_bf16(sacc[nt], qfh[ks], blp);
                mma_bf16(sacc[nt], qfl[ks], bhp);
            }
        }

        // ---- warp-local online softmax (log2 domain) ----
        float tm0 = -INFINITY, tm1 = -INFINITY;
#pragma unroll
        for (int nt = 0; nt < 8; nt++) {
            tm0 = fmaxf(tm0, fmaxf(sacc[nt][0], sacc[nt][1]));
            tm1 = fmaxf(tm1, fmaxf(sacc[nt][2], sacc[nt][3]));
        }
        tm0 = fmaxf(tm0, __shfl_xor_sync(0xffffffffu, tm0, 1));
        tm0 = fmaxf(tm0, __shfl_xor_sync(0xffffffffu, tm0, 2));
        tm1 = fmaxf(tm1, __shfl_xor_sync(0xffffffffu, tm1, 1));
        tm1 = fmaxf(tm1, __shfl_xor_sync(0xffffffffu, tm1, 2));
        const float mn0 = fmaxf(m0, tm0), mn1 = fmaxf(m1, tm1);
        const float c0 = ex2f(m0 - mn0), c1 = ex2f(m1 - mn1);
        m0 = mn0; m1 = mn1;

        float ls0 = 0.f, ls1 = 0.f;
#pragma unroll
        for (int nt = 0; nt < 8; nt++) {
            sacc[nt][0] = ex2f(sacc[nt][0] - mn0);
            sacc[nt][1] = ex2f(sacc[nt][1] - mn0);
            sacc[nt][2] = ex2f(sacc[nt][2] - mn1);
            sacc[nt][3] = ex2f(sacc[nt][3] - mn1);
            ls0 += sacc[nt][0] + sacc[nt][1];
            ls1 += sacc[nt][2] + sacc[nt][3];
        }
        ls0 += __shfl_xor_sync(0xffffffffu, ls0, 1);
        ls0 += __shfl_xor_sync(0xffffffffu, ls0, 2);
        ls1 += __shfl_xor_sync(0xffffffffu, ls1, 1);
        ls1 += __shfl_xor_sync(0xffffffffu, ls1, 2);
        l0 = l0 * c0 + ls0;
        l1 = l1 * c1 + ls1;

        if (c0 != 1.f || c1 != 1.f) {
#pragma unroll
            for (int nt = 0; nt < 16; nt++) {
                oacc[nt][0] *= c0; oacc[nt][1] *= c0;
                oacc[nt][2] *= c1; oacc[nt][3] *= c1;
            }
        }

        // ---- Phase 2: O += P V  (P as register A-fragments) ----
#pragma unroll
        for (int ks = 0; ks < 4; ks++) {
            uint32_t ph4[4], pl4[4];
            split_pack2(sacc[2 * ks][0], sacc[2 * ks][1], ph4[0], pl4[0]);
            split_pack2(sacc[2 * ks][2], sacc[2 * ks][3], ph4[1], pl4[1]);
            split_pack2(sacc[2 * ks + 1][0], sacc[2 * ks + 1][1], ph4[2], pl4[2]);
            split_pack2(sacc[2 * ks + 1][2], sacc[2 * ks + 1][3], ph4[3], pl4[3]);
            const int k0 = ks * 16;
#pragma unroll
            for (int g = 0; g < 8; g++) {
                uint32_t vh[4], vl[4];
                int off = ((g * 16 + b_n) * LDV + k0 + b_k) * 2;
                ldsm4(vh, stg + AVH * 2 + off);
                ldsm4(vl, stg + AVL * 2 + off);
#pragma unroll
                for (int sub = 0; sub < 2; sub++) {
                    const int nt = g * 2 + sub;
                    mma_bf16(oacc[nt], ph4, &vh[sub * 2]);
                    mma_bf16(oacc[nt], ph4, &vl[sub * 2]);
                    mma_bf16(oacc[nt], pl4, &vh[sub * 2]);
                }
            }
        }
    }

    // ---- epilogue ----
    const float inv0 = 1.f / l0, inv1 = 1.f / l1;
    const int r0 = qrow + (lane >> 2);
#pragma unroll
    for (int nt = 0; nt < 16; nt++) {
        const int col = nt * 8 + (lane & 3) * 2;
        size_t i0 = (size_t)(qb + r0) * HDIM + h * HD + col;
        size_t i1 = (size_t)(qb + r0 + 8) * HDIM + h * HD + col;
        split_store2(Ohi + i0, Olo + i0, oacc[nt][0] * inv0, oacc[nt][1] * inv0);
        split_store2(Ohi + i1, Olo + i1, oacc[nt][2] * inv1, oacc[nt][3] * inv1);
    }
}

// ---------------- launch ----------------
extern "C" void kernel_launch(void* const* d_in, const int* in_sizes, int n_in,
                              void* d_out, int out_size)
{
    const float* hidden = (const float*)d_in[0];
    const float* Wq = (const float*)d_in[1];
    const float* bq = (const float*)d_in[2];
    const float* Wk = (const float*)d_in[3];
    const float* bk = (const float*)d_in[4];
    const float* Wv = (const float*)d_in[5];
    const float* bv = (const float*)d_in[6];
    const float* Wo = (const float*)d_in[7];
    const float* bo = (const float*)d_in[8];
    float* out = (float*)d_out;

    __nv_bfloat16 *Hhi, *Hlo, *Wqhi, *Wqlo, *Wkhi, *Wklo, *Wvhi, *Wvlo,
                  *Wohi, *Wolo, *Qhi, *Qlo, *Khi, *Klo, *Ohi, *Olo, *VThi, *VTlo;
    uint32_t *Vp;
    cudaGetSymbolAddress((void**)&Hhi, g_Hhi);  cudaGetSymbolAddress((void**)&Hlo, g_Hlo);
    cudaGetSymbolAddress((void**)&Wqhi, g_Wqhi); cudaGetSymbolAddress((void**)&Wqlo, g_Wqlo);
    cudaGetSymbolAddress((void**)&Wkhi, g_Wkhi); cudaGetSymbolAddress((void**)&Wklo, g_Wklo);
    cudaGetSymbolAddress((void**)&Wvhi, g_Wvhi); cudaGetSymbolAddress((void**)&Wvlo, g_Wvlo);
    cudaGetSymbolAddress((void**)&Wohi, g_Wohi); cudaGetSymbolAddress((void**)&Wolo, g_Wolo);
    cudaGetSymbolAddress((void**)&Qhi, g_Qhi);   cudaGetSymbolAddress((void**)&Qlo, g_Qlo);
    cudaGetSymbolAddress((void**)&Khi, g_Khi);   cudaGetSymbolAddress((void**)&Klo, g_Klo);
    cudaGetSymbolAddress((void**)&Ohi, g_Ohi);   cudaGetSymbolAddress((void**)&Olo, g_Olo);
    cudaGetSymbolAddress((void**)&Vp, g_Vp);
    cudaGetSymbolAddress((void**)&VThi, g_VThi); cudaGetSymbolAddress((void**)&VTlo, g_VTlo);

    cudaFuncSetAttribute(gemm_hmma<0>, cudaFuncAttributeMaxDynamicSharedMemorySize, GEMM_SMEM);
    cudaFuncSetAttribute(gemm_hmma<1>, cudaFuncAttributeMaxDynamicSharedMemorySize, GEMM_SMEM);
    cudaFuncSetAttribute(gemm_hmma<2>, cudaFuncAttributeMaxDynamicSharedMemorySize, GEMM_SMEM);
    cudaFuncSetAttribute(attn_hmma, cudaFuncAttributeMaxDynamicSharedMemorySize, ATT_SMEM);

    const int nH4 = S_LEN * HDIM / 4, nW4 = HDIM * HDIM / 4;
    split_pre<<<nH4 / 256, 256>>>(hidden, Hhi, Hlo, nH4);
    split_pre<<<nW4 / 256, 256>>>(Wq, Wqhi, Wqlo, nW4);
    split_pre<<<nW4 / 256, 256>>>(Wk, Wkhi, Wklo, nW4);
    split_pre<<<nW4 / 256, 256>>>(Wv, Wvhi, Wvlo, nW4);
    split_pre<<<nW4 / 256, 256>>>(Wo, Wohi, Wolo, nW4);

    dim3 ggrid(HDIM / 128, S_LEN / 128);   // (16, 32)
    // Q projection pre-scaled by SCALE*log2(e) -> softmax in log2 domain
    gemm_hmma<1><<<ggrid, 256, GEMM_SMEM>>>(Hhi, Hlo, Wqhi, Wqlo, bq, SCALE2,
                                            nullptr, Qhi, Qlo, nullptr,
                                            S_LEN, HDIM, HDIM);
    gemm_hmma<1><<<ggrid, 256, GEMM_SMEM>>>(Hhi, Hlo, Wkhi, Wklo, bk, 1.f,
                                            nullptr, Khi, Klo, nullptr,
                                            S_LEN, HDIM, HDIM);
    gemm_hmma<2><<<ggrid, 256, GEMM_SMEM>>>(Hhi, Hlo, Wvhi, Wvlo, bv, 1.f,
                                            nullptr, nullptr, nullptr, Vp,
                                            S_LEN, HDIM, HDIM);

    dim3 tgrid(HDIM / 32, S_LEN / 32);
    transpose_hl<<<tgrid, dim3(32, 8)>>>(Vp, VThi, VTlo);

    dim3 agrid(S_LEN / 128, NHEADS);       // (32, 16)
    attn_hmma<<<agrid, 256, ATT_SMEM>>>(Qhi, Qlo, Khi, Klo, VThi, VTlo, Ohi, Olo);

    gemm_hmma<0><<<ggrid, 256, GEMM_SMEM>>>(Ohi, Olo, Wohi, Wolo, bo, 1.f,
                                            out, nullptr, nullptr, nullptr,
                                            S_LEN, HDIM, HDIM);
}

// round 10
// speedup vs baseline: 3.8275x; 1.2045x over previous
#include <cuda_runtime.h>
#include <cuda_bf16.h>
#include <cuda_fp16.h>
#include <cstdint>
#include <math.h>

#define S_LEN 4096
#define HDIM  2048
#define NHEADS 16
#define HD    128
#define SCALE 0.08838834764831845f
// SCALE * log2(e): scores come out of QK^T already in log2 units
#define SCALE2 0.1275332511737922f

// ---------------- scratch globals ----------------
__device__ __nv_bfloat16 g_Hhi[S_LEN * HDIM], g_Hlo[S_LEN * HDIM];
__device__ __nv_bfloat16 g_Wqhi[HDIM * HDIM], g_Wqlo[HDIM * HDIM];
__device__ __nv_bfloat16 g_Wkhi[HDIM * HDIM], g_Wklo[HDIM * HDIM];
__device__ __nv_bfloat16 g_Wvhi[HDIM * HDIM], g_Wvlo[HDIM * HDIM];
__device__ __nv_bfloat16 g_Wohi[HDIM * HDIM], g_Wolo[HDIM * HDIM];
__device__ __half g_Qh[S_LEN * HDIM], g_Ql[S_LEN * HDIM];   // Q fp16 hi/lo
__device__ __half g_Kh[S_LEN * HDIM];                       // K fp16 single
__device__ __half g_Vh[S_LEN * HDIM];                       // V fp16 single
__device__ __half g_VTh[HDIM * S_LEN];                      // V^T fp16
__device__ __nv_bfloat16 g_Ohi[S_LEN * HDIM], g_Olo[S_LEN * HDIM];

// ---------------- helpers ----------------
__device__ __forceinline__ uint32_t smem_u32(const void* p) {
    uint32_t a;
    asm("{ .reg .u64 t; cvta.to.shared.u64 t, %1; cvt.u32.u64 %0, t; }"
        : "=r"(a) : "l"(p));
    return a;
}
__device__ __forceinline__ void ldsm4(uint32_t* r, uint32_t a) {
    asm volatile("ldmatrix.sync.aligned.m8n8.x4.shared.b16 {%0,%1,%2,%3}, [%4];"
        : "=r"(r[0]), "=r"(r[1]), "=r"(r[2]), "=r"(r[3]) : "r"(a));
}
__device__ __forceinline__ void mma_bf16(float* c, const uint32_t* a,
                                         const uint32_t* b) {
    asm volatile("mma.sync.aligned.m16n8k16.row.col.f32.bf16.bf16.f32 "
        "{%0,%1,%2,%3}, {%4,%5,%6,%7}, {%8,%9}, {%0,%1,%2,%3};"
        : "+f"(c[0]), "+f"(c[1]), "+f"(c[2]), "+f"(c[3])
        : "r"(a[0]), "r"(a[1]), "r"(a[2]), "r"(a[3]), "r"(b[0]), "r"(b[1]));
}
__device__ __forceinline__ void mma_f16(float* c, const uint32_t* a,
                                        const uint32_t* b) {
    asm volatile("mma.sync.aligned.m16n8k16.row.col.f32.f16.f16.f32 "
        "{%0,%1,%2,%3}, {%4,%5,%6,%7}, {%8,%9}, {%0,%1,%2,%3};"
        : "+f"(c[0]), "+f"(c[1]), "+f"(c[2]), "+f"(c[3])
        : "r"(a[0]), "r"(a[1]), "r"(a[2]), "r"(a[3]), "r"(b[0]), "r"(b[1]));
}
__device__ __forceinline__ float ex2f(float x) {
    float r;
    asm("ex2.approx.f32 %0, %1;" : "=f"(r) : "f"(x));
    return r;
}
__device__ __forceinline__ void split_store2(__nv_bfloat16* hi,
                                             __nv_bfloat16* lo,
                                             float x, float y) {
    __nv_bfloat16 hx = __float2bfloat16(x), hy = __float2bfloat16(y);
    __nv_bfloat162 h2; h2.x = hx; h2.y = hy;
    __nv_bfloat162 l2;
    l2.x = __float2bfloat16(x - __bfloat162float(hx));
    l2.y = __float2bfloat16(y - __bfloat162float(hy));
    *reinterpret_cast<__nv_bfloat162*>(hi) = h2;
    *reinterpret_cast<__nv_bfloat162*>(lo) = l2;
}
__device__ __forceinline__ void split_store2h(__half* hi, __half* lo,
                                              float x, float y) {
    __half hx = __float2half_rn(x), hy = __float2half_rn(y);
    __half2 h2 = __halves2half2(hx, hy);
    __half2 l2 = __halves2half2(__float2half_rn(x - __half2float(hx)),
                                __float2half_rn(y - __half2float(hy)));
    *reinterpret_cast<__half2*>(hi) = h2;
    *reinterpret_cast<__half2*>(lo) = l2;
}
// split two floats into packed fp16x2 hi-word and lo-word
__device__ __forceinline__ void split_pack2h(float x, float y,
                                             uint32_t& hi, uint32_t& lo) {
    __half hx = __float2half_rn(x), hy = __float2half_rn(y);
    __half lx = __float2half_rn(x - __half2float(hx));
    __half ly = __float2half_rn(y - __half2float(hy));
    uint16_t a = *(uint16_t*)&hx, b = *(uint16_t*)&hy;
    uint16_t c = *(uint16_t*)&lx, d = *(uint16_t*)&ly;
    hi = (uint32_t)a | ((uint32_t)b << 16);
    lo = (uint32_t)c | ((uint32_t)d << 16);
}
#define CP_ASYNC16(dst, src) \
    asm volatile("cp.async.cg.shared.global [%0], [%1], 16;\n" \
                 :: "r"(dst), "l"(src))
#define CP_COMMIT asm volatile("cp.async.commit_group;\n" ::: "memory")
#define CP_WAIT0  asm volatile("cp.async.wait_group 0;\n" ::: "memory")
#define CP_WAIT1  asm volatile("cp.async.wait_group 1;\n" ::: "memory")

// ---------------- prepass: fp32 -> bf16 hi/lo ----------------
__global__ __launch_bounds__(256) void split_pre(
    const float* __restrict__ in, __nv_bfloat16* __restrict__ hi,
    __nv_bfloat16* __restrict__ lo, int n4)
{
    int i = blockIdx.x * blockDim.x + threadIdx.x;
    if (i < n4) {
        float4 v = ((const float4*)in)[i];
        split_store2(hi + i * 4, lo + i * 4, v.x, v.y);
        split_store2(hi + i * 4 + 2, lo + i * 4 + 2, v.z, v.w);
    }
}

// ---------------- HMMA GEMM (NT + bias)*scale, cp.async 2-stage ----------
// inputs bf16 hi/lo, 3-MMA exact path. BM=BN=128, BK=32, 256 thr, 8 warps.
// OUT_MODE: 0 = fp32, 1 = fp16 hi/lo planes, 2 = fp16 single plane
#define LDAB 40
#define STG_BYTES 40960
#define GEMM_SMEM (2 * STG_BYTES)

template <int OUT_MODE>
__global__ __launch_bounds__(256) void gemm_hmma(
    const __nv_bfloat16* __restrict__ Ahi, const __nv_bfloat16* __restrict__ Alo,
    const __nv_bfloat16* __restrict__ Bhi, const __nv_bfloat16* __restrict__ Blo,
    const float* __restrict__ bias, float scale,
    float* __restrict__ Cf, __half* __restrict__ Chh,
    __half* __restrict__ Chl, __half* __restrict__ Ch,
    int M, int N, int K)
{
    extern __shared__ char smraw[];
    const uint32_t sb = smem_u32(smraw);

    const int tid = threadIdx.x, lane = tid & 31, wid = tid >> 5;
    const int wm = wid >> 2, wn = wid & 3;
    const int bm = blockIdx.y * 128, bn = blockIdx.x * 128;
    const int m0 = wm * 64, n0 = wn * 32;

    const int a_r = lane & 15, a_c = (lane >> 4) * 8;
    const int b_n = ((lane >> 4) & 1) * 8 + (lane & 7);
    const int b_k = ((lane >> 3) & 1) * 8;

    const int l_row0 = (tid * 2) >> 2, l_c0 = ((tid * 2) & 3) * 8;
    const int l_row1 = (tid * 2 + 1) >> 2, l_c1 = ((tid * 2 + 1) & 3) * 8;

    float acc[4][4][4];
#pragma unroll
    for (int mt = 0; mt < 4; mt++)
#pragma unroll
        for (int nt = 0; nt < 4; nt++)
#pragma unroll
            for (int j = 0; j < 4; j++) acc[mt][nt][j] = 0.f;

    const int nIter = K / 32;

    auto load_stage = [&](int kc, int s) {
        const uint32_t st = sb + s * STG_BYTES;
        const int k0 = kc * 32;
        CP_ASYNC16(st + (l_row0 * LDAB + l_c0) * 2,
                   Ahi + (size_t)(bm + l_row0) * K + k0 + l_c0);
        CP_ASYNC16(st + (l_row1 * LDAB + l_c1) * 2,
                   Ahi + (size_t)(bm + l_row1) * K + k0 + l_c1);
        CP_ASYNC16(st + 10240 + (l_row0 * LDAB + l_c0) * 2,
                   Alo + (size_t)(bm + l_row0) * K + k0 + l_c0);
        CP_ASYNC16(st + 10240 + (l_row1 * LDAB + l_c1) * 2,
                   Alo + (size_t)(bm + l_row1) * K + k0 + l_c1);
        CP_ASYNC16(st + 20480 + (l_row0 * LDAB + l_c0) * 2,
                   Bhi + (size_t)(bn + l_row0) * K + k0 + l_c0);
        CP_ASYNC16(st + 20480 + (l_row1 * LDAB + l_c1) * 2,
                   Bhi + (size_t)(bn + l_row1) * K + k0 + l_c1);
        CP_ASYNC16(st + 30720 + (l_row0 * LDAB + l_c0) * 2,
                   Blo + (size_t)(bn + l_row0) * K + k0 + l_c0);
        CP_ASYNC16(st + 30720 + (l_row1 * LDAB + l_c1) * 2,
                   Blo + (size_t)(bn + l_row1) * K + k0 + l_c1);
        CP_COMMIT;
    };

    load_stage(0, 0);
    for (int kc = 0; kc < nIter; kc++) {
        const int s = kc & 1;
        CP_WAIT0;
        __syncthreads();
        if (kc + 1 < nIter) load_stage(kc + 1, s ^ 1);

        const uint32_t st = sb + s * STG_BYTES;
#pragma unroll
        for (int ks = 0; ks < 2; ks++) {
            const int k0 = ks * 16;
            uint32_t ah[4][4], al[4][4], bh[2][4], bl[2][4];
#pragma unroll
            for (int mt = 0; mt < 4; mt++) {
                int off = ((m0 + mt * 16 + a_r) * LDAB + k0 + a_c) * 2;
                ldsm4(ah[mt], st + off);
                ldsm4(al[mt], st + 10240 + off);
            }
#pragma unroll
            for (int bp = 0; bp < 2; bp++) {
                int off = ((n0 + bp * 16 + b_n) * LDAB + k0 + b_k) * 2;
                ldsm4(bh[bp], st + 20480 + off);
                ldsm4(bl[bp], st + 30720 + off);
            }
#pragma unroll
            for (int mt = 0; mt < 4; mt++)
#pragma unroll
                for (int nt = 0; nt < 4; nt++) {
                    const uint32_t* bhp = &bh[nt >> 1][(nt & 1) * 2];
                    const uint32_t* blp = &bl[nt >> 1][(nt & 1) * 2];
                    mma_bf16(acc[mt][nt], ah[mt], bhp);
                    mma_bf16(acc[mt][nt], ah[mt], blp);
                    mma_bf16(acc[mt][nt], al[mt], bhp);
                }
        }
    }

#pragma unroll
    for (int mt = 0; mt < 4; mt++) {
        const int r0 = bm + m0 + mt * 16 + (lane >> 2);
#pragma unroll
        for (int nt = 0; nt < 4; nt++) {
            const int col = bn + n0 + nt * 8 + (lane & 3) * 2;
            float2 bv = *(const float2*)(bias + col);
            float c00 = (acc[mt][nt][0] + bv.x) * scale;
            float c01 = (acc[mt][nt][1] + bv.y) * scale;
            float c10 = (acc[mt][nt][2] + bv.x) * scale;
            float c11 = (acc[mt][nt][3] + bv.y) * scale;
            if (OUT_MODE == 0) {
                *(float2*)(Cf + (size_t)r0 * N + col) = make_float2(c00, c01);
                *(float2*)(Cf + (size_t)(r0 + 8) * N + col) = make_float2(c10, c11);
            } else if (OUT_MODE == 1) {
                split_store2h(Chh + (size_t)r0 * N + col,
                              Chl + (size_t)r0 * N + col, c00, c01);
                split_store2h(Chh + (size_t)(r0 + 8) * N + col,
                              Chl + (size_t)(r0 + 8) * N + col, c10, c11);
            } else {
                *(__half2*)(Ch + (size_t)r0 * N + col) =
                    __halves2half2(__float2half_rn(c00), __float2half_rn(c01));
                *(__half2*)(Ch + (size_t)(r0 + 8) * N + col) =
                    __halves2half2(__float2half_rn(c10), __float2half_rn(c11));
            }
        }
    }
}

// ------- transpose fp16: out[c][s] = in[s][c] -------
__global__ __launch_bounds__(256) void transpose_h(
    const __half* __restrict__ in, __half* __restrict__ out)
{
    __shared__ __half tile[32][34];
    const int cb = blockIdx.x * 32, sbk = blockIdx.y * 32;
    const int tx = threadIdx.x, ty = threadIdx.y;
#pragma unroll
    for (int j = 0; j < 4; j++)
        tile[ty + j * 8][tx] = in[(size_t)(sbk + ty + j * 8) * HDIM + cb + tx];
    __syncthreads();
#pragma unroll
    for (int j = 0; j < 4; j++)
        out[(size_t)(cb + ty + j * 8) * S_LEN + sbk + tx] = tile[tx][ty + j * 8];
}

// ---------------- fp16 flash attention, FA2 + cp.async, Q in registers ----
// CTA = (128 queries, 1 head). warp w owns rows [w*16, w*16+16). 64-key tiles.
// S = (Qh+Ql)·K_fp16 (2 MMAs), O += (Ph+Pl)·V_fp16 (2 MMAs).
// Q scores in log2 units (SCALE2 folded into Q projection) -> ex2 softmax.
#define LDQ 136
#define LDV 72
#define AQL 17408          /* Ql plane offset (elems)            */
#define ASTG0 34816        /* first KV stage base (elems)        */
#define ASTG  17920        /* stage size: K 8704 + V 9216        */
#define AVH_OFF 8704       /* V offset within stage (elems)      */
#define ATT_SMEM 141312

__global__ __launch_bounds__(256) void attn_hmma(
    const __half* __restrict__ Qhi, const __half* __restrict__ Qlo,
    const __half* __restrict__ Kh, const __half* __restrict__ VTh,
    __nv_bfloat16* __restrict__ Ohi, __nv_bfloat16* __restrict__ Olo)
{
    extern __shared__ __half smh[];
    const uint32_t sb = smem_u32(smh);

    const int tid = threadIdx.x, lane = tid & 31, wid = tid >> 5;
    const int qb = blockIdx.x * 128, h = blockIdx.y;

    const int a_r = lane & 15, a_c = (lane >> 4) * 8;
    const int b_n = ((lane >> 4) & 1) * 8 + (lane & 7);
    const int b_k = ((lane >> 3) & 1) * 8;
    const int qrow = wid * 16;

    const int k_r = tid >> 2, k_c = (tid & 3) * 32;
    const int v_r = tid >> 1, v_c = (tid & 1) * 32;

    auto load_kv = [&](int t, int s) {
        const uint32_t stg = sb + (ASTG0 + s * ASTG) * 2;
        const __half* kp = Kh + (size_t)(t * 64 + k_r) * HDIM + h * HD + k_c;
#pragma unroll
        for (int j = 0; j < 4; j++)
            CP_ASYNC16(stg + (k_r * LDQ + k_c + j * 8) * 2, kp + j * 8);
        const __half* vp = VTh + (size_t)(h * HD + v_r) * S_LEN + t * 64 + v_c;
#pragma unroll
        for (int j = 0; j < 4; j++)
            CP_ASYNC16(stg + (AVH_OFF + v_r * LDV + v_c + j * 8) * 2, vp + j * 8);
        CP_COMMIT;
    };

    // Q tile via cp.async into smem (own group), then hoist into registers
    {
        const int r = tid >> 1, cs = (tid & 1) * 64;
        const __half* qh = Qhi + (size_t)(qb + r) * HDIM + h * HD + cs;
        const __half* ql = Qlo + (size_t)(qb + r) * HDIM + h * HD + cs;
#pragma unroll
        for (int j = 0; j < 8; j++) {
            CP_ASYNC16(sb + (r * LDQ + cs + j * 8) * 2, qh + j * 8);
            CP_ASYNC16(sb + (AQL + r * LDQ + cs + j * 8) * 2, ql + j * 8);
        }
        CP_COMMIT;          // group: Q
    }
    load_kv(0, 0);          // group: KV(0)

    CP_WAIT1;               // Q arrived
    __syncthreads();

    uint32_t qfh[8][4], qfl[8][4];
#pragma unroll
    for (int ks = 0; ks < 8; ks++) {
        int off = ((qrow + a_r) * LDQ + ks * 16 + a_c) * 2;
        ldsm4(qfh[ks], sb + off);
        ldsm4(qfl[ks], sb + AQL * 2 + off);
    }

    float m0 = -INFINITY, m1 = -INFINITY, l0 = 0.f, l1 = 0.f;
    float oacc[16][4];
#pragma unroll
    for (int nt = 0; nt < 16; nt++)
#pragma unroll
        for (int j = 0; j < 4; j++) oacc[nt][j] = 0.f;

    const int NT = S_LEN / 64;
    for (int t = 0; t < NT; t++) {
        const int s = t & 1;
        CP_WAIT0;
        __syncthreads();
        if (t + 1 < NT) load_kv(t + 1, s ^ 1);

        const uint32_t stg = sb + (ASTG0 + s * ASTG) * 2;

        // ---- Phase 1: S = Q K^T  (2 MMAs per sub-tile) ----
        float sacc[8][4];
#pragma unroll
        for (int nt = 0; nt < 8; nt++)
#pragma unroll
            for (int j = 0; j < 4; j++) sacc[nt][j] = 0.f;

#pragma unroll
        for (int ks = 0; ks < 8; ks++) {
            const int k0 = ks * 16;
            uint32_t bh[4][4];
#pragma unroll
            for (int g = 0; g < 4; g++) {
                int off = ((g * 16 + b_n) * LDQ + k0 + b_k) * 2;
                ldsm4(bh[g], stg + off);
            }
#pragma unroll
            for (int nt = 0; nt < 8; nt++) {
                const uint32_t* bhp = &bh[nt >> 1][(nt & 1) * 2];
                mma_f16(sacc[nt], qfh[ks], bhp);
                mma_f16(sacc[nt], qfl[ks], bhp);
            }
        }

        // ---- warp-local online softmax (log2 domain) ----
        float tm0 = -INFINITY, tm1 = -INFINITY;
#pragma unroll
        for (int nt = 0; nt < 8; nt++) {
            tm0 = fmaxf(tm0, fmaxf(sacc[nt][0], sacc[nt][1]));
            tm1 = fmaxf(tm1, fmaxf(sacc[nt][2], sacc[nt][3]));
        }
        tm0 = fmaxf(tm0, __shfl_xor_sync(0xffffffffu, tm0, 1));
        tm0 = fmaxf(tm0, __shfl_xor_sync(0xffffffffu, tm0, 2));
        tm1 = fmaxf(tm1, __shfl_xor_sync(0xffffffffu, tm1, 1));
        tm1 = fmaxf(tm1, __shfl_xor_sync(0xffffffffu, tm1, 2));
        const float mn0 = fmaxf(m0, tm0), mn1 = fmaxf(m1, tm1);
        const float c0 = ex2f(m0 - mn0), c1 = ex2f(m1 - mn1);
        m0 = mn0; m1 = mn1;

        float ls0 = 0.f, ls1 = 0.f;
#pragma unroll
        for (int nt = 0; nt < 8; nt++) {
            sacc[nt][0] = ex2f(sacc[nt][0] - mn0);
            sacc[nt][1] = ex2f(sacc[nt][1] - mn0);
            sacc[nt][2] = ex2f(sacc[nt][2] - mn1);
            sacc[nt][3] = ex2f(sacc[nt][3] - mn1);
            ls0 += sacc[nt][0] + sacc[nt][1];
            ls1 += sacc[nt][2] + sacc[nt][3];
        }
        ls0 += __shfl_xor_sync(0xffffffffu, ls0, 1);
        ls0 += __shfl_xor_sync(0xffffffffu, ls0, 2);
        ls1 += __shfl_xor_sync(0xffffffffu, ls1, 1);
        ls1 += __shfl_xor_sync(0xffffffffu, ls1, 2);
        l0 = l0 * c0 + ls0;
        l1 = l1 * c1 + ls1;

        if (c0 != 1.f || c1 != 1.f) {
#pragma unroll
            for (int nt = 0; nt < 16; nt++) {
                oacc[nt][0] *= c0; oacc[nt][1] *= c0;
                oacc[nt][2] *= c1; oacc[nt][3] *= c1;
            }
        }

        // ---- Phase 2: O += P V  (P fp16 hi/lo register A-fragments) ----
#pragma unroll
        for (int ks = 0; ks < 4; ks++) {
            uint32_t ph4[4], pl4[4];
            split_pack2h(sacc[2 * ks][0], sacc[2 * ks][1], ph4[0], pl4[0]);
            split_pack2h(sacc[2 * ks][2], sacc[2 * ks][3], ph4[1], pl4[1]);
            split_pack2h(sacc[2 * ks + 1][0], sacc[2 * ks + 1][1], ph4[2], pl4[2]);
            split_pack2h(sacc[2 * ks + 1][2], sacc[2 * ks + 1][3], ph4[3], pl4[3]);
            const int k0 = ks * 16;
#pragma unroll
            for (int g = 0; g < 8; g++) {
                uint32_t vh[4];
                int off = ((g * 16 + b_n) * LDV + k0 + b_k) * 2;
                ldsm4(vh, stg + AVH_OFF * 2 + off);
#pragma unroll
                for (int sub = 0; sub < 2; sub++) {
                    const int nt = g * 2 + sub;
                    mma_f16(oacc[nt], ph4, &vh[sub * 2]);
                    mma_f16(oacc[nt], pl4, &vh[sub * 2]);
                }
            }
        }
    }

    // ---- epilogue: normalize + bf16 hi/lo split out ----
    const float inv0 = 1.f / l0, inv1 = 1.f / l1;
    const int r0 = qrow + (lane >> 2);
#pragma unroll
    for (int nt = 0; nt < 16; nt++) {
        const int col = nt * 8 + (lane & 3) * 2;
        size_t i0 = (size_t)(qb + r0) * HDIM + h * HD + col;
        size_t i1 = (size_t)(qb + r0 + 8) * HDIM + h * HD + col;
        split_store2(Ohi + i0, Olo + i0, oacc[nt][0] * inv0, oacc[nt][1] * inv0);
        split_store2(Ohi + i1, Olo + i1, oacc[nt][2] * inv1, oacc[nt][3] * inv1);
    }
}

// ---------------- launch ----------------
extern "C" void kernel_launch(void* const* d_in, const int* in_sizes, int n_in,
                              void* d_out, int out_size)
{
    const float* hidden = (const float*)d_in[0];
    const float* Wq = (const float*)d_in[1];
    const float* bq = (const float*)d_in[2];
    const float* Wk = (const float*)d_in[3];
    const float* bk = (const float*)d_in[4];
    const float* Wv = (const float*)d_in[5];
    const float* bv = (const float*)d_in[6];
    const float* Wo = (const float*)d_in[7];
    const float* bo = (const float*)d_in[8];
    float* out = (float*)d_out;

    __nv_bfloat16 *Hhi, *Hlo, *Wqhi, *Wqlo, *Wkhi, *Wklo, *Wvhi, *Wvlo,
                  *Wohi, *Wolo, *Ohi, *Olo;
    __half *Qh, *Ql, *Kh, *Vh, *VTh;
    cudaGetSymbolAddress((void**)&Hhi, g_Hhi);  cudaGetSymbolAddress((void**)&Hlo, g_Hlo);
    cudaGetSymbolAddress((void**)&Wqhi, g_Wqhi); cudaGetSymbolAddress((void**)&Wqlo, g_Wqlo);
    cudaGetSymbolAddress((void**)&Wkhi, g_Wkhi); cudaGetSymbolAddress((void**)&Wklo, g_Wklo);
    cudaGetSymbolAddress((void**)&Wvhi, g_Wvhi); cudaGetSymbolAddress((void**)&Wvlo, g_Wvlo);
    cudaGetSymbolAddress((void**)&Wohi, g_Wohi); cudaGetSymbolAddress((void**)&Wolo, g_Wolo);
    cudaGetSymbolAddress((void**)&Qh, g_Qh);     cudaGetSymbolAddress((void**)&Ql, g_Ql);
    cudaGetSymbolAddress((void**)&Kh, g_Kh);     cudaGetSymbolAddress((void**)&Vh, g_Vh);
    cudaGetSymbolAddress((void**)&VTh, g_VTh);
    cudaGetSymbolAddress((void**)&Ohi, g_Ohi);   cudaGetSymbolAddress((void**)&Olo, g_Olo);

    cudaFuncSetAttribute(gemm_hmma<0>, cudaFuncAttributeMaxDynamicSharedMemorySize, GEMM_SMEM);
    cudaFuncSetAttribute(gemm_hmma<1>, cudaFuncAttributeMaxDynamicSharedMemorySize, GEMM_SMEM);
    cudaFuncSetAttribute(gemm_hmma<2>, cudaFuncAttributeMaxDynamicSharedMemorySize, GEMM_SMEM);
    cudaFuncSetAttribute(attn_hmma, cudaFuncAttributeMaxDynamicSharedMemorySize, ATT_SMEM);

    const int nH4 = S_LEN * HDIM / 4, nW4 = HDIM * HDIM / 4;
    split_pre<<<nH4 / 256, 256>>>(hidden, Hhi, Hlo, nH4);
    split_pre<<<nW4 / 256, 256>>>(Wq, Wqhi, Wqlo, nW4);
    split_pre<<<nW4 / 256, 256>>>(Wk, Wkhi, Wklo, nW4);
    split_pre<<<nW4 / 256, 256>>>(Wv, Wvhi, Wvlo, nW4);
    split_pre<<<nW4 / 256, 256>>>(Wo, Wohi, Wolo, nW4);

    dim3 ggrid(HDIM / 128, S_LEN / 128);   // (16, 32)
    // Q: fp16 hi/lo, pre-scaled by SCALE*log2(e)
    gemm_hmma<1><<<ggrid, 256, GEMM_SMEM>>>(Hhi, Hlo, Wqhi, Wqlo, bq, SCALE2,
                                            nullptr, Qh, Ql, nullptr,
                                            S_LEN, HDIM, HDIM);
    // K: fp16 single
    gemm_hmma<2><<<ggrid, 256, GEMM_SMEM>>>(Hhi, Hlo, Wkhi, Wklo, bk, 1.f,
                                            nullptr, nullptr, nullptr, Kh,
                                            S_LEN, HDIM, HDIM);
    // V: fp16 single
    gemm_hmma<2><<<ggrid, 256, GEMM_SMEM>>>(Hhi, Hlo, Wvhi, Wvlo, bv, 1.f,
                                            nullptr, nullptr, nullptr, Vh,
                                            S_LEN, HDIM, HDIM);

    dim3 tgrid(HDIM / 32, S_LEN / 32);
    transpose_h<<<tgrid, dim3(32, 8)>>>(Vh, VTh);

    dim3 agrid(S_LEN / 128, NHEADS);       // (32, 16)
    attn_hmma<<<agrid, 256, ATT_SMEM>>>(Qh, Ql, Kh, VTh, Ohi, Olo);

    gemm_hmma<0><<<ggrid, 256, GEMM_SMEM>>>(Ohi, Olo, Wohi, Wolo, bo, 1.f,
                                            out, nullptr, nullptr, nullptr,
                                            S_LEN, HDIM, HDIM);
}

// round 11
// speedup vs baseline: 4.6352x; 1.2110x over previous
#include <cuda_runtime.h>
#include <cuda_bf16.h>
#include <cuda_fp16.h>
#include <cstdint>
#include <math.h>

#define S_LEN 4096
#define HDIM  2048
#define NHEADS 16
#define HD    128
#define SCALE 0.08838834764831845f
// SCALE * log2(e): scores come out of QK^T already in log2 units
#define SCALE2 0.1275332511737922f

// ---------------- scratch globals ----------------
__device__ __half g_Hhi[S_LEN * HDIM], g_Hlo[S_LEN * HDIM];   // hidden fp16 hi/lo
__device__ __half g_Wq[HDIM * HDIM], g_Wk[HDIM * HDIM];       // weights fp16
__device__ __half g_Wv[HDIM * HDIM], g_Wo[HDIM * HDIM];
__device__ __half g_Qh[S_LEN * HDIM], g_Ql[S_LEN * HDIM];     // Q fp16 hi/lo
__device__ __half g_Kh[S_LEN * HDIM];                         // K fp16
__device__ __half g_Vh[S_LEN * HDIM];                         // V fp16
__device__ __half g_VTh[HDIM * S_LEN];                        // V^T fp16
__device__ __half g_Ohi[S_LEN * HDIM], g_Olo[S_LEN * HDIM];   // attn out fp16 hi/lo

// ---------------- helpers ----------------
__device__ __forceinline__ uint32_t smem_u32(const void* p) {
    uint32_t a;
    asm("{ .reg .u64 t; cvta.to.shared.u64 t, %1; cvt.u32.u64 %0, t; }"
        : "=r"(a) : "l"(p));
    return a;
}
__device__ __forceinline__ void ldsm4(uint32_t* r, uint32_t a) {
    asm volatile("ldmatrix.sync.aligned.m8n8.x4.shared.b16 {%0,%1,%2,%3}, [%4];"
        : "=r"(r[0]), "=r"(r[1]), "=r"(r[2]), "=r"(r[3]) : "r"(a));
}
__device__ __forceinline__ void mma_f16(float* c, const uint32_t* a,
                                        const uint32_t* b) {
    asm volatile("mma.sync.aligned.m16n8k16.row.col.f32.f16.f16.f32 "
        "{%0,%1,%2,%3}, {%4,%5,%6,%7}, {%8,%9}, {%0,%1,%2,%3};"
        : "+f"(c[0]), "+f"(c[1]), "+f"(c[2]), "+f"(c[3])
        : "r"(a[0]), "r"(a[1]), "r"(a[2]), "r"(a[3]), "r"(b[0]), "r"(b[1]));
}
__device__ __forceinline__ float ex2f(float x) {
    float r;
    asm("ex2.approx.f32 %0, %1;" : "=f"(r) : "f"(x));
    return r;
}
__device__ __forceinline__ void split_store2h(__half* hi, __half* lo,
                                              float x, float y) {
    __half hx = __float2half_rn(x), hy = __float2half_rn(y);
    __half2 h2 = __halves2half2(hx, hy);
    __half2 l2 = __halves2half2(__float2half_rn(x - __half2float(hx)),
                                __float2half_rn(y - __half2float(hy)));
    *reinterpret_cast<__half2*>(hi) = h2;
    *reinterpret_cast<__half2*>(lo) = l2;
}
__device__ __forceinline__ void split_pack2h(float x, float y,
                                             uint32_t& hi, uint32_t& lo) {
    __half hx = __float2half_rn(x), hy = __float2half_rn(y);
    __half lx = __float2half_rn(x - __half2float(hx));
    __half ly = __float2half_rn(y - __half2float(hy));
    uint16_t a = *(uint16_t*)&hx, b = *(uint16_t*)&hy;
    uint16_t c = *(uint16_t*)&lx, d = *(uint16_t*)&ly;
    hi = (uint32_t)a | ((uint32_t)b << 16);
    lo = (uint32_t)c | ((uint32_t)d << 16);
}
#define CP_ASYNC16(dst, src) \
    asm volatile("cp.async.cg.shared.global [%0], [%1], 16;\n" \
                 :: "r"(dst), "l"(src))
#define CP_COMMIT asm volatile("cp.async.commit_group;\n" ::: "memory")
#define CP_WAIT0  asm volatile("cp.async.wait_group 0;\n" ::: "memory")
#define CP_WAIT1  asm volatile("cp.async.wait_group 1;\n" ::: "memory")

// ---------------- prepass ----------------
// fp32 -> fp16 hi/lo (hidden)
__global__ __launch_bounds__(256) void split_pre_h(
    const float* __restrict__ in, __half* __restrict__ hi,
    __half* __restrict__ lo, int n4)
{
    int i = blockIdx.x * blockDim.x + threadIdx.x;
    if (i < n4) {
        float4 v = ((const float4*)in)[i];
        split_store2h(hi + i * 4, lo + i * 4, v.x, v.y);
        split_store2h(hi + i * 4 + 2, lo + i * 4 + 2, v.z, v.w);
    }
}
// fp32 -> fp16 single (weights)
__global__ __launch_bounds__(256) void conv_fp16(
    const float* __restrict__ in, __half* __restrict__ out, int n4)
{
    int i = blockIdx.x * blockDim.x + threadIdx.x;
    if (i < n4) {
        float4 v = ((const float4*)in)[i];
        __half2 a = __halves2half2(__float2half_rn(v.x), __float2half_rn(v.y));
        __half2 b = __halves2half2(__float2half_rn(v.z), __float2half_rn(v.w));
        *(__half2*)(out + i * 4) = a;
        *(__half2*)(out + i * 4 + 2) = b;
    }
}

// ---------------- HMMA GEMM (NT + bias)*scale, fp16 2-MMA, cp.async 2-stage
// A = fp16 hi/lo planes (near-exact), B = fp16 single plane (weights).
// BM=BN=128, BK=32, 256 threads, 8 warps (2m x 4n).
// OUT_MODE: 0 = fp32, 1 = fp16 hi/lo planes, 2 = fp16 single plane
#define LDAB 40
#define STG_BYTES 30720    /* Ahi 10240 | Alo 10240 | B 10240 */
#define GEMM_SMEM (2 * STG_BYTES)

template <int OUT_MODE>
__global__ __launch_bounds__(256) void gemm_hmma(
    const __half* __restrict__ Ahi, const __half* __restrict__ Alo,
    const __half* __restrict__ B,
    const float* __restrict__ bias, float scale,
    float* __restrict__ Cf, __half* __restrict__ Chh,
    __half* __restrict__ Chl, __half* __restrict__ Ch,
    int M, int N, int K)
{
    extern __shared__ char smraw[];
    const uint32_t sb = smem_u32(smraw);

    const int tid = threadIdx.x, lane = tid & 31, wid = tid >> 5;
    const int wm = wid >> 2, wn = wid & 3;
    const int bm = blockIdx.y * 128, bn = blockIdx.x * 128;
    const int m0 = wm * 64, n0 = wn * 32;

    const int a_r = lane & 15, a_c = (lane >> 4) * 8;
    const int b_n = ((lane >> 4) & 1) * 8 + (lane & 7);
    const int b_k = ((lane >> 3) & 1) * 8;

    const int l_row0 = (tid * 2) >> 2, l_c0 = ((tid * 2) & 3) * 8;
    const int l_row1 = (tid * 2 + 1) >> 2, l_c1 = ((tid * 2 + 1) & 3) * 8;

    float acc[4][4][4];
#pragma unroll
    for (int mt = 0; mt < 4; mt++)
#pragma unroll
        for (int nt = 0; nt < 4; nt++)
#pragma unroll
            for (int j = 0; j < 4; j++) acc[mt][nt][j] = 0.f;

    const int nIter = K / 32;

    auto load_stage = [&](int kc, int s) {
        const uint32_t st = sb + s * STG_BYTES;
        const int k0 = kc * 32;
        CP_ASYNC16(st + (l_row0 * LDAB + l_c0) * 2,
                   Ahi + (size_t)(bm + l_row0) * K + k0 + l_c0);
        CP_ASYNC16(st + (l_row1 * LDAB + l_c1) * 2,
                   Ahi + (size_t)(bm + l_row1) * K + k0 + l_c1);
        CP_ASYNC16(st + 10240 + (l_row0 * LDAB + l_c0) * 2,
                   Alo + (size_t)(bm + l_row0) * K + k0 + l_c0);
        CP_ASYNC16(st + 10240 + (l_row1 * LDAB + l_c1) * 2,
                   Alo + (size_t)(bm + l_row1) * K + k0 + l_c1);
        CP_ASYNC16(st + 20480 + (l_row0 * LDAB + l_c0) * 2,
                   B + (size_t)(bn + l_row0) * K + k0 + l_c0);
        CP_ASYNC16(st + 20480 + (l_row1 * LDAB + l_c1) * 2,
                   B + (size_t)(bn + l_row1) * K + k0 + l_c1);
        CP_COMMIT;
    };

    load_stage(0, 0);
    for (int kc = 0; kc < nIter; kc++) {
        const int s = kc & 1;
        CP_WAIT0;
        __syncthreads();
        if (kc + 1 < nIter) load_stage(kc + 1, s ^ 1);

        const uint32_t st = sb + s * STG_BYTES;
#pragma unroll
        for (int ks = 0; ks < 2; ks++) {
            const int k0 = ks * 16;
            uint32_t ah[4][4], al[4][4], bb[2][4];
#pragma unroll
            for (int mt = 0; mt < 4; mt++) {
                int off = ((m0 + mt * 16 + a_r) * LDAB + k0 + a_c) * 2;
                ldsm4(ah[mt], st + off);
                ldsm4(al[mt], st + 10240 + off);
            }
#pragma unroll
            for (int bp = 0; bp < 2; bp++) {
                int off = ((n0 + bp * 16 + b_n) * LDAB + k0 + b_k) * 2;
                ldsm4(bb[bp], st + 20480 + off);
            }
#pragma unroll
            for (int mt = 0; mt < 4; mt++)
#pragma unroll
                for (int nt = 0; nt < 4; nt++) {
                    const uint32_t* bp_ = &bb[nt >> 1][(nt & 1) * 2];
                    mma_f16(acc[mt][nt], ah[mt], bp_);
                    mma_f16(acc[mt][nt], al[mt], bp_);
                }
        }
    }

#pragma unroll
    for (int mt = 0; mt < 4; mt++) {
        const int r0 = bm + m0 + mt * 16 + (lane >> 2);
#pragma unroll
        for (int nt = 0; nt < 4; nt++) {
            const int col = bn + n0 + nt * 8 + (lane & 3) * 2;
            float2 bv = *(const float2*)(bias + col);
            float c00 = (acc[mt][nt][0] + bv.x) * scale;
            float c01 = (acc[mt][nt][1] + bv.y) * scale;
            float c10 = (acc[mt][nt][2] + bv.x) * scale;
            float c11 = (acc[mt][nt][3] + bv.y) * scale;
            if (OUT_MODE == 0) {
                *(float2*)(Cf + (size_t)r0 * N + col) = make_float2(c00, c01);
                *(float2*)(Cf + (size_t)(r0 + 8) * N + col) = make_float2(c10, c11);
            } else if (OUT_MODE == 1) {
                split_store2h(Chh + (size_t)r0 * N + col,
                              Chl + (size_t)r0 * N + col, c00, c01);
                split_store2h(Chh + (size_t)(r0 + 8) * N + col,
                              Chl + (size_t)(r0 + 8) * N + col, c10, c11);
            } else {
                *(__half2*)(Ch + (size_t)r0 * N + col) =
                    __halves2half2(__float2half_rn(c00), __float2half_rn(c01));
                *(__half2*)(Ch + (size_t)(r0 + 8) * N + col) =
                    __halves2half2(__float2half_rn(c10), __float2half_rn(c11));
            }
        }
    }
}

// ------- transpose fp16: out[c][s] = in[s][c] -------
__global__ __launch_bounds__(256) void transpose_h(
    const __half* __restrict__ in, __half* __restrict__ out)
{
    __shared__ __half tile[32][34];
    const int cb = blockIdx.x * 32, sbk = blockIdx.y * 32;
    const int tx = threadIdx.x, ty = threadIdx.y;
#pragma unroll
    for (int j = 0; j < 4; j++)
        tile[ty + j * 8][tx] = in[(size_t)(sbk + ty + j * 8) * HDIM + cb + tx];
    __syncthreads();
#pragma unroll
    for (int j = 0; j < 4; j++)
        out[(size_t)(cb + ty + j * 8) * S_LEN + sbk + tx] = tile[tx][ty + j * 8];
}

// ---------------- fp16 flash attention, FA2 + cp.async, Q in registers ----
#define LDQ 136
#define LDV 72
#define AQL 17408
#define ASTG0 34816
#define ASTG  17920
#define AVH_OFF 8704
#define ATT_SMEM 141312

__global__ __launch_bounds__(256) void attn_hmma(
    const __half* __restrict__ Qhi, const __half* __restrict__ Qlo,
    const __half* __restrict__ Kh, const __half* __restrict__ VTh,
    __half* __restrict__ Ohi, __half* __restrict__ Olo)
{
    extern __shared__ __half smh[];
    const uint32_t sb = smem_u32(smh);

    const int tid = threadIdx.x, lane = tid & 31, wid = tid >> 5;
    const int qb = blockIdx.x * 128, h = blockIdx.y;

    const int a_r = lane & 15, a_c = (lane >> 4) * 8;
    const int b_n = ((lane >> 4) & 1) * 8 + (lane & 7);
    const int b_k = ((lane >> 3) & 1) * 8;
    const int qrow = wid * 16;

    const int k_r = tid >> 2, k_c = (tid & 3) * 32;
    const int v_r = tid >> 1, v_c = (tid & 1) * 32;

    auto load_kv = [&](int t, int s) {
        const uint32_t stg = sb + (ASTG0 + s * ASTG) * 2;
        const __half* kp = Kh + (size_t)(t * 64 + k_r) * HDIM + h * HD + k_c;
#pragma unroll
        for (int j = 0; j < 4; j++)
            CP_ASYNC16(stg + (k_r * LDQ + k_c + j * 8) * 2, kp + j * 8);
        const __half* vp = VTh + (size_t)(h * HD + v_r) * S_LEN + t * 64 + v_c;
#pragma unroll
        for (int j = 0; j < 4; j++)
            CP_ASYNC16(stg + (AVH_OFF + v_r * LDV + v_c + j * 8) * 2, vp + j * 8);
        CP_COMMIT;
    };

    {
        const int r = tid >> 1, cs = (tid & 1) * 64;
        const __half* qh = Qhi + (size_t)(qb + r) * HDIM + h * HD + cs;
        const __half* ql = Qlo + (size_t)(qb + r) * HDIM + h * HD + cs;
#pragma unroll
        for (int j = 0; j < 8; j++) {
            CP_ASYNC16(sb + (r * LDQ + cs + j * 8) * 2, qh + j * 8);
            CP_ASYNC16(sb + (AQL + r * LDQ + cs + j * 8) * 2, ql + j * 8);
        }
        CP_COMMIT;          // group: Q
    }
    load_kv(0, 0);          // group: KV(0)

    CP_WAIT1;
    __syncthreads();

    uint32_t qfh[8][4], qfl[8][4];
#pragma unroll
    for (int ks = 0; ks < 8; ks++) {
        int off = ((qrow + a_r) * LDQ + ks * 16 + a_c) * 2;
        ldsm4(qfh[ks], sb + off);
        ldsm4(qfl[ks], sb + AQL * 2 + off);
    }

    float m0 = -INFINITY, m1 = -INFINITY, l0 = 0.f, l1 = 0.f;
    float oacc[16][4];
#pragma unroll
    for (int nt = 0; nt < 16; nt++)
#pragma unroll
        for (int j = 0; j < 4; j++) oacc[nt][j] = 0.f;

    const int NT = S_LEN / 64;
    for (int t = 0; t < NT; t++) {
        const int s = t & 1;
        CP_WAIT0;
        __syncthreads();
        if (t + 1 < NT) load_kv(t + 1, s ^ 1);

        const uint32_t stg = sb + (ASTG0 + s * ASTG) * 2;

        // ---- Phase 1: S = Q K^T ----
        float sacc[8][4];
#pragma unroll
        for (int nt = 0; nt < 8; nt++)
#pragma unroll
            for (int j = 0; j < 4; j++) sacc[nt][j] = 0.f;

#pragma unroll
        for (int ks = 0; ks < 8; ks++) {
            const int k0 = ks * 16;
            uint32_t bh[4][4];
#pragma unroll
            for (int g = 0; g < 4; g++) {
                int off = ((g * 16 + b_n) * LDQ + k0 + b_k) * 2;
                ldsm4(bh[g], stg + off);
            }
#pragma unroll
            for (int nt = 0; nt < 8; nt++) {
                const uint32_t* bhp = &bh[nt >> 1][(nt & 1) * 2];
                mma_f16(sacc[nt], qfh[ks], bhp);
                mma_f16(sacc[nt], qfl[ks], bhp);
            }
        }

        // ---- warp-local online softmax (log2 domain) ----
        float tm0 = -INFINITY, tm1 = -INFINITY;
#pragma unroll
        for (int nt = 0; nt < 8; nt++) {
            tm0 = fmaxf(tm0, fmaxf(sacc[nt][0], sacc[nt][1]));
            tm1 = fmaxf(tm1, fmaxf(sacc[nt][2], sacc[nt][3]));
        }
        tm0 = fmaxf(tm0, __shfl_xor_sync(0xffffffffu, tm0, 1));
        tm0 = fmaxf(tm0, __shfl_xor_sync(0xffffffffu, tm0, 2));
        tm1 = fmaxf(tm1, __shfl_xor_sync(0xffffffffu, tm1, 1));
        tm1 = fmaxf(tm1, __shfl_xor_sync(0xffffffffu, tm1, 2));
        const float mn0 = fmaxf(m0, tm0), mn1 = fmaxf(m1, tm1);
        const float c0 = ex2f(m0 - mn0), c1 = ex2f(m1 - mn1);
        m0 = mn0; m1 = mn1;

        float ls0 = 0.f, ls1 = 0.f;
#pragma unroll
        for (int nt = 0; nt < 8; nt++) {
            sacc[nt][0] = ex2f(sacc[nt][0] - mn0);
            sacc[nt][1] = ex2f(sacc[nt][1] - mn0);
            sacc[nt][2] = ex2f(sacc[nt][2] - mn1);
            sacc[nt][3] = ex2f(sacc[nt][3] - mn1);
            ls0 += sacc[nt][0] + sacc[nt][1];
            ls1 += sacc[nt][2] + sacc[nt][3];
        }
        ls0 += __shfl_xor_sync(0xffffffffu, ls0, 1);
        ls0 += __shfl_xor_sync(0xffffffffu, ls0, 2);
        ls1 += __shfl_xor_sync(0xffffffffu, ls1, 1);
        ls1 += __shfl_xor_sync(0xffffffffu, ls1, 2);
        l0 = l0 * c0 + ls0;
        l1 = l1 * c1 + ls1;

        if (c0 != 1.f || c1 != 1.f) {
#pragma unroll
            for (int nt = 0; nt < 16; nt++) {
                oacc[nt][0] *= c0; oacc[nt][1] *= c0;
                oacc[nt][2] *= c1; oacc[nt][3] *= c1;
            }
        }

        // ---- Phase 2: O += P V ----
#pragma unroll
        for (int ks = 0; ks < 4; ks++) {
            uint32_t ph4[4], pl4[4];
            split_pack2h(sacc[2 * ks][0], sacc[2 * ks][1], ph4[0], pl4[0]);
            split_pack2h(sacc[2 * ks][2], sacc[2 * ks][3], ph4[1], pl4[1]);
            split_pack2h(sacc[2 * ks + 1][0], sacc[2 * ks + 1][1], ph4[2], pl4[2]);
            split_pack2h(sacc[2 * ks + 1][2], sacc[2 * ks + 1][3], ph4[3], pl4[3]);
            const int k0 = ks * 16;
#pragma unroll
            for (int g = 0; g < 8; g++) {
                uint32_t vh[4];
                int off = ((g * 16 + b_n) * LDV + k0 + b_k) * 2;
                ldsm4(vh, stg + AVH_OFF * 2 + off);
#pragma unroll
                for (int sub = 0; sub < 2; sub++) {
                    const int nt = g * 2 + sub;
                    mma_f16(oacc[nt], ph4, &vh[sub * 2]);
                    mma_f16(oacc[nt], pl4, &vh[sub * 2]);
                }
            }
        }
    }

    // ---- epilogue: normalize + fp16 hi/lo split out ----
    const float inv0 = 1.f / l0, inv1 = 1.f / l1;
    const int r0 = qrow + (lane >> 2);
#pragma unroll
    for (int nt = 0; nt < 16; nt++) {
        const int col = nt * 8 + (lane & 3) * 2;
        size_t i0 = (size_t)(qb + r0) * HDIM + h * HD + col;
        size_t i1 = (size_t)(qb + r0 + 8) * HDIM + h * HD + col;
        split_store2h(Ohi + i0, Olo + i0, oacc[nt][0] * inv0, oacc[nt][1] * inv0);
        split_store2h(Ohi + i1, Olo + i1, oacc[nt][2] * inv1, oacc[nt][3] * inv1);
    }
}

// ---------------- launch ----------------
extern "C" void kernel_launch(void* const* d_in, const int* in_sizes, int n_in,
                              void* d_out, int out_size)
{
    const float* hidden = (const float*)d_in[0];
    const float* Wq = (const float*)d_in[1];
    const float* bq = (const float*)d_in[2];
    const float* Wk = (const float*)d_in[3];
    const float* bk = (const float*)d_in[4];
    const float* Wv = (const float*)d_in[5];
    const float* bv = (const float*)d_in[6];
    const float* Wo = (const float*)d_in[7];
    const float* bo = (const float*)d_in[8];
    float* out = (float*)d_out;

    __half *Hhi, *Hlo, *Wqp, *Wkp, *Wvp, *Wop, *Qh, *Ql, *Kh, *Vh, *VTh,
           *Ohi, *Olo;
    cudaGetSymbolAddress((void**)&Hhi, g_Hhi);  cudaGetSymbolAddress((void**)&Hlo, g_Hlo);
    cudaGetSymbolAddress((void**)&Wqp, g_Wq);   cudaGetSymbolAddress((void**)&Wkp, g_Wk);
    cudaGetSymbolAddress((void**)&Wvp, g_Wv);   cudaGetSymbolAddress((void**)&Wop, g_Wo);
    cudaGetSymbolAddress((void**)&Qh, g_Qh);    cudaGetSymbolAddress((void**)&Ql, g_Ql);
    cudaGetSymbolAddress((void**)&Kh, g_Kh);    cudaGetSymbolAddress((void**)&Vh, g_Vh);
    cudaGetSymbolAddress((void**)&VTh, g_VTh);
    cudaGetSymbolAddress((void**)&Ohi, g_Ohi);  cudaGetSymbolAddress((void**)&Olo, g_Olo);

    cudaFuncSetAttribute(gemm_hmma<0>, cudaFuncAttributeMaxDynamicSharedMemorySize, GEMM_SMEM);
    cudaFuncSetAttribute(gemm_hmma<1>, cudaFuncAttributeMaxDynamicSharedMemorySize, GEMM_SMEM);
    cudaFuncSetAttribute(gemm_hmma<2>, cudaFuncAttributeMaxDynamicSharedMemorySize, GEMM_SMEM);
    cudaFuncSetAttribute(attn_hmma, cudaFuncAttributeMaxDynamicSharedMemorySize, ATT_SMEM);

    const int nH4 = S_LEN * HDIM / 4, nW4 = HDIM * HDIM / 4;
    split_pre_h<<<nH4 / 256, 256>>>(hidden, Hhi, Hlo, nH4);
    conv_fp16<<<nW4 / 256, 256>>>(Wq, Wqp, nW4);
    conv_fp16<<<nW4 / 256, 256>>>(Wk, Wkp, nW4);
    conv_fp16<<<nW4 / 256, 256>>>(Wv, Wvp, nW4);
    conv_fp16<<<nW4 / 256, 256>>>(Wo, Wop, nW4);

    dim3 ggrid(HDIM / 128, S_LEN / 128);   // (16, 32)
    // Q: fp16 hi/lo, pre-scaled by SCALE*log2(e)
    gemm_hmma<1><<<ggrid, 256, GEMM_SMEM>>>(Hhi, Hlo, Wqp, bq, SCALE2,
                                            nullptr, Qh, Ql, nullptr,
                                            S_LEN, HDIM, HDIM);
    gemm_hmma<2><<<ggrid, 256, GEMM_SMEM>>>(Hhi, Hlo, Wkp, bk, 1.f,
                                            nullptr, nullptr, nullptr, Kh,
                                            S_LEN, HDIM, HDIM);
    gemm_hmma<2><<<ggrid, 256, GEMM_SMEM>>>(Hhi, Hlo, Wvp, bv, 1.f,
                                            nullptr, nullptr, nullptr, Vh,
                                            S_LEN, HDIM, HDIM);

    dim3 tgrid(HDIM / 32, S_LEN / 32);
    transpose_h<<<tgrid, dim3(32, 8)>>>(Vh, VTh);

    dim3 agrid(S_LEN / 128, NHEADS);       // (32, 16)
    attn_hmma<<<agrid, 256, ATT_SMEM>>>(Qh, Ql, Kh, VTh, Ohi, Olo);

    gemm_hmma<0><<<ggrid, 256, GEMM_SMEM>>>(Ohi, Olo, Wop, bo, 1.f,
                                            out, nullptr, nullptr, nullptr,
                                            S_LEN, HDIM, HDIM);
}

// round 12
// speedup vs baseline: 5.6897x; 1.2275x over previous
#include <cuda_runtime.h>
#include <cuda_bf16.h>
#include <cuda_fp16.h>
#include <cstdint>
#include <math.h>

#define S_LEN 4096
#define HDIM  2048
#define NHEADS 16
#define HD    128
#define SCALE 0.08838834764831845f
// SCALE * log2(e): scores come out of QK^T already in log2 units
#define SCALE2 0.1275332511737922f

// ---------------- scratch globals ----------------
__device__ __half g_H[S_LEN * HDIM];                          // hidden fp16
__device__ __half g_Wq[HDIM * HDIM], g_Wk[HDIM * HDIM];       // weights fp16
__device__ __half g_Wv[HDIM * HDIM], g_Wo[HDIM * HDIM];
__device__ __half g_Qh[S_LEN * HDIM], g_Ql[S_LEN * HDIM];     // Q fp16 hi/lo
__device__ __half g_Kh[S_LEN * HDIM];                         // K fp16
__device__ __half g_Vh[S_LEN * HDIM];                         // V fp16
__device__ __half g_VTh[HDIM * S_LEN];                        // V^T fp16
__device__ __half g_O[S_LEN * HDIM];                          // attn out fp16

// ---------------- helpers ----------------
__device__ __forceinline__ uint32_t smem_u32(const void* p) {
    uint32_t a;
    asm("{ .reg .u64 t; cvta.to.shared.u64 t, %1; cvt.u32.u64 %0, t; }"
        : "=r"(a) : "l"(p));
    return a;
}
__device__ __forceinline__ void ldsm4(uint32_t* r, uint32_t a) {
    asm volatile("ldmatrix.sync.aligned.m8n8.x4.shared.b16 {%0,%1,%2,%3}, [%4];"
        : "=r"(r[0]), "=r"(r[1]), "=r"(r[2]), "=r"(r[3]) : "r"(a));
}
__device__ __forceinline__ void mma_f16(float* c, const uint32_t* a,
                                        const uint32_t* b) {
    asm volatile("mma.sync.aligned.m16n8k16.row.col.f32.f16.f16.f32 "
        "{%0,%1,%2,%3}, {%4,%5,%6,%7}, {%8,%9}, {%0,%1,%2,%3};"
        : "+f"(c[0]), "+f"(c[1]), "+f"(c[2]), "+f"(c[3])
        : "r"(a[0]), "r"(a[1]), "r"(a[2]), "r"(a[3]), "r"(b[0]), "r"(b[1]));
}
__device__ __forceinline__ float ex2f(float x) {
    float r;
    asm("ex2.approx.f32 %0, %1;" : "=f"(r) : "f"(x));
    return r;
}
__device__ __forceinline__ void split_store2h(__half* hi, __half* lo,
                                              float x, float y) {
    __half hx = __float2half_rn(x), hy = __float2half_rn(y);
    __half2 h2 = __halves2half2(hx, hy);
    __half2 l2 = __halves2half2(__float2half_rn(x - __half2float(hx)),
                                __float2half_rn(y - __half2float(hy)));
    *reinterpret_cast<__half2*>(hi) = h2;
    *reinterpret_cast<__half2*>(lo) = l2;
}
__device__ __forceinline__ void split_pack2h(float x, float y,
                                             uint32_t& hi, uint32_t& lo) {
    __half hx = __float2half_rn(x), hy = __float2half_rn(y);
    __half lx = __float2half_rn(x - __half2float(hx));
    __half ly = __float2half_rn(y - __half2float(hy));
    uint16_t a = *(uint16_t*)&hx, b = *(uint16_t*)&hy;
    uint16_t c = *(uint16_t*)&lx, d = *(uint16_t*)&ly;
    hi = (uint32_t)a | ((uint32_t)b << 16);
    lo = (uint32_t)c | ((uint32_t)d << 16);
}
#define CP_ASYNC16(dst, src) \
    asm volatile("cp.async.cg.shared.global [%0], [%1], 16;\n" \
                 :: "r"(dst), "l"(src))
#define CP_COMMIT asm volatile("cp.async.commit_group;\n" ::: "memory")
#define CP_WAIT0  asm volatile("cp.async.wait_group 0;\n" ::: "memory")
#define CP_WAIT1  asm volatile("cp.async.wait_group 1;\n" ::: "memory")

// ---------------- prepass: fp32 -> fp16 ----------------
__global__ __launch_bounds__(256) void conv_fp16(
    const float* __restrict__ in, __half* __restrict__ out, int n4)
{
    int i = blockIdx.x * blockDim.x + threadIdx.x;
    if (i < n4) {
        float4 v = ((const float4*)in)[i];
        __half2 a = __halves2half2(__float2half_rn(v.x), __float2half_rn(v.y));
        __half2 b = __halves2half2(__float2half_rn(v.z), __float2half_rn(v.w));
        *(__half2*)(out + i * 4) = a;
        *(__half2*)(out + i * 4 + 2) = b;
    }
}

// ---------------- HMMA GEMM (NT + bias)*scale, fp16 1-MMA, cp.async 2-stage
// A = fp16 single plane, B = fp16 single plane. BM=BN=128, BK=32, 256 thr.
// OUT_MODE: 0 = fp32, 1 = fp16 hi/lo planes, 2 = fp16 single plane
#define LDAB 40
#define STG_BYTES 20480    /* A 10240 | B 10240 */
#define GEMM_SMEM (2 * STG_BYTES)

template <int OUT_MODE>
__global__ __launch_bounds__(256) void gemm_hmma(
    const __half* __restrict__ A, const __half* __restrict__ B,
    const float* __restrict__ bias, float scale,
    float* __restrict__ Cf, __half* __restrict__ Chh,
    __half* __restrict__ Chl, __half* __restrict__ Ch,
    int M, int N, int K)
{
    extern __shared__ char smraw[];
    const uint32_t sb = smem_u32(smraw);

    const int tid = threadIdx.x, lane = tid & 31, wid = tid >> 5;
    const int wm = wid >> 2, wn = wid & 3;
    const int bm = blockIdx.y * 128, bn = blockIdx.x * 128;
    const int m0 = wm * 64, n0 = wn * 32;

    const int a_r = lane & 15, a_c = (lane >> 4) * 8;
    const int b_n = ((lane >> 4) & 1) * 8 + (lane & 7);
    const int b_k = ((lane >> 3) & 1) * 8;

    const int l_row0 = (tid * 2) >> 2, l_c0 = ((tid * 2) & 3) * 8;
    const int l_row1 = (tid * 2 + 1) >> 2, l_c1 = ((tid * 2 + 1) & 3) * 8;

    float acc[4][4][4];
#pragma unroll
    for (int mt = 0; mt < 4; mt++)
#pragma unroll
        for (int nt = 0; nt < 4; nt++)
#pragma unroll
            for (int j = 0; j < 4; j++) acc[mt][nt][j] = 0.f;

    const int nIter = K / 32;

    auto load_stage = [&](int kc, int s) {
        const uint32_t st = sb + s * STG_BYTES;
        const int k0 = kc * 32;
        CP_ASYNC16(st + (l_row0 * LDAB + l_c0) * 2,
                   A + (size_t)(bm + l_row0) * K + k0 + l_c0);
        CP_ASYNC16(st + (l_row1 * LDAB + l_c1) * 2,
                   A + (size_t)(bm + l_row1) * K + k0 + l_c1);
        CP_ASYNC16(st + 10240 + (l_row0 * LDAB + l_c0) * 2,
                   B + (size_t)(bn + l_row0) * K + k0 + l_c0);
        CP_ASYNC16(st + 10240 + (l_row1 * LDAB + l_c1) * 2,
                   B + (size_t)(bn + l_row1) * K + k0 + l_c1);
        CP_COMMIT;
    };

    load_stage(0, 0);
    for (int kc = 0; kc < nIter; kc++) {
        const int s = kc & 1;
        CP_WAIT0;
        __syncthreads();
        if (kc + 1 < nIter) load_stage(kc + 1, s ^ 1);

        const uint32_t st = sb + s * STG_BYTES;
#pragma unroll
        for (int ks = 0; ks < 2; ks++) {
            const int k0 = ks * 16;
            uint32_t ah[4][4], bb[2][4];
#pragma unroll
            for (int mt = 0; mt < 4; mt++) {
                int off = ((m0 + mt * 16 + a_r) * LDAB + k0 + a_c) * 2;
                ldsm4(ah[mt], st + off);
            }
#pragma unroll
            for (int bp = 0; bp < 2; bp++) {
                int off = ((n0 + bp * 16 + b_n) * LDAB + k0 + b_k) * 2;
                ldsm4(bb[bp], st + 10240 + off);
            }
#pragma unroll
            for (int mt = 0; mt < 4; mt++)
#pragma unroll
                for (int nt = 0; nt < 4; nt++)
                    mma_f16(acc[mt][nt], ah[mt], &bb[nt >> 1][(nt & 1) * 2]);
        }
    }

#pragma unroll
    for (int mt = 0; mt < 4; mt++) {
        const int r0 = bm + m0 + mt * 16 + (lane >> 2);
#pragma unroll
        for (int nt = 0; nt < 4; nt++) {
            const int col = bn + n0 + nt * 8 + (lane & 3) * 2;
            float2 bv = *(const float2*)(bias + col);
            float c00 = (acc[mt][nt][0] + bv.x) * scale;
            float c01 = (acc[mt][nt][1] + bv.y) * scale;
            float c10 = (acc[mt][nt][2] + bv.x) * scale;
            float c11 = (acc[mt][nt][3] + bv.y) * scale;
            if (OUT_MODE == 0) {
                *(float2*)(Cf + (size_t)r0 * N + col) = make_float2(c00, c01);
                *(float2*)(Cf + (size_t)(r0 + 8) * N + col) = make_float2(c10, c11);
            } else if (OUT_MODE == 1) {
                split_store2h(Chh + (size_t)r0 * N + col,
                              Chl + (size_t)r0 * N + col, c00, c01);
                split_store2h(Chh + (size_t)(r0 + 8) * N + col,
                              Chl + (size_t)(r0 + 8) * N + col, c10, c11);
            } else {
                *(__half2*)(Ch + (size_t)r0 * N + col) =
                    __halves2half2(__float2half_rn(c00), __float2half_rn(c01));
                *(__half2*)(Ch + (size_t)(r0 + 8) * N + col) =
                    __halves2half2(__float2half_rn(c10), __float2half_rn(c11));
            }
        }
    }
}

// ------- transpose fp16: out[c][s] = in[s][c] -------
__global__ __launch_bounds__(256) void transpose_h(
    const __half* __restrict__ in, __half* __restrict__ out)
{
    __shared__ __half tile[32][34];
    const int cb = blockIdx.x * 32, sbk = blockIdx.y * 32;
    const int tx = threadIdx.x, ty = threadIdx.y;
#pragma unroll
    for (int j = 0; j < 4; j++)
        tile[ty + j * 8][tx] = in[(size_t)(sbk + ty + j * 8) * HDIM + cb + tx];
    __syncthreads();
#pragma unroll
    for (int j = 0; j < 4; j++)
        out[(size_t)(cb + ty + j * 8) * S_LEN + sbk + tx] = tile[tx][ty + j * 8];
}

// ---------------- fp16 flash attention, FA2 + cp.async, Q in registers ----
// S = (Qh+Ql)·K (2 MMAs), O += (Ph+Pl)·V (2 MMAs). ex2 softmax (log2 domain).
#define LDQ 136
#define LDV 72
#define AQL 17408
#define ASTG0 34816
#define ASTG  17920
#define AVH_OFF 8704
#define ATT_SMEM 141312

__global__ __launch_bounds__(256) void attn_hmma(
    const __half* __restrict__ Qhi, const __half* __restrict__ Qlo,
    const __half* __restrict__ Kh, const __half* __restrict__ VTh,
    __half* __restrict__ O)
{
    extern __shared__ __half smh[];
    const uint32_t sb = smem_u32(smh);

    const int tid = threadIdx.x, lane = tid & 31, wid = tid >> 5;
    const int qb = blockIdx.x * 128, h = blockIdx.y;

    const int a_r = lane & 15, a_c = (lane >> 4) * 8;
    const int b_n = ((lane >> 4) & 1) * 8 + (lane & 7);
    const int b_k = ((lane >> 3) & 1) * 8;
    const int qrow = wid * 16;

    const int k_r = tid >> 2, k_c = (tid & 3) * 32;
    const int v_r = tid >> 1, v_c = (tid & 1) * 32;

    auto load_kv = [&](int t, int s) {
        const uint32_t stg = sb + (ASTG0 + s * ASTG) * 2;
        const __half* kp = Kh + (size_t)(t * 64 + k_r) * HDIM + h * HD + k_c;
#pragma unroll
        for (int j = 0; j < 4; j++)
            CP_ASYNC16(stg + (k_r * LDQ + k_c + j * 8) * 2, kp + j * 8);
        const __half* vp = VTh + (size_t)(h * HD + v_r) * S_LEN + t * 64 + v_c;
#pragma unroll
        for (int j = 0; j < 4; j++)
            CP_ASYNC16(stg + (AVH_OFF + v_r * LDV + v_c + j * 8) * 2, vp + j * 8);
        CP_COMMIT;
    };

    {
        const int r = tid >> 1, cs = (tid & 1) * 64;
        const __half* qh = Qhi + (size_t)(qb + r) * HDIM + h * HD + cs;
        const __half* ql = Qlo + (size_t)(qb + r) * HDIM + h * HD + cs;
#pragma unroll
        for (int j = 0; j < 8; j++) {
            CP_ASYNC16(sb + (r * LDQ + cs + j * 8) * 2, qh + j * 8);
            CP_ASYNC16(sb + (AQL + r * LDQ + cs + j * 8) * 2, ql + j * 8);
        }
        CP_COMMIT;          // group: Q
    }
    load_kv(0, 0);          // group: KV(0)

    CP_WAIT1;
    __syncthreads();

    uint32_t qfh[8][4], qfl[8][4];
#pragma unroll
    for (int ks = 0; ks < 8; ks++) {
        int off = ((qrow + a_r) * LDQ + ks * 16 + a_c) * 2;
        ldsm4(qfh[ks], sb + off);
        ldsm4(qfl[ks], sb + AQL * 2 + off);
    }

    float m0 = -INFINITY, m1 = -INFINITY, l0 = 0.f, l1 = 0.f;
    float oacc[16][4];
#pragma unroll
    for (int nt = 0; nt < 16; nt++)
#pragma unroll
        for (int j = 0; j < 4; j++) oacc[nt][j] = 0.f;

    const int NT = S_LEN / 64;
    for (int t = 0; t < NT; t++) {
        const int s = t & 1;
        CP_WAIT0;
        __syncthreads();
        if (t + 1 < NT) load_kv(t + 1, s ^ 1);

        const uint32_t stg = sb + (ASTG0 + s * ASTG) * 2;

        // ---- Phase 1: S = Q K^T ----
        float sacc[8][4];
#pragma unroll
        for (int nt = 0; nt < 8; nt++)
#pragma unroll
            for (int j = 0; j < 4; j++) sacc[nt][j] = 0.f;

#pragma unroll
        for (int ks = 0; ks < 8; ks++) {
            const int k0 = ks * 16;
            uint32_t bh[4][4];
#pragma unroll
            for (int g = 0; g < 4; g++) {
                int off = ((g * 16 + b_n) * LDQ + k0 + b_k) * 2;
                ldsm4(bh[g], stg + off);
            }
#pragma unroll
            for (int nt = 0; nt < 8; nt++) {
                const uint32_t* bhp = &bh[nt >> 1][(nt & 1) * 2];
                mma_f16(sacc[nt], qfh[ks], bhp);
                mma_f16(sacc[nt], qfl[ks], bhp);
            }
        }

        // ---- warp-local online softmax (log2 domain) ----
        float tm0 = -INFINITY, tm1 = -INFINITY;
#pragma unroll
        for (int nt = 0; nt < 8; nt++) {
            tm0 = fmaxf(tm0, fmaxf(sacc[nt][0], sacc[nt][1]));
            tm1 = fmaxf(tm1, fmaxf(sacc[nt][2], sacc[nt][3]));
        }
        tm0 = fmaxf(tm0, __shfl_xor_sync(0xffffffffu, tm0, 1));
        tm0 = fmaxf(tm0, __shfl_xor_sync(0xffffffffu, tm0, 2));
        tm1 = fmaxf(tm1, __shfl_xor_sync(0xffffffffu, tm1, 1));
        tm1 = fmaxf(tm1, __shfl_xor_sync(0xffffffffu, tm1, 2));
        const float mn0 = fmaxf(m0, tm0), mn1 = fmaxf(m1, tm1);
        const float c0 = ex2f(m0 - mn0), c1 = ex2f(m1 - mn1);
        m0 = mn0; m1 = mn1;

        float ls0 = 0.f, ls1 = 0.f;
#pragma unroll
        for (int nt = 0; nt < 8; nt++) {
            sacc[nt][0] = ex2f(sacc[nt][0] - mn0);
            sacc[nt][1] = ex2f(sacc[nt][1] - mn0);
            sacc[nt][2] = ex2f(sacc[nt][2] - mn1);
            sacc[nt][3] = ex2f(sacc[nt][3] - mn1);
            ls0 += sacc[nt][0] + sacc[nt][1];
            ls1 += sacc[nt][2] + sacc[nt][3];
        }
        ls0 += __shfl_xor_sync(0xffffffffu, ls0, 1);
        ls0 += __shfl_xor_sync(0xffffffffu, ls0, 2);
        ls1 += __shfl_xor_sync(0xffffffffu, ls1, 1);
        ls1 += __shfl_xor_sync(0xffffffffu, ls1, 2);
        l0 = l0 * c0 + ls0;
        l1 = l1 * c1 + ls1;

        if (c0 != 1.f || c1 != 1.f) {
#pragma unroll
            for (int nt = 0; nt < 16; nt++) {
                oacc[nt][0] *= c0; oacc[nt][1] *= c0;
                oacc[nt][2] *= c1; oacc[nt][3] *= c1;
            }
        }

        // ---- Phase 2: O += P V ----
#pragma unroll
        for (int ks = 0; ks < 4; ks++) {
            uint32_t ph4[4], pl4[4];
            split_pack2h(sacc[2 * ks][0], sacc[2 * ks][1], ph4[0], pl4[0]);
            split_pack2h(sacc[2 * ks][2], sacc[2 * ks][3], ph4[1], pl4[1]);
            split_pack2h(sacc[2 * ks + 1][0], sacc[2 * ks + 1][1], ph4[2], pl4[2]);
            split_pack2h(sacc[2 * ks + 1][2], sacc[2 * ks + 1][3], ph4[3], pl4[3]);
            const int k0 = ks * 16;
#pragma unroll
            for (int g = 0; g < 8; g++) {
                uint32_t vh[4];
                int off = ((g * 16 + b_n) * LDV + k0 + b_k) * 2;
                ldsm4(vh, stg + AVH_OFF * 2 + off);
#pragma unroll
                for (int sub = 0; sub < 2; sub++) {
                    const int nt = g * 2 + sub;
                    mma_f16(oacc[nt], ph4, &vh[sub * 2]);
                    mma_f16(oacc[nt], pl4, &vh[sub * 2]);
                }
            }
        }
    }

    // ---- epilogue: normalize + fp16 out ----
    const float inv0 = 1.f / l0, inv1 = 1.f / l1;
    const int r0 = qrow + (lane >> 2);
#pragma unroll
    for (int nt = 0; nt < 16; nt++) {
        const int col = nt * 8 + (lane & 3) * 2;
        size_t i0 = (size_t)(qb + r0) * HDIM + h * HD + col;
        size_t i1 = (size_t)(qb + r0 + 8) * HDIM + h * HD + col;
        *(__half2*)(O + i0) = __halves2half2(
            __float2half_rn(oacc[nt][0] * inv0), __float2half_rn(oacc[nt][1] * inv0));
        *(__half2*)(O + i1) = __halves2half2(
            __float2half_rn(oacc[nt][2] * inv1), __float2half_rn(oacc[nt][3] * inv1));
    }
}

// ---------------- launch ----------------
extern "C" void kernel_launch(void* const* d_in, const int* in_sizes, int n_in,
                              void* d_out, int out_size)
{
    const float* hidden = (const float*)d_in[0];
    const float* Wq = (const float*)d_in[1];
    const float* bq = (const float*)d_in[2];
    const float* Wk = (const float*)d_in[3];
    const float* bk = (const float*)d_in[4];
    const float* Wv = (const float*)d_in[5];
    const float* bv = (const float*)d_in[6];
    const float* Wo = (const float*)d_in[7];
    const float* bo = (const float*)d_in[8];
    float* out = (float*)d_out;

    __half *Hp, *Wqp, *Wkp, *Wvp, *Wop, *Qh, *Ql, *Kh, *Vh, *VTh, *Op;
    cudaGetSymbolAddress((void**)&Hp, g_H);
    cudaGetSymbolAddress((void**)&Wqp, g_Wq);   cudaGetSymbolAddress((void**)&Wkp, g_Wk);
    cudaGetSymbolAddress((void**)&Wvp, g_Wv);   cudaGetSymbolAddress((void**)&Wop, g_Wo);
    cudaGetSymbolAddress((void**)&Qh, g_Qh);    cudaGetSymbolAddress((void**)&Ql, g_Ql);
    cudaGetSymbolAddress((void**)&Kh, g_Kh);    cudaGetSymbolAddress((void**)&Vh, g_Vh);
    cudaGetSymbolAddress((void**)&VTh, g_VTh);
    cudaGetSymbolAddress((void**)&Op, g_O);

    cudaFuncSetAttribute(gemm_hmma<0>, cudaFuncAttributeMaxDynamicSharedMemorySize, GEMM_SMEM);
    cudaFuncSetAttribute(gemm_hmma<1>, cudaFuncAttributeMaxDynamicSharedMemorySize, GEMM_SMEM);
    cudaFuncSetAttribute(gemm_hmma<2>, cudaFuncAttributeMaxDynamicSharedMemorySize, GEMM_SMEM);
    cudaFuncSetAttribute(attn_hmma, cudaFuncAttributeMaxDynamicSharedMemorySize, ATT_SMEM);

    const int nH4 = S_LEN * HDIM / 4, nW4 = HDIM * HDIM / 4;
    conv_fp16<<<nH4 / 256, 256>>>(hidden, Hp, nH4);
    conv_fp16<<<nW4 / 256, 256>>>(Wq, Wqp, nW4);
    conv_fp16<<<nW4 / 256, 256>>>(Wk, Wkp, nW4);
    conv_fp16<<<nW4 / 256, 256>>>(Wv, Wvp, nW4);
    conv_fp16<<<nW4 / 256, 256>>>(Wo, Wop, nW4);

    dim3 ggrid(HDIM / 128, S_LEN / 128);   // (16, 32)
    // Q: fp16 hi/lo planes, pre-scaled by SCALE*log2(e)
    gemm_hmma<1><<<ggrid, 256, GEMM_SMEM>>>(Hp, Wqp, bq, SCALE2,
                                            nullptr, Qh, Ql, nullptr,
                                            S_LEN, HDIM, HDIM);
    gemm_hmma<2><<<ggrid, 256, GEMM_SMEM>>>(Hp, Wkp, bk, 1.f,
                                            nullptr, nullptr, nullptr, Kh,
                                            S_LEN, HDIM, HDIM);
    gemm_hmma<2><<<ggrid, 256, GEMM_SMEM>>>(Hp, Wvp, bv, 1.f,
                                            nullptr, nullptr, nullptr, Vh,
                                            S_LEN, HDIM, HDIM);

    dim3 tgrid(HDIM / 32, S_LEN / 32);
    transpose_h<<<tgrid, dim3(32, 8)>>>(Vh, VTh);

    dim3 agrid(S_LEN / 128, NHEADS);       // (32, 16)
    attn_hmma<<<agrid, 256, ATT_SMEM>>>(Qh, Ql, Kh, VTh, Op);

    gemm_hmma<0><<<ggrid, 256, GEMM_SMEM>>>(Op, Wop, bo, 1.f,
                                            out, nullptr, nullptr, nullptr,
                                            S_LEN, HDIM, HDIM);
}

// round 13
// speedup vs baseline: 6.3530x; 1.1166x over previous
#include <cuda_runtime.h>
#include <cuda_bf16.h>
#include <cuda_fp16.h>
#include <cstdint>
#include <math.h>

#define S_LEN 4096
#define HDIM  2048
#define NHEADS 16
#define HD    128
#define SCALE 0.08838834764831845f
// SCALE * log2(e): scores come out of QK^T already in log2 units
#define SCALE2 0.1275332511737922f

// ---------------- scratch globals ----------------
__device__ __half g_H[S_LEN * HDIM];                          // hidden fp16
__device__ __half g_Wq[HDIM * HDIM], g_Wk[HDIM * HDIM];       // weights fp16
__device__ __half g_Wv[HDIM * HDIM], g_Wo[HDIM * HDIM];
__device__ __half g_Qh[S_LEN * HDIM], g_Ql[S_LEN * HDIM];     // Q fp16 hi/lo
__device__ __half g_Kh[S_LEN * HDIM];                         // K fp16
__device__ __half g_Vh[S_LEN * HDIM];                         // V fp16
__device__ __half g_VTh[HDIM * S_LEN];                        // V^T fp16
__device__ __half g_O[S_LEN * HDIM];                          // attn out fp16

// ---------------- helpers ----------------
__device__ __forceinline__ uint32_t smem_u32(const void* p) {
    uint32_t a;
    asm("{ .reg .u64 t; cvta.to.shared.u64 t, %1; cvt.u32.u64 %0, t; }"
        : "=r"(a) : "l"(p));
    return a;
}
__device__ __forceinline__ void ldsm4(uint32_t* r, uint32_t a) {
    asm volatile("ldmatrix.sync.aligned.m8n8.x4.shared.b16 {%0,%1,%2,%3}, [%4];"
        : "=r"(r[0]), "=r"(r[1]), "=r"(r[2]), "=r"(r[3]) : "r"(a));
}
__device__ __forceinline__ void mma_f16(float* c, const uint32_t* a,
                                        const uint32_t* b) {
    asm volatile("mma.sync.aligned.m16n8k16.row.col.f32.f16.f16.f32 "
        "{%0,%1,%2,%3}, {%4,%5,%6,%7}, {%8,%9}, {%0,%1,%2,%3};"
        : "+f"(c[0]), "+f"(c[1]), "+f"(c[2]), "+f"(c[3])
        : "r"(a[0]), "r"(a[1]), "r"(a[2]), "r"(a[3]), "r"(b[0]), "r"(b[1]));
}
__device__ __forceinline__ float ex2f(float x) {
    float r;
    asm("ex2.approx.f32 %0, %1;" : "=f"(r) : "f"(x));
    return r;
}
__device__ __forceinline__ void split_store2h(__half* hi, __half* lo,
                                              float x, float y) {
    __half hx = __float2half_rn(x), hy = __float2half_rn(y);
    __half2 h2 = __halves2half2(hx, hy);
    __half2 l2 = __halves2half2(__float2half_rn(x - __half2float(hx)),
                                __float2half_rn(y - __half2float(hy)));
    *reinterpret_cast<__half2*>(hi) = h2;
    *reinterpret_cast<__half2*>(lo) = l2;
}
__device__ __forceinline__ uint32_t pack2h(float x, float y) {
    __half hx = __float2half_rn(x), hy = __float2half_rn(y);
    uint16_t a = *(uint16_t*)&hx, b = *(uint16_t*)&hy;
    return (uint32_t)a | ((uint32_t)b << 16);
}
#define CP_ASYNC16(dst, src) \
    asm volatile("cp.async.cg.shared.global [%0], [%1], 16;\n" \
                 :: "r"(dst), "l"(src))
#define CP_COMMIT asm volatile("cp.async.commit_group;\n" ::: "memory")
#define CP_WAIT0  asm volatile("cp.async.wait_group 0;\n" ::: "memory")
#define CP_WAIT1  asm volatile("cp.async.wait_group 1;\n" ::: "memory")

// ---------------- prepass: fp32 -> fp16 ----------------
__global__ __launch_bounds__(256) void conv_fp16(
    const float* __restrict__ in, __half* __restrict__ out, int n4)
{
    int i = blockIdx.x * blockDim.x + threadIdx.x;
    if (i < n4) {
        float4 v = ((const float4*)in)[i];
        *(__half2*)(out + i * 4) =
            __halves2half2(__float2half_rn(v.x), __float2half_rn(v.y));
        *(__half2*)(out + i * 4 + 2) =
            __halves2half2(__float2half_rn(v.z), __float2half_rn(v.w));
    }
}
// fused 4-weight conversion: blockIdx.y selects the tensor
__global__ __launch_bounds__(256) void conv_fp16_w4(
    const float* __restrict__ w0, const float* __restrict__ w1,
    const float* __restrict__ w2, const float* __restrict__ w3,
    __half* __restrict__ o0, __half* __restrict__ o1,
    __half* __restrict__ o2, __half* __restrict__ o3, int n4)
{
    const float* src = (blockIdx.y == 0) ? w0 : (blockIdx.y == 1) ? w1
                       : (blockIdx.y == 2) ? w2 : w3;
    __half* dst = (blockIdx.y == 0) ? o0 : (blockIdx.y == 1) ? o1
                  : (blockIdx.y == 2) ? o2 : o3;
    int i = blockIdx.x * blockDim.x + threadIdx.x;
    if (i < n4) {
        float4 v = ((const float4*)src)[i];
        *(__half2*)(dst + i * 4) =
            __halves2half2(__float2half_rn(v.x), __float2half_rn(v.y));
        *(__half2*)(dst + i * 4 + 2) =
            __halves2half2(__float2half_rn(v.z), __float2half_rn(v.w));
    }
}

// ---------------- HMMA GEMM (NT + bias)*scale, fp16 1-MMA, cp.async 2-stage
// OUT_MODE: 0 = fp32, 1 = fp16 hi/lo planes, 2 = fp16 single plane
#define LDAB 40
#define STG_BYTES 20480
#define GEMM_SMEM (2 * STG_BYTES)

template <int OUT_MODE>
__global__ __launch_bounds__(256) void gemm_hmma(
    const __half* __restrict__ A, const __half* __restrict__ B,
    const float* __restrict__ bias, float scale,
    float* __restrict__ Cf, __half* __restrict__ Chh,
    __half* __restrict__ Chl, __half* __restrict__ Ch,
    int M, int N, int K)
{
    extern __shared__ char smraw[];
    const uint32_t sb = smem_u32(smraw);

    const int tid = threadIdx.x, lane = tid & 31, wid = tid >> 5;
    const int wm = wid >> 2, wn = wid & 3;
    const int bm = blockIdx.y * 128, bn = blockIdx.x * 128;
    const int m0 = wm * 64, n0 = wn * 32;

    const int a_r = lane & 15, a_c = (lane >> 4) * 8;
    const int b_n = ((lane >> 4) & 1) * 8 + (lane & 7);
    const int b_k = ((lane >> 3) & 1) * 8;

    const int l_row0 = (tid * 2) >> 2, l_c0 = ((tid * 2) & 3) * 8;
    const int l_row1 = (tid * 2 + 1) >> 2, l_c1 = ((tid * 2 + 1) & 3) * 8;

    float acc[4][4][4];
#pragma unroll
    for (int mt = 0; mt < 4; mt++)
#pragma unroll
        for (int nt = 0; nt < 4; nt++)
#pragma unroll
            for (int j = 0; j < 4; j++) acc[mt][nt][j] = 0.f;

    const int nIter = K / 32;

    auto load_stage = [&](int kc, int s) {
        const uint32_t st = sb + s * STG_BYTES;
        const int k0 = kc * 32;
        CP_ASYNC16(st + (l_row0 * LDAB + l_c0) * 2,
                   A + (size_t)(bm + l_row0) * K + k0 + l_c0);
        CP_ASYNC16(st + (l_row1 * LDAB + l_c1) * 2,
                   A + (size_t)(bm + l_row1) * K + k0 + l_c1);
        CP_ASYNC16(st + 10240 + (l_row0 * LDAB + l_c0) * 2,
                   B + (size_t)(bn + l_row0) * K + k0 + l_c0);
        CP_ASYNC16(st + 10240 + (l_row1 * LDAB + l_c1) * 2,
                   B + (size_t)(bn + l_row1) * K + k0 + l_c1);
        CP_COMMIT;
    };

    load_stage(0, 0);
    for (int kc = 0; kc < nIter; kc++) {
        const int s = kc & 1;
        CP_WAIT0;
        __syncthreads();
        if (kc + 1 < nIter) load_stage(kc + 1, s ^ 1);

        const uint32_t st = sb + s * STG_BYTES;
#pragma unroll
        for (int ks = 0; ks < 2; ks++) {
            const int k0 = ks * 16;
            uint32_t ah[4][4], bb[2][4];
#pragma unroll
            for (int mt = 0; mt < 4; mt++) {
                int off = ((m0 + mt * 16 + a_r) * LDAB + k0 + a_c) * 2;
                ldsm4(ah[mt], st + off);
            }
#pragma unroll
            for (int bp = 0; bp < 2; bp++) {
                int off = ((n0 + bp * 16 + b_n) * LDAB + k0 + b_k) * 2;
                ldsm4(bb[bp], st + 10240 + off);
            }
#pragma unroll
            for (int mt = 0; mt < 4; mt++)
#pragma unroll
                for (int nt = 0; nt < 4; nt++)
                    mma_f16(acc[mt][nt], ah[mt], &bb[nt >> 1][(nt & 1) * 2]);
        }
    }

#pragma unroll
    for (int mt = 0; mt < 4; mt++) {
        const int r0 = bm + m0 + mt * 16 + (lane >> 2);
#pragma unroll
        for (int nt = 0; nt < 4; nt++) {
            const int col = bn + n0 + nt * 8 + (lane & 3) * 2;
            float2 bv = *(const float2*)(bias + col);
            float c00 = (acc[mt][nt][0] + bv.x) * scale;
            float c01 = (acc[mt][nt][1] + bv.y) * scale;
            float c10 = (acc[mt][nt][2] + bv.x) * scale;
            float c11 = (acc[mt][nt][3] + bv.y) * scale;
            if (OUT_MODE == 0) {
                *(float2*)(Cf + (size_t)r0 * N + col) = make_float2(c00, c01);
                *(float2*)(Cf + (size_t)(r0 + 8) * N + col) = make_float2(c10, c11);
            } else if (OUT_MODE == 1) {
                split_store2h(Chh + (size_t)r0 * N + col,
                              Chl + (size_t)r0 * N + col, c00, c01);
                split_store2h(Chh + (size_t)(r0 + 8) * N + col,
                              Chl + (size_t)(r0 + 8) * N + col, c10, c11);
            } else {
                *(uint32_t*)(Ch + (size_t)r0 * N + col) = pack2h(c00, c01);
                *(uint32_t*)(Ch + (size_t)(r0 + 8) * N + col) = pack2h(c10, c11);
            }
        }
    }
}

// ------- transpose fp16: out[c][s] = in[s][c] -------
__global__ __launch_bounds__(256) void transpose_h(
    const __half* __restrict__ in, __half* __restrict__ out)
{
    __shared__ __half tile[32][34];
    const int cb = blockIdx.x * 32, sbk = blockIdx.y * 32;
    const int tx = threadIdx.x, ty = threadIdx.y;
#pragma unroll
    for (int j = 0; j < 4; j++)
        tile[ty + j * 8][tx] = in[(size_t)(sbk + ty + j * 8) * HDIM + cb + tx];
    __syncthreads();
#pragma unroll
    for (int j = 0; j < 4; j++)
        out[(size_t)(cb + ty + j * 8) * S_LEN + sbk + tx] = tile[tx][ty + j * 8];
}

// ---------------- fp16 flash attention, FA2 + cp.async, Q in registers ----
// S = (Qh+Ql)·K (2 MMAs), O += P·V (1 MMA, P single fp16). ex2 softmax.
#define LDQ 136
#define LDV 72
#define AQL 17408
#define ASTG0 34816
#define ASTG  17920
#define AVH_OFF 8704
#define ATT_SMEM 141312

__global__ __launch_bounds__(256) void attn_hmma(
    const __half* __restrict__ Qhi, const __half* __restrict__ Qlo,
    const __half* __restrict__ Kh, const __half* __restrict__ VTh,
    __half* __restrict__ O)
{
    extern __shared__ __half smh[];
    const uint32_t sb = smem_u32(smh);

    const int tid = threadIdx.x, lane = tid & 31, wid = tid >> 5;
    const int qb = blockIdx.x * 128, h = blockIdx.y;

    const int a_r = lane & 15, a_c = (lane >> 4) * 8;
    const int b_n = ((lane >> 4) & 1) * 8 + (lane & 7);
    const int b_k = ((lane >> 3) & 1) * 8;
    const int qrow = wid * 16;

    const int k_r = tid >> 2, k_c = (tid & 3) * 32;
    const int v_r = tid >> 1, v_c = (tid & 1) * 32;

    auto load_kv = [&](int t, int s) {
        const uint32_t stg = sb + (ASTG0 + s * ASTG) * 2;
        const __half* kp = Kh + (size_t)(t * 64 + k_r) * HDIM + h * HD + k_c;
#pragma unroll
        for (int j = 0; j < 4; j++)
            CP_ASYNC16(stg + (k_r * LDQ + k_c + j * 8) * 2, kp + j * 8);
        const __half* vp = VTh + (size_t)(h * HD + v_r) * S_LEN + t * 64 + v_c;
#pragma unroll
        for (int j = 0; j < 4; j++)
            CP_ASYNC16(stg + (AVH_OFF + v_r * LDV + v_c + j * 8) * 2, vp + j * 8);
        CP_COMMIT;
    };

    {
        const int r = tid >> 1, cs = (tid & 1) * 64;
        const __half* qh = Qhi + (size_t)(qb + r) * HDIM + h * HD + cs;
        const __half* ql = Qlo + (size_t)(qb + r) * HDIM + h * HD + cs;
#pragma unroll
        for (int j = 0; j < 8; j++) {
            CP_ASYNC16(sb + (r * LDQ + cs + j * 8) * 2, qh + j * 8);
            CP_ASYNC16(sb + (AQL + r * LDQ + cs + j * 8) * 2, ql + j * 8);
        }
        CP_COMMIT;          // group: Q
    }
    load_kv(0, 0);          // group: KV(0)

    CP_WAIT1;
    __syncthreads();

    uint32_t qfh[8][4], qfl[8][4];
#pragma unroll
    for (int ks = 0; ks < 8; ks++) {
        int off = ((qrow + a_r) * LDQ + ks * 16 + a_c) * 2;
        ldsm4(qfh[ks], sb + off);
        ldsm4(qfl[ks], sb + AQL * 2 + off);
    }

    float m0 = -INFINITY, m1 = -INFINITY, l0 = 0.f, l1 = 0.f;
    float oacc[16][4];
#pragma unroll
    for (int nt = 0; nt < 16; nt++)
#pragma unroll
        for (int j = 0; j < 4; j++) oacc[nt][j] = 0.f;

    const int NT = S_LEN / 64;
    for (int t = 0; t < NT; t++) {
        const int s = t & 1;
        CP_WAIT0;
        __syncthreads();
        if (t + 1 < NT) load_kv(t + 1, s ^ 1);

        const uint32_t stg = sb + (ASTG0 + s * ASTG) * 2;

        // ---- Phase 1: S = Q K^T (2 MMAs, Q hi/lo exact) ----
        float sacc[8][4];
#pragma unroll
        for (int nt = 0; nt < 8; nt++)
#pragma unroll
            for (int j = 0; j < 4; j++) sacc[nt][j] = 0.f;

#pragma unroll
        for (int ks = 0; ks < 8; ks++) {
            const int k0 = ks * 16;
            uint32_t bh[4][4];
#pragma unroll
            for (int g = 0; g < 4; g++) {
                int off = ((g * 16 + b_n) * LDQ + k0 + b_k) * 2;
                ldsm4(bh[g], stg + off);
            }
#pragma unroll
            for (int nt = 0; nt < 8; nt++) {
                const uint32_t* bhp = &bh[nt >> 1][(nt & 1) * 2];
                mma_f16(sacc[nt], qfh[ks], bhp);
                mma_f16(sacc[nt], qfl[ks], bhp);
            }
        }

        // ---- warp-local online softmax (log2 domain) ----
        float tm0 = -INFINITY, tm1 = -INFINITY;
#pragma unroll
        for (int nt = 0; nt < 8; nt++) {
            tm0 = fmaxf(tm0, fmaxf(sacc[nt][0], sacc[nt][1]));
            tm1 = fmaxf(tm1, fmaxf(sacc[nt][2], sacc[nt][3]));
        }
        tm0 = fmaxf(tm0, __shfl_xor_sync(0xffffffffu, tm0, 1));
        tm0 = fmaxf(tm0, __shfl_xor_sync(0xffffffffu, tm0, 2));
        tm1 = fmaxf(tm1, __shfl_xor_sync(0xffffffffu, tm1, 1));
        tm1 = fmaxf(tm1, __shfl_xor_sync(0xffffffffu, tm1, 2));
        const float mn0 = fmaxf(m0, tm0), mn1 = fmaxf(m1, tm1);
        const float c0 = ex2f(m0 - mn0), c1 = ex2f(m1 - mn1);
        m0 = mn0; m1 = mn1;

        float ls0 = 0.f, ls1 = 0.f;
#pragma unroll
        for (int nt = 0; nt < 8; nt++) {
            sacc[nt][0] = ex2f(sacc[nt][0] - mn0);
            sacc[nt][1] = ex2f(sacc[nt][1] - mn0);
            sacc[nt][2] = ex2f(sacc[nt][2] - mn1);
            sacc[nt][3] = ex2f(sacc[nt][3] - mn1);
            ls0 += sacc[nt][0] + sacc[nt][1];
            ls1 += sacc[nt][2] + sacc[nt][3];
        }
        ls0 += __shfl_xor_sync(0xffffffffu, ls0, 1);
        ls0 += __shfl_xor_sync(0xffffffffu, ls0, 2);
        ls1 += __shfl_xor_sync(0xffffffffu, ls1, 1);
        ls1 += __shfl_xor_sync(0xffffffffu, ls1, 2);
        l0 = l0 * c0 + ls0;
        l1 = l1 * c1 + ls1;

        if (c0 != 1.f || c1 != 1.f) {
#pragma unroll
            for (int nt = 0; nt < 16; nt++) {
                oacc[nt][0] *= c0; oacc[nt][1] *= c0;
                oacc[nt][2] *= c1; oacc[nt][3] *= c1;
            }
        }

        // ---- Phase 2: O += P V  (single fp16 P, 1 MMA per sub-tile) ----
#pragma unroll
        for (int ks = 0; ks < 4; ks++) {
            uint32_t p4[4];
            p4[0] = pack2h(sacc[2 * ks][0], sacc[2 * ks][1]);
            p4[1] = pack2h(sacc[2 * ks][2], sacc[2 * ks][3]);
            p4[2] = pack2h(sacc[2 * ks + 1][0], sacc[2 * ks + 1][1]);
            p4[3] = pack2h(sacc[2 * ks + 1][2], sacc[2 * ks + 1][3]);
            const int k0 = ks * 16;
#pragma unroll
            for (int g = 0; g < 8; g++) {
                uint32_t vh[4];
                int off = ((g * 16 + b_n) * LDV + k0 + b_k) * 2;
                ldsm4(vh, stg + AVH_OFF * 2 + off);
                mma_f16(oacc[g * 2 + 0], p4, &vh[0]);
                mma_f16(oacc[g * 2 + 1], p4, &vh[2]);
            }
        }
    }

    // ---- epilogue: normalize + fp16 out ----
    const float inv0 = 1.f / l0, inv1 = 1.f / l1;
    const int r0 = qrow + (lane >> 2);
#pragma unroll
    for (int nt = 0; nt < 16; nt++) {
        const int col = nt * 8 + (lane & 3) * 2;
        size_t i0 = (size_t)(qb + r0) * HDIM + h * HD + col;
        size_t i1 = (size_t)(qb + r0 + 8) * HDIM + h * HD + col;
        *(uint32_t*)(O + i0) = pack2h(oacc[nt][0] * inv0, oacc[nt][1] * inv0);
        *(uint32_t*)(O + i1) = pack2h(oacc[nt][2] * inv1, oacc[nt][3] * inv1);
    }
}

// ---------------- launch ----------------
extern "C" void kernel_launch(void* const* d_in, const int* in_sizes, int n_in,
                              void* d_out, int out_size)
{
    const float* hidden = (const float*)d_in[0];
    const float* Wq = (const float*)d_in[1];
    const float* bq = (const float*)d_in[2];
    const float* Wk = (const float*)d_in[3];
    const float* bk = (const float*)d_in[4];
    const float* Wv = (const float*)d_in[5];
    const float* bv = (const float*)d_in[6];
    const float* Wo = (const float*)d_in[7];
    const float* bo = (const float*)d_in[8];
    float* out = (float*)d_out;

    __half *Hp, *Wqp, *Wkp, *Wvp, *Wop, *Qh, *Ql, *Kh, *Vh, *VTh, *Op;
    cudaGetSymbolAddress((void**)&Hp, g_H);
    cudaGetSymbolAddress((void**)&Wqp, g_Wq);   cudaGetSymbolAddress((void**)&Wkp, g_Wk);
    cudaGetSymbolAddress((void**)&Wvp, g_Wv);   cudaGetSymbolAddress((void**)&Wop, g_Wo);
    cudaGetSymbolAddress((void**)&Qh, g_Qh);    cudaGetSymbolAddress((void**)&Ql, g_Ql);
    cudaGetSymbolAddress((void**)&Kh, g_Kh);    cudaGetSymbolAddress((void**)&Vh, g_Vh);
    cudaGetSymbolAddress((void**)&VTh, g_VTh);
    cudaGetSymbolAddress((void**)&Op, g_O);

    cudaFuncSetAttribute(gemm_hmma<0>, cudaFuncAttributeMaxDynamicSharedMemorySize, GEMM_SMEM);
    cudaFuncSetAttribute(gemm_hmma<1>, cudaFuncAttributeMaxDynamicSharedMemorySize, GEMM_SMEM);
    cudaFuncSetAttribute(gemm_hmma<2>, cudaFuncAttributeMaxDynamicSharedMemorySize, GEMM_SMEM);
    cudaFuncSetAttribute(attn_hmma, cudaFuncAttributeMaxDynamicSharedMemorySize, ATT_SMEM);

    const int nH4 = S_LEN * HDIM / 4, nW4 = HDIM * HDIM / 4;
    conv_fp16<<<nH4 / 256, 256>>>(hidden, Hp, nH4);
    conv_fp16_w4<<<dim3(nW4 / 256, 4), 256>>>(Wq, Wk, Wv, Wo,
                                              Wqp, Wkp, Wvp, Wop, nW4);

    dim3 ggrid(HDIM / 128, S_LEN / 128);   // (16, 32)
    // Q: fp16 hi/lo planes, pre-scaled by SCALE*log2(e)
    gemm_hmma<1><<<ggrid, 256, GEMM_SMEM>>>(Hp, Wqp, bq, SCALE2,
                                            nullptr, Qh, Ql, nullptr,
                                            S_LEN, HDIM, HDIM);
    gemm_hmma<2><<<ggrid, 256, GEMM_SMEM>>>(Hp, Wkp, bk, 1.f,
                                            nullptr, nullptr, nullptr, Kh,
                                            S_LEN, HDIM, HDIM);
    gemm_hmma<2><<<ggrid, 256, GEMM_SMEM>>>(Hp, Wvp, bv, 1.f,
                                            nullptr, nullptr, nullptr, Vh,
                                            S_LEN, HDIM, HDIM);

    dim3 tgrid(HDIM / 32, S_LEN / 32);
    transpose_h<<<tgrid, dim3(32, 8)>>>(Vh, VTh);

    dim3 agrid(S_LEN / 128, NHEADS);       // (32, 16)
    attn_hmma<<<agrid, 256, ATT_SMEM>>>(Qh, Ql, Kh, VTh, Op);

    gemm_hmma<0><<<ggrid, 256, GEMM_SMEM>>>(Op, Wop, bo, 1.f,
                                            out, nullptr, nullptr, nullptr,
                                            S_LEN, HDIM, HDIM);
}

// round 14
// speedup vs baseline: 6.6920x; 1.0534x over previous
#include <cuda_runtime.h>
#include <cuda_bf16.h>
#include <cuda_fp16.h>
#include <cstdint>
#include <math.h>

#define S_LEN 4096
#define HDIM  2048
#define NHEADS 16
#define HD    128
#define SCALE 0.08838834764831845f
// SCALE * log2(e): scores come out of QK^T already in log2 units
#define SCALE2 0.1275332511737922f

// ---------------- scratch globals ----------------
__device__ __half g_H[S_LEN * HDIM];                          // hidden fp16
__device__ __half g_Wq[HDIM * HDIM], g_Wk[HDIM * HDIM];       // weights fp16
__device__ __half g_Wv[HDIM * HDIM], g_Wo[HDIM * HDIM];
__device__ __half g_Qh[S_LEN * HDIM], g_Ql[S_LEN * HDIM];     // Q fp16 hi/lo
__device__ __half g_Kh[S_LEN * HDIM];                         // K fp16
__device__ __half g_Vh[S_LEN * HDIM];                         // V fp16
__device__ __half g_VTh[HDIM * S_LEN];                        // V^T fp16
__device__ __half g_O[S_LEN * HDIM];                          // attn out fp16

// ---------------- helpers ----------------
__device__ __forceinline__ uint32_t smem_u32(const void* p) {
    uint32_t a;
    asm("{ .reg .u64 t; cvta.to.shared.u64 t, %1; cvt.u32.u64 %0, t; }"
        : "=r"(a) : "l"(p));
    return a;
}
__device__ __forceinline__ void ldsm4(uint32_t* r, uint32_t a) {
    asm volatile("ldmatrix.sync.aligned.m8n8.x4.shared.b16 {%0,%1,%2,%3}, [%4];"
        : "=r"(r[0]), "=r"(r[1]), "=r"(r[2]), "=r"(r[3]) : "r"(a));
}
__device__ __forceinline__ void mma_f16(float* c, const uint32_t* a,
                                        const uint32_t* b) {
    asm volatile("mma.sync.aligned.m16n8k16.row.col.f32.f16.f16.f32 "
        "{%0,%1,%2,%3}, {%4,%5,%6,%7}, {%8,%9}, {%0,%1,%2,%3};"
        : "+f"(c[0]), "+f"(c[1]), "+f"(c[2]), "+f"(c[3])
        : "r"(a[0]), "r"(a[1]), "r"(a[2]), "r"(a[3]), "r"(b[0]), "r"(b[1]));
}
__device__ __forceinline__ float ex2f(float x) {
    float r;
    asm("ex2.approx.f32 %0, %1;" : "=f"(r) : "f"(x));
    return r;
}
__device__ __forceinline__ void split_store2h(__half* hi, __half* lo,
                                              float x, float y) {
    __half hx = __float2half_rn(x), hy = __float2half_rn(y);
    __half2 h2 = __halves2half2(hx, hy);
    __half2 l2 = __halves2half2(__float2half_rn(x - __half2float(hx)),
                                __float2half_rn(y - __half2float(hy)));
    *reinterpret_cast<__half2*>(hi) = h2;
    *reinterpret_cast<__half2*>(lo) = l2;
}
__device__ __forceinline__ uint32_t pack2h(float x, float y) {
    __half hx = __float2half_rn(x), hy = __float2half_rn(y);
    uint16_t a = *(uint16_t*)&hx, b = *(uint16_t*)&hy;
    return (uint32_t)a | ((uint32_t)b << 16);
}
#define CP_ASYNC16(dst, src) \
    asm volatile("cp.async.cg.shared.global [%0], [%1], 16;\n" \
                 :: "r"(dst), "l"(src))
#define CP_COMMIT asm volatile("cp.async.commit_group;\n" ::: "memory")
#define CP_WAIT0  asm volatile("cp.async.wait_group 0;\n" ::: "memory")
#define CP_WAIT1  asm volatile("cp.async.wait_group 1;\n" ::: "memory")

// ---------------- prepass: fp32 -> fp16 ----------------
__global__ __launch_bounds__(256) void conv_fp16(
    const float* __restrict__ in, __half* __restrict__ out, int n4)
{
    int i = blockIdx.x * blockDim.x + threadIdx.x;
    if (i < n4) {
        float4 v = ((const float4*)in)[i];
        *(__half2*)(out + i * 4) =
            __halves2half2(__float2half_rn(v.x), __float2half_rn(v.y));
        *(__half2*)(out + i * 4 + 2) =
            __halves2half2(__float2half_rn(v.z), __float2half_rn(v.w));
    }
}
__global__ __launch_bounds__(256) void conv_fp16_w4(
    const float* __restrict__ w0, const float* __restrict__ w1,
    const float* __restrict__ w2, const float* __restrict__ w3,
    __half* __restrict__ o0, __half* __restrict__ o1,
    __half* __restrict__ o2, __half* __restrict__ o3, int n4)
{
    const float* src = (blockIdx.y == 0) ? w0 : (blockIdx.y == 1) ? w1
                       : (blockIdx.y == 2) ? w2 : w3;
    __half* dst = (blockIdx.y == 0) ? o0 : (blockIdx.y == 1) ? o1
                  : (blockIdx.y == 2) ? o2 : o3;
    int i = blockIdx.x * blockDim.x + threadIdx.x;
    if (i < n4) {
        float4 v = ((const float4*)src)[i];
        *(__half2*)(dst + i * 4) =
            __halves2half2(__float2half_rn(v.x), __float2half_rn(v.y));
        *(__half2*)(dst + i * 4 + 2) =
            __halves2half2(__float2half_rn(v.z), __float2half_rn(v.w));
    }
}

// ---- HMMA GEMM v2: BM=128 BN=256 BK=32, warp tile 64x64, 3-stage cp.async
// OUT_MODE: 0 = fp32, 1 = fp16 hi/lo planes, 2 = fp16 single plane
#define LDAB 40
#define G_BOFF 10240                  /* B plane offset within stage (bytes) */
#define STG_BYTES 30720               /* A 10240 + B 20480 */
#define GEMM_SMEM (3 * STG_BYTES)     /* 92160 */

template <int OUT_MODE>
__global__ __launch_bounds__(256) void gemm_hmma(
    const __half* __restrict__ A, const __half* __restrict__ B,
    const float* __restrict__ bias, float scale,
    float* __restrict__ Cf, __half* __restrict__ Chh,
    __half* __restrict__ Chl, __half* __restrict__ Ch,
    int M, int N, int K)
{
    extern __shared__ char smraw[];
    const uint32_t sb = smem_u32(smraw);

    const int tid = threadIdx.x, lane = tid & 31, wid = tid >> 5;
    const int wm = wid >> 2, wn = wid & 3;           // 2 x 4 warps
    const int bm = blockIdx.y * 128, bn = blockIdx.x * 256;
    const int m0 = wm * 64, n0 = wn * 64;

    const int a_r = lane & 15, a_c = (lane >> 4) * 8;
    const int b_n = ((lane >> 4) & 1) * 8 + (lane & 7);
    const int b_k = ((lane >> 3) & 1) * 8;

    const int l_row = tid >> 2, l_col = (tid & 3) * 8;

    float acc[4][8][4];
#pragma unroll
    for (int mt = 0; mt < 4; mt++)
#pragma unroll
        for (int nt = 0; nt < 8; nt++)
#pragma unroll
            for (int j = 0; j < 4; j++) acc[mt][nt][j] = 0.f;

    const int nIter = K / 32;

    auto load_stage = [&](int kc, int s) {
        const uint32_t st = sb + s * STG_BYTES;
        const int k0 = kc * 32;
        // A: 128 rows x 32 cols = 512 chunks, 2 per thread
#pragma unroll
        for (int it = 0; it < 2; it++) {
            int row = l_row + it * 64;
            CP_ASYNC16(st + (row * LDAB + l_col) * 2,
                       A + (size_t)(bm + row) * K + k0 + l_col);
        }
        // B: 256 rows x 32 cols = 1024 chunks, 4 per thread
#pragma unroll
        for (int it = 0; it < 4; it++) {
            int row = l_row + it * 64;
            CP_ASYNC16(st + G_BOFF + (row * LDAB + l_col) * 2,
                       B + (size_t)(bn + row) * K + k0 + l_col);
        }
        CP_COMMIT;
    };

    load_stage(0, 0);
    load_stage(1, 1);
    for (int kc = 0; kc < nIter; kc++) {
        CP_WAIT1;            // stage kc ready (only load kc+1 may be pending)
        __syncthreads();     // all warps done with stage (kc-1)%3
        if (kc + 2 < nIter) load_stage(kc + 2, (kc + 2) % 3);

        const uint32_t st = sb + (kc % 3) * STG_BYTES;
#pragma unroll
        for (int ks = 0; ks < 2; ks++) {
            const int k0 = ks * 16;
            uint32_t ah[4][4], bb[4][4];
#pragma unroll
            for (int mt = 0; mt < 4; mt++) {
                int off = ((m0 + mt * 16 + a_r) * LDAB + k0 + a_c) * 2;
                ldsm4(ah[mt], st + off);
            }
#pragma unroll
            for (int bp = 0; bp < 4; bp++) {
                int off = ((n0 + bp * 16 + b_n) * LDAB + k0 + b_k) * 2;
                ldsm4(bb[bp], st + G_BOFF + off);
            }
#pragma unroll
            for (int mt = 0; mt < 4; mt++)
#pragma unroll
                for (int nt = 0; nt < 8; nt++)
                    mma_f16(acc[mt][nt], ah[mt], &bb[nt >> 1][(nt & 1) * 2]);
        }
    }

#pragma unroll
    for (int mt = 0; mt < 4; mt++) {
        const int r0 = bm + m0 + mt * 16 + (lane >> 2);
#pragma unroll
        for (int nt = 0; nt < 8; nt++) {
            const int col = bn + n0 + nt * 8 + (lane & 3) * 2;
            float2 bv = *(const float2*)(bias + col);
            float c00 = (acc[mt][nt][0] + bv.x) * scale;
            float c01 = (acc[mt][nt][1] + bv.y) * scale;
            float c10 = (acc[mt][nt][2] + bv.x) * scale;
            float c11 = (acc[mt][nt][3] + bv.y) * scale;
            if (OUT_MODE == 0) {
                *(float2*)(Cf + (size_t)r0 * N + col) = make_float2(c00, c01);
                *(float2*)(Cf + (size_t)(r0 + 8) * N + col) = make_float2(c10, c11);
            } else if (OUT_MODE == 1) {
                split_store2h(Chh + (size_t)r0 * N + col,
                              Chl + (size_t)r0 * N + col, c00, c01);
                split_store2h(Chh + (size_t)(r0 + 8) * N + col,
                              Chl + (size_t)(r0 + 8) * N + col, c10, c11);
            } else {
                *(uint32_t*)(Ch + (size_t)r0 * N + col) = pack2h(c00, c01);
                *(uint32_t*)(Ch + (size_t)(r0 + 8) * N + col) = pack2h(c10, c11);
            }
        }
    }
}

// ------- transpose fp16: out[c][s] = in[s][c] -------
__global__ __launch_bounds__(256) void transpose_h(
    const __half* __restrict__ in, __half* __restrict__ out)
{
    __shared__ __half tile[32][34];
    const int cb = blockIdx.x * 32, sbk = blockIdx.y * 32;
    const int tx = threadIdx.x, ty = threadIdx.y;
#pragma unroll
    for (int j = 0; j < 4; j++)
        tile[ty + j * 8][tx] = in[(size_t)(sbk + ty + j * 8) * HDIM + cb + tx];
    __syncthreads();
#pragma unroll
    for (int j = 0; j < 4; j++)
        out[(size_t)(cb + ty + j * 8) * S_LEN + sbk + tx] = tile[tx][ty + j * 8];
}

// ---------------- fp16 flash attention (unchanged from round 13) ----------
#define LDQ 136
#define LDV 72
#define AQL 17408
#define ASTG0 34816
#define ASTG  17920
#define AVH_OFF 8704
#define ATT_SMEM 141312

__global__ __launch_bounds__(256) void attn_hmma(
    const __half* __restrict__ Qhi, const __half* __restrict__ Qlo,
    const __half* __restrict__ Kh, const __half* __restrict__ VTh,
    __half* __restrict__ O)
{
    extern __shared__ __half smh[];
    const uint32_t sb = smem_u32(smh);

    const int tid = threadIdx.x, lane = tid & 31, wid = tid >> 5;
    const int qb = blockIdx.x * 128, h = blockIdx.y;

    const int a_r = lane & 15, a_c = (lane >> 4) * 8;
    const int b_n = ((lane >> 4) & 1) * 8 + (lane & 7);
    const int b_k = ((lane >> 3) & 1) * 8;
    const int qrow = wid * 16;

    const int k_r = tid >> 2, k_c = (tid & 3) * 32;
    const int v_r = tid >> 1, v_c = (tid & 1) * 32;

    auto load_kv = [&](int t, int s) {
        const uint32_t stg = sb + (ASTG0 + s * ASTG) * 2;
        const __half* kp = Kh + (size_t)(t * 64 + k_r) * HDIM + h * HD + k_c;
#pragma unroll
        for (int j = 0; j < 4; j++)
            CP_ASYNC16(stg + (k_r * LDQ + k_c + j * 8) * 2, kp + j * 8);
        const __half* vp = VTh + (size_t)(h * HD + v_r) * S_LEN + t * 64 + v_c;
#pragma unroll
        for (int j = 0; j < 4; j++)
            CP_ASYNC16(stg + (AVH_OFF + v_r * LDV + v_c + j * 8) * 2, vp + j * 8);
        CP_COMMIT;
    };

    {
        const int r = tid >> 1, cs = (tid & 1) * 64;
        const __half* qh = Qhi + (size_t)(qb + r) * HDIM + h * HD + cs;
        const __half* ql = Qlo + (size_t)(qb + r) * HDIM + h * HD + cs;
#pragma unroll
        for (int j = 0; j < 8; j++) {
            CP_ASYNC16(sb + (r * LDQ + cs + j * 8) * 2, qh + j * 8);
            CP_ASYNC16(sb + (AQL + r * LDQ + cs + j * 8) * 2, ql + j * 8);
        }
        CP_COMMIT;          // group: Q
    }
    load_kv(0, 0);          // group: KV(0)

    CP_WAIT1;
    __syncthreads();

    uint32_t qfh[8][4], qfl[8][4];
#pragma unroll
    for (int ks = 0; ks < 8; ks++) {
        int off = ((qrow + a_r) * LDQ + ks * 16 + a_c) * 2;
        ldsm4(qfh[ks], sb + off);
        ldsm4(qfl[ks], sb + AQL * 2 + off);
    }

    float m0 = -INFINITY, m1 = -INFINITY, l0 = 0.f, l1 = 0.f;
    float oacc[16][4];
#pragma unroll
    for (int nt = 0; nt < 16; nt++)
#pragma unroll
        for (int j = 0; j < 4; j++) oacc[nt][j] = 0.f;

    const int NT = S_LEN / 64;
    for (int t = 0; t < NT; t++) {
        const int s = t & 1;
        CP_WAIT0;
        __syncthreads();
        if (t + 1 < NT) load_kv(t + 1, s ^ 1);

        const uint32_t stg = sb + (ASTG0 + s * ASTG) * 2;

        // ---- Phase 1: S = Q K^T (2 MMAs, Q hi/lo exact) ----
        float sacc[8][4];
#pragma unroll
        for (int nt = 0; nt < 8; nt++)
#pragma unroll
            for (int j = 0; j < 4; j++) sacc[nt][j] = 0.f;

#pragma unroll
        for (int ks = 0; ks < 8; ks++) {
            const int k0 = ks * 16;
            uint32_t bh[4][4];
#pragma unroll
            for (int g = 0; g < 4; g++) {
                int off = ((g * 16 + b_n) * LDQ + k0 + b_k) * 2;
                ldsm4(bh[g], stg + off);
            }
#pragma unroll
            for (int nt = 0; nt < 8; nt++) {
                const uint32_t* bhp = &bh[nt >> 1][(nt & 1) * 2];
                mma_f16(sacc[nt], qfh[ks], bhp);
                mma_f16(sacc[nt], qfl[ks], bhp);
            }
        }

        // ---- warp-local online softmax (log2 domain) ----
        float tm0 = -INFINITY, tm1 = -INFINITY;
#pragma unroll
        for (int nt = 0; nt < 8; nt++) {
            tm0 = fmaxf(tm0, fmaxf(sacc[nt][0], sacc[nt][1]));
            tm1 = fmaxf(tm1, fmaxf(sacc[nt][2], sacc[nt][3]));
        }
        tm0 = fmaxf(tm0, __shfl_xor_sync(0xffffffffu, tm0, 1));
        tm0 = fmaxf(tm0, __shfl_xor_sync(0xffffffffu, tm0, 2));
        tm1 = fmaxf(tm1, __shfl_xor_sync(0xffffffffu, tm1, 1));
        tm1 = fmaxf(tm1, __shfl_xor_sync(0xffffffffu, tm1, 2));
        const float mn0 = fmaxf(m0, tm0), mn1 = fmaxf(m1, tm1);
        const float c0 = ex2f(m0 - mn0), c1 = ex2f(m1 - mn1);
        m0 = mn0; m1 = mn1;

        float ls0 = 0.f, ls1 = 0.f;
#pragma unroll
        for (int nt = 0; nt < 8; nt++) {
            sacc[nt][0] = ex2f(sacc[nt][0] - mn0);
            sacc[nt][1] = ex2f(sacc[nt][1] - mn0);
            sacc[nt][2] = ex2f(sacc[nt][2] - mn1);
            sacc[nt][3] = ex2f(sacc[nt][3] - mn1);
            ls0 += sacc[nt][0] + sacc[nt][1];
            ls1 += sacc[nt][2] + sacc[nt][3];
        }
        ls0 += __shfl_xor_sync(0xffffffffu, ls0, 1);
        ls0 += __shfl_xor_sync(0xffffffffu, ls0, 2);
        ls1 += __shfl_xor_sync(0xffffffffu, ls1, 1);
        ls1 += __shfl_xor_sync(0xffffffffu, ls1, 2);
        l0 = l0 * c0 + ls0;
        l1 = l1 * c1 + ls1;

        if (c0 != 1.f || c1 != 1.f) {
#pragma unroll
            for (int nt = 0; nt < 16; nt++) {
                oacc[nt][0] *= c0; oacc[nt][1] *= c0;
                oacc[nt][2] *= c1; oacc[nt][3] *= c1;
            }
        }

        // ---- Phase 2: O += P V (single fp16 P) ----
#pragma unroll
        for (int ks = 0; ks < 4; ks++) {
            uint32_t p4[4];
            p4[0] = pack2h(sacc[2 * ks][0], sacc[2 * ks][1]);
            p4[1] = pack2h(sacc[2 * ks][2], sacc[2 * ks][3]);
            p4[2] = pack2h(sacc[2 * ks + 1][0], sacc[2 * ks + 1][1]);
            p4[3] = pack2h(sacc[2 * ks + 1][2], sacc[2 * ks + 1][3]);
            const int k0 = ks * 16;
#pragma unroll
            for (int g = 0; g < 8; g++) {
                uint32_t vh[4];
                int off = ((g * 16 + b_n) * LDV + k0 + b_k) * 2;
                ldsm4(vh, stg + AVH_OFF * 2 + off);
                mma_f16(oacc[g * 2 + 0], p4, &vh[0]);
                mma_f16(oacc[g * 2 + 1], p4, &vh[2]);
            }
        }
    }

    // ---- epilogue ----
    const float inv0 = 1.f / l0, inv1 = 1.f / l1;
    const int r0 = qrow + (lane >> 2);
#pragma unroll
    for (int nt = 0; nt < 16; nt++) {
        const int col = nt * 8 + (lane & 3) * 2;
        size_t i0 = (size_t)(qb + r0) * HDIM + h * HD + col;
        size_t i1 = (size_t)(qb + r0 + 8) * HDIM + h * HD + col;
        *(uint32_t*)(O + i0) = pack2h(oacc[nt][0] * inv0, oacc[nt][1] * inv0);
        *(uint32_t*)(O + i1) = pack2h(oacc[nt][2] * inv1, oacc[nt][3] * inv1);
    }
}

// ---------------- launch ----------------
extern "C" void kernel_launch(void* const* d_in, const int* in_sizes, int n_in,
                              void* d_out, int out_size)
{
    const float* hidden = (const float*)d_in[0];
    const float* Wq = (const float*)d_in[1];
    const float* bq = (const float*)d_in[2];
    const float* Wk = (const float*)d_in[3];
    const float* bk = (const float*)d_in[4];
    const float* Wv = (const float*)d_in[5];
    const float* bv = (const float*)d_in[6];
    const float* Wo = (const float*)d_in[7];
    const float* bo = (const float*)d_in[8];
    float* out = (float*)d_out;

    __half *Hp, *Wqp, *Wkp, *Wvp, *Wop, *Qh, *Ql, *Kh, *Vh, *VTh, *Op;
    cudaGetSymbolAddress((void**)&Hp, g_H);
    cudaGetSymbolAddress((void**)&Wqp, g_Wq);   cudaGetSymbolAddress((void**)&Wkp, g_Wk);
    cudaGetSymbolAddress((void**)&Wvp, g_Wv);   cudaGetSymbolAddress((void**)&Wop, g_Wo);
    cudaGetSymbolAddress((void**)&Qh, g_Qh);    cudaGetSymbolAddress((void**)&Ql, g_Ql);
    cudaGetSymbolAddress((void**)&Kh, g_Kh);    cudaGetSymbolAddress((void**)&Vh, g_Vh);
    cudaGetSymbolAddress((void**)&VTh, g_VTh);
    cudaGetSymbolAddress((void**)&Op, g_O);

    cudaFuncSetAttribute(gemm_hmma<0>, cudaFuncAttributeMaxDynamicSharedMemorySize, GEMM_SMEM);
    cudaFuncSetAttribute(gemm_hmma<1>, cudaFuncAttributeMaxDynamicSharedMemorySize, GEMM_SMEM);
    cudaFuncSetAttribute(gemm_hmma<2>, cudaFuncAttributeMaxDynamicSharedMemorySize, GEMM_SMEM);
    cudaFuncSetAttribute(attn_hmma, cudaFuncAttributeMaxDynamicSharedMemorySize, ATT_SMEM);

    const int nH4 = S_LEN * HDIM / 4, nW4 = HDIM * HDIM / 4;
    conv_fp16<<<nH4 / 256, 256>>>(hidden, Hp, nH4);
    conv_fp16_w4<<<dim3(nW4 / 256, 4), 256>>>(Wq, Wk, Wv, Wo,
                                              Wqp, Wkp, Wvp, Wop, nW4);

    dim3 ggrid(HDIM / 256, S_LEN / 128);   // (8, 32)
    // Q: fp16 hi/lo planes, pre-scaled by SCALE*log2(e)
    gemm_hmma<1><<<ggrid, 256, GEMM_SMEM>>>(Hp, Wqp, bq, SCALE2,
                                            nullptr, Qh, Ql, nullptr,
                                            S_LEN, HDIM, HDIM);
    gemm_hmma<2><<<ggrid, 256, GEMM_SMEM>>>(Hp, Wkp, bk, 1.f,
                                            nullptr, nullptr, nullptr, Kh,
                                            S_LEN, HDIM, HDIM);
    gemm_hmma<2><<<ggrid, 256, GEMM_SMEM>>>(Hp, Wvp, bv, 1.f,
                                            nullptr, nullptr, nullptr, Vh,
                                            S_LEN, HDIM, HDIM);

    dim3 tgrid(HDIM / 32, S_LEN / 32);
    transpose_h<<<tgrid, dim3(32, 8)>>>(Vh, VTh);

    dim3 agrid(S_LEN / 128, NHEADS);       // (32, 16)
    attn_hmma<<<agrid, 256, ATT_SMEM>>>(Qh, Ql, Kh, VTh, Op);

    gemm_hmma<0><<<ggrid, 256, GEMM_SMEM>>>(Op, Wop, bo, 1.f,
                                            out, nullptr, nullptr, nullptr,
                                            S_LEN, HDIM, HDIM);
}